// round 2
// baseline (speedup 1.0000x reference)
#include <cuda_runtime.h>

// Problem constants
#define B_   4
#define T_   32
#define D_   768
#define P_   256          // Hp*Wp = 16*16
#define BS_  1024         // B_*P_ sequences
#define M_   32768        // BS_*T_ rows for projection GEMMs
#define NH_  12
#define HD_  64

// Scratch (device globals — no cudaMalloc allowed)
__device__ float g_hseq[(size_t)M_ * D_];
__device__ float g_Q   [(size_t)M_ * D_];
__device__ float g_K   [(size_t)M_ * D_];
__device__ float g_V   [(size_t)M_ * D_];
__device__ float g_att [(size_t)M_ * D_];
__device__ float g_oseq[(size_t)M_ * D_];
__device__ float g_upen[M_];

// -------------------------------------------------------------------------
// (B,T,D,P) -> (b*P+p, t, d)   [h -> h_seq]
// -------------------------------------------------------------------------
__global__ __launch_bounds__(1024) void transpose_in(const float* __restrict__ src,
                                                     float* __restrict__ dst) {
    __shared__ float tile[32][33];
    int bt   = blockIdx.z;          // 0..127 = b*32+t
    int b    = bt >> 5, t = bt & 31;
    int dblk = blockIdx.y * 32;     // 24 blocks
    int pblk = blockIdx.x * 32;     // 8 blocks

    int d = dblk + threadIdx.y;
    int p = pblk + threadIdx.x;
    tile[threadIdx.y][threadIdx.x] = src[((size_t)bt * D_ + d) * P_ + p];
    __syncthreads();
    int d2 = dblk + threadIdx.x;
    int p2 = pblk + threadIdx.y;
    dst[(((size_t)(b * P_ + p2)) * T_ + t) * D_ + d2] = tile[threadIdx.x][threadIdx.y];
}

// -------------------------------------------------------------------------
// (bs, t, d) -> (B,T,D,P)   [out_seq -> final output]
// -------------------------------------------------------------------------
__global__ __launch_bounds__(1024) void transpose_out(const float* __restrict__ src,
                                                      float* __restrict__ dst) {
    __shared__ float tile[32][33];
    int bt   = blockIdx.z;
    int b    = bt >> 5, t = bt & 31;
    int dblk = blockIdx.y * 32;
    int pblk = blockIdx.x * 32;

    int d = dblk + threadIdx.x;
    int p = pblk + threadIdx.y;
    tile[threadIdx.y][threadIdx.x] = src[(((size_t)(b * P_ + p)) * T_ + t) * D_ + d];
    __syncthreads();
    int p2 = pblk + threadIdx.x;
    int d2 = dblk + threadIdx.y;
    dst[((size_t)bt * D_ + d2) * P_ + p2] = tile[threadIdx.x][threadIdx.y];
}

// -------------------------------------------------------------------------
// u_pen[bs][t] = lam[b][t][p] * mean_d u_enc[b][t][d][p]
// one block per (b,t); 256 threads = one per p; coalesced across threads
// -------------------------------------------------------------------------
__global__ __launch_bounds__(256) void upen_kernel(const float* __restrict__ u,
                                                   const float* __restrict__ lam,
                                                   float* __restrict__ upen) {
    int bt = blockIdx.x;            // 0..127
    int b  = bt >> 5, t = bt & 31;
    int p  = threadIdx.x;
    const float* up = u + (size_t)bt * D_ * P_ + p;
    float acc = 0.f;
#pragma unroll 8
    for (int d = 0; d < D_; d++) acc += up[(size_t)d * P_];
    upen[(b * P_ + p) * T_ + t] = lam[(size_t)bt * P_ + p] * acc * (1.0f / (float)D_);
}

// -------------------------------------------------------------------------
// C[m][n] = sum_k A[m][k] * W[n][k] + bias[n]      (x @ W^T + b)
// M=32768, N=768, K=768. 128x128 block tile, K-tile 8, 256 threads, 8x8/thread
// -------------------------------------------------------------------------
__global__ __launch_bounds__(256) void gemm_bias(const float* __restrict__ A,
                                                 const float* __restrict__ W,
                                                 const float* __restrict__ bias,
                                                 float* __restrict__ C) {
    __shared__ float As[8][128];
    __shared__ float Bs[8][128];

    int tid  = threadIdx.x;
    int mblk = blockIdx.y * 128;
    int nblk = blockIdx.x * 128;

    int lr = tid >> 1;            // 0..127 : row (m or n) being loaded
    int lk = (tid & 1) * 4;       // k offset within K-tile

    int tx = (tid & 15) * 8;      // n within tile
    int ty = (tid >> 4) * 8;      // m within tile

    float acc[8][8];
#pragma unroll
    for (int i = 0; i < 8; i++)
#pragma unroll
        for (int j = 0; j < 8; j++) acc[i][j] = 0.f;

    const float* Aptr = A + (size_t)(mblk + lr) * D_ + lk;
    const float* Wptr = W + (size_t)(nblk + lr) * D_ + lk;

    for (int kb = 0; kb < D_; kb += 8) {
        float4 av = *reinterpret_cast<const float4*>(Aptr + kb);
        float4 bv = *reinterpret_cast<const float4*>(Wptr + kb);
        __syncthreads();
        As[lk + 0][lr] = av.x; As[lk + 1][lr] = av.y;
        As[lk + 2][lr] = av.z; As[lk + 3][lr] = av.w;
        Bs[lk + 0][lr] = bv.x; Bs[lk + 1][lr] = bv.y;
        Bs[lk + 2][lr] = bv.z; Bs[lk + 3][lr] = bv.w;
        __syncthreads();
#pragma unroll
        for (int k = 0; k < 8; k++) {
            float4 a0 = *reinterpret_cast<const float4*>(&As[k][ty]);
            float4 a1 = *reinterpret_cast<const float4*>(&As[k][ty + 4]);
            float4 b0 = *reinterpret_cast<const float4*>(&Bs[k][tx]);
            float4 b1 = *reinterpret_cast<const float4*>(&Bs[k][tx + 4]);
            float af[8] = {a0.x, a0.y, a0.z, a0.w, a1.x, a1.y, a1.z, a1.w};
            float bf[8] = {b0.x, b0.y, b0.z, b0.w, b1.x, b1.y, b1.z, b1.w};
#pragma unroll
            for (int i = 0; i < 8; i++)
#pragma unroll
                for (int j = 0; j < 8; j++) acc[i][j] += af[i] * bf[j];
        }
    }

#pragma unroll
    for (int i = 0; i < 8; i++) {
        int m = mblk + ty + i;
#pragma unroll
        for (int j = 0; j < 8; j++) {
            int n = nblk + tx + j;
            C[(size_t)m * D_ + n] = acc[i][j] + bias[n];
        }
    }
}

// -------------------------------------------------------------------------
// Fused attention per (bs, head): 32x32 scores, softmax, 32x64 out
// -------------------------------------------------------------------------
__global__ __launch_bounds__(128) void attn_kernel(const float* __restrict__ Q,
                                                   const float* __restrict__ K,
                                                   const float* __restrict__ V,
                                                   const float* __restrict__ upen,
                                                   float* __restrict__ O) {
    int bs = blockIdx.x;   // 0..1023
    int h  = blockIdx.y;   // 0..11
    __shared__ float Qs[32][64];
    __shared__ float Ks[32][64];
    __shared__ float Vs[32][64];
    __shared__ float Sc[32][33];

    int tid = threadIdx.x;
    const float* qb = Q + (size_t)(bs * T_) * D_ + h * HD_;
    const float* kb = K + (size_t)(bs * T_) * D_ + h * HD_;
    const float* vb = V + (size_t)(bs * T_) * D_ + h * HD_;

    // 32 rows * 16 float4 = 512 float4 per tile
    for (int i = tid; i < 512; i += 128) {
        int r = i >> 4, c = (i & 15) * 4;
        *reinterpret_cast<float4*>(&Qs[r][c]) = *reinterpret_cast<const float4*>(&qb[(size_t)r * D_ + c]);
        *reinterpret_cast<float4*>(&Ks[r][c]) = *reinterpret_cast<const float4*>(&kb[(size_t)r * D_ + c]);
        *reinterpret_cast<float4*>(&Vs[r][c]) = *reinterpret_cast<const float4*>(&vb[(size_t)r * D_ + c]);
    }
    __syncthreads();

    // scores = Q K^T / 8 - upen[k]
    for (int i = tid; i < 1024; i += 128) {
        int q = i >> 5, k = i & 31;
        float s = 0.f;
#pragma unroll
        for (int d = 0; d < HD_; d++) s += Qs[q][d] * Ks[k][d];
        Sc[q][k] = s * 0.125f - upen[bs * T_ + k];
    }
    __syncthreads();

    // row softmax (32 rows, one thread each — tiny)
    if (tid < 32) {
        float mx = -1e30f;
#pragma unroll
        for (int k = 0; k < 32; k++) mx = fmaxf(mx, Sc[tid][k]);
        float sum = 0.f;
#pragma unroll
        for (int k = 0; k < 32; k++) { float e = __expf(Sc[tid][k] - mx); Sc[tid][k] = e; sum += e; }
        float inv = 1.f / sum;
#pragma unroll
        for (int k = 0; k < 32; k++) Sc[tid][k] *= inv;
    }
    __syncthreads();

    // out = attn @ V
    float* ob = O + (size_t)(bs * T_) * D_ + h * HD_;
    for (int i = tid; i < 2048; i += 128) {
        int t = i >> 6, d = i & 63;
        float s = 0.f;
#pragma unroll
        for (int k = 0; k < 32; k++) s += Sc[t][k] * Vs[k][d];
        ob[(size_t)t * D_ + d] = s;
    }
}

// -------------------------------------------------------------------------
extern "C" void kernel_launch(void* const* d_in, const int* in_sizes, int n_in,
                              void* d_out, int out_size) {
    const float* h   = (const float*)d_in[0];
    const float* u   = (const float*)d_in[1];
    const float* lam = (const float*)d_in[2];
    const float* Wq  = (const float*)d_in[3];
    const float* bq  = (const float*)d_in[4];
    const float* Wk  = (const float*)d_in[5];
    const float* bk  = (const float*)d_in[6];
    const float* Wv  = (const float*)d_in[7];
    const float* bv  = (const float*)d_in[8];
    const float* Wo  = (const float*)d_in[9];
    const float* bo  = (const float*)d_in[10];
    float* out = (float*)d_out;

    float *hseq, *Qb, *Kb, *Vb, *att, *oseq, *upen;
    cudaGetSymbolAddress((void**)&hseq, g_hseq);
    cudaGetSymbolAddress((void**)&Qb,   g_Q);
    cudaGetSymbolAddress((void**)&Kb,   g_K);
    cudaGetSymbolAddress((void**)&Vb,   g_V);
    cudaGetSymbolAddress((void**)&att,  g_att);
    cudaGetSymbolAddress((void**)&oseq, g_oseq);
    cudaGetSymbolAddress((void**)&upen, g_upen);

    dim3 tgrid(8, 24, 128), tblk(32, 32);
    transpose_in<<<tgrid, tblk>>>(h, hseq);
    upen_kernel<<<128, 256>>>(u, lam, upen);

    dim3 ggrid(D_ / 128, M_ / 128);
    gemm_bias<<<ggrid, 256>>>(hseq, Wq, bq, Qb);
    gemm_bias<<<ggrid, 256>>>(hseq, Wk, bk, Kb);
    gemm_bias<<<ggrid, 256>>>(hseq, Wv, bv, Vb);

    dim3 agrid(BS_, NH_);
    attn_kernel<<<agrid, 128>>>(Qb, Kb, Vb, upen, att);

    gemm_bias<<<ggrid, 256>>>(att, Wo, bo, oseq);

    transpose_out<<<tgrid, tblk>>>(oseq, out);
}

// round 5
// speedup vs baseline: 2.8274x; 2.8274x over previous
#include <cuda_runtime.h>
#include <cuda_fp16.h>
#include <cstdint>

// Problem constants
#define B_   4
#define T_   32
#define D_   768
#define P_   256
#define BS_  1024
#define M_   32768
#define NH_  12
#define HD_  64
#define K2_  1536          // 2 * 768 (fp16 hi/lo split on the A side)

// GEMM tiling
#define BM   128
#define BN   128
#define BK   32
#define NKT  (K2_ / BK)    // 48
#define LDS_ 40            // padded row stride in fp16 elements (80 bytes)
#define TILE_BYTES (BM * LDS_ * 2)       // 10240 per operand
#define STAGE_BYTES (2 * TILE_BYTES)     // 20480 (A + B)
#define A_OFF 0
#define B_OFF TILE_BYTES

// ---------------- scratch (device globals; no cudaMalloc allowed) ----------
__device__ __half g_hsplit[(size_t)M_ * K2_];   // h_seq [hi, lo]
__device__ __half g_asplit[(size_t)M_ * K2_];   // attention out [hi, lo]
__device__ __half g_wq[(size_t)D_ * K2_];       // [w, w] duplicated
__device__ __half g_wk[(size_t)D_ * K2_];
__device__ __half g_wv[(size_t)D_ * K2_];
__device__ __half g_wo[(size_t)D_ * K2_];
__device__ float g_Q   [(size_t)M_ * D_];
__device__ float g_K   [(size_t)M_ * D_];
__device__ float g_V   [(size_t)M_ * D_];
__device__ float g_oseq[(size_t)M_ * D_];
__device__ float g_upen[M_];

// ---------------- PTX helpers (all base-PTX, sm_80-era) --------------------
__device__ __forceinline__ uint32_t smem_u32(const void* p) {
    uint32_t a;
    asm("{ .reg .u64 t; cvta.to.shared.u64 t, %1; cvt.u32.u64 %0, t; }"
        : "=r"(a) : "l"(p));
    return a;
}

__device__ __forceinline__ void cp16(uint32_t dst, const void* src) {
    asm volatile("cp.async.cg.shared.global [%0], [%1], 16;" :: "r"(dst), "l"(src));
}
#define CP_COMMIT() asm volatile("cp.async.commit_group;" ::: "memory")
#define CP_WAIT(n)  asm volatile("cp.async.wait_group %0;" :: "n"(n) : "memory")

__device__ __forceinline__ void ldsm4(uint32_t (&r)[4], uint32_t addr) {
    asm volatile("ldmatrix.sync.aligned.m8n8.x4.shared.b16 {%0,%1,%2,%3}, [%4];"
                 : "=r"(r[0]), "=r"(r[1]), "=r"(r[2]), "=r"(r[3]) : "r"(addr));
}

__device__ __forceinline__ void mma16816(float (&d)[4], const uint32_t (&a)[4],
                                         uint32_t b0, uint32_t b1) {
    asm volatile(
        "mma.sync.aligned.m16n8k16.row.col.f32.f16.f16.f32 "
        "{%0,%1,%2,%3}, {%4,%5,%6,%7}, {%8,%9}, {%0,%1,%2,%3};"
        : "+f"(d[0]), "+f"(d[1]), "+f"(d[2]), "+f"(d[3])
        : "r"(a[0]), "r"(a[1]), "r"(a[2]), "r"(a[3]), "r"(b0), "r"(b1));
}

// ---------------------------------------------------------------------------
// transpose + fp16 hi/lo split:  h (B,T,D,P) -> g_hsplit[(b*P+p)*T+t][k']
//   k' in [0,768): hi     [768,1536): lo
// ---------------------------------------------------------------------------
__global__ __launch_bounds__(1024) void transpose_in_split(const float* __restrict__ src,
                                                           __half* __restrict__ dst) {
    __shared__ float tile[32][33];
    int bt = blockIdx.z, b = bt >> 5, t = bt & 31;
    int dblk = blockIdx.y * 32, pblk = blockIdx.x * 32;

    int d = dblk + threadIdx.y, p = pblk + threadIdx.x;
    tile[threadIdx.y][threadIdx.x] = src[((size_t)bt * D_ + d) * P_ + p];
    __syncthreads();
    int d2 = dblk + threadIdx.x, p2 = pblk + threadIdx.y;
    float v = tile[threadIdx.x][threadIdx.y];
    __half hi = __float2half(v);
    __half lo = __float2half(v - __half2float(hi));
    size_t base = (((size_t)(b * P_ + p2)) * T_ + t) * K2_ + d2;
    dst[base]      = hi;
    dst[base + D_] = lo;
}

// ---------------------------------------------------------------------------
// weight convert: W (N x D fp32) -> Ws (N x K2) = [w, w] fp16 duplicated
// ---------------------------------------------------------------------------
__global__ __launch_bounds__(256) void wsplit(const float* __restrict__ W,
                                              __half* __restrict__ Ws) {
    int i = blockIdx.x * 256 + threadIdx.x;          // 0 .. 768*768-1
    int n = i / D_, d = i % D_;
    __half w = __float2half(W[i]);
    size_t base = (size_t)n * K2_ + d;
    Ws[base]      = w;
    Ws[base + D_] = w;
}

// ---------------------------------------------------------------------------
// (bs, t, d) -> (B,T,D,P)
// ---------------------------------------------------------------------------
__global__ __launch_bounds__(1024) void transpose_out(const float* __restrict__ src,
                                                      float* __restrict__ dst) {
    __shared__ float tile[32][33];
    int bt = blockIdx.z, b = bt >> 5, t = bt & 31;
    int dblk = blockIdx.y * 32, pblk = blockIdx.x * 32;

    int d = dblk + threadIdx.x, p = pblk + threadIdx.y;
    tile[threadIdx.y][threadIdx.x] = src[(((size_t)(b * P_ + p)) * T_ + t) * D_ + d];
    __syncthreads();
    int p2 = pblk + threadIdx.x, d2 = dblk + threadIdx.y;
    dst[((size_t)bt * D_ + d2) * P_ + p2] = tile[threadIdx.x][threadIdx.y];
}

// ---------------------------------------------------------------------------
// u_pen
// ---------------------------------------------------------------------------
__global__ __launch_bounds__(256) void upen_kernel(const float* __restrict__ u,
                                                   const float* __restrict__ lam,
                                                   float* __restrict__ upen) {
    int bt = blockIdx.x, b = bt >> 5, t = bt & 31;
    int p = threadIdx.x;
    const float* up = u + (size_t)bt * D_ * P_ + p;
    float acc = 0.f;
#pragma unroll 8
    for (int d = 0; d < D_; d++) acc += up[(size_t)d * P_];
    upen[(b * P_ + p) * T_ + t] = lam[(size_t)bt * P_ + p] * acc * (1.0f / (float)D_);
}

// ---------------------------------------------------------------------------
// HMMA GEMM:  C[M,768] = A'[M,1536] @ Ws'[768,1536]^T + bias
// 128x128 tile, BK=32, 3-stage cp.async, 8 warps x (64x32) warp tiles.
// ---------------------------------------------------------------------------
__global__ __launch_bounds__(256) void gemm_mma(const __half* __restrict__ A,
                                                const __half* __restrict__ Wt,
                                                const float* __restrict__ bias,
                                                float* __restrict__ C) {
    extern __shared__ __align__(128) char dyn[];
    const uint32_t dynb = smem_u32(dyn);

    const int tid  = threadIdx.x;
    const int wid  = tid >> 5;
    const int lane = tid & 31;
    const int mblk = blockIdx.y * BM;
    const int nblk = blockIdx.x * BN;

    const int warp_m = (wid >> 2) * 64;   // 0 or 64
    const int warp_n = (wid & 3) * 32;    // 0,32,64,96

    const __half* Ab = A  + (size_t)mblk * K2_;
    const __half* Bb = Wt + (size_t)nblk * K2_;

    // cp.async chunk mapping: 512 A chunks + 512 B chunks, 4 per thread
    // chunk c (operand-local): row r = c>>2, k-chunk kc = c&3 (16B = 8 fp16)
    const int cA0 = tid;            // A chunks: tid, tid+256
    const int cB0 = tid;            // B chunks: tid, tid+256
    auto load_tile = [&](int stage, int kt) {
        uint32_t sb = dynb + stage * STAGE_BYTES;
        const __half* Ak = Ab + kt * BK;
        const __half* Bk = Bb + kt * BK;
#pragma unroll
        for (int i = 0; i < 2; ++i) {
            int c = cA0 + 256 * i;
            int r = c >> 2, kc = c & 3;
            cp16(sb + A_OFF + r * 80 + kc * 16, Ak + (size_t)r * K2_ + kc * 8);
        }
#pragma unroll
        for (int i = 0; i < 2; ++i) {
            int c = cB0 + 256 * i;
            int r = c >> 2, kc = c & 3;
            cp16(sb + B_OFF + r * 80 + kc * 16, Bk + (size_t)r * K2_ + kc * 8);
        }
        CP_COMMIT();
    };

    // ldmatrix per-lane base offsets (bytes) within a stage
    // A: lanes 0-15 -> rows m0-15 (k lo half), 16-31 -> rows m0-15 (k hi half)
    const int a_row = lane & 15;
    const int a_kh  = lane >> 4;
    const uint32_t a_base = A_OFF + (warp_m + a_row) * 80 + a_kh * 16;
    // B: lanes 0-7 -> n0-7 k-lo, 8-15 -> n0-7 k-hi, 16-23 -> n8-15 k-lo, 24-31 -> n8-15 k-hi
    const int b_row = (lane & 7) + ((lane >> 4) << 3);
    const int b_kh  = (lane >> 3) & 1;
    const uint32_t b_base = B_OFF + (warp_n + b_row) * 80 + b_kh * 16;

    float acc[4][4][4];
#pragma unroll
    for (int mi = 0; mi < 4; mi++)
#pragma unroll
        for (int ni = 0; ni < 4; ni++)
#pragma unroll
            for (int e = 0; e < 4; e++) acc[mi][ni][e] = 0.f;

    // prologue
    load_tile(0, 0);
    load_tile(1, 1);

    for (int kt = 0; kt < NKT; ++kt) {
        const int cur = kt % 3;

        if (kt < NKT - 1) CP_WAIT(1); else CP_WAIT(0);
        __syncthreads();

        if (kt + 2 < NKT) load_tile((kt + 2) % 3, kt + 2);

        const uint32_t sb = dynb + cur * STAGE_BYTES;
#pragma unroll
        for (int s = 0; s < 2; ++s) {               // two k16 steps per tile
            uint32_t afr[4][4];
            uint32_t bfr[2][4];
#pragma unroll
            for (int mi = 0; mi < 4; mi++)
                ldsm4(afr[mi], sb + a_base + mi * 16 * 80 + s * 32);
#pragma unroll
            for (int nj = 0; nj < 2; nj++)
                ldsm4(bfr[nj], sb + b_base + nj * 16 * 80 + s * 32);
#pragma unroll
            for (int mi = 0; mi < 4; mi++) {
#pragma unroll
                for (int ni = 0; ni < 4; ni++) {
                    uint32_t b0 = bfr[ni >> 1][(ni & 1) * 2 + 0];
                    uint32_t b1 = bfr[ni >> 1][(ni & 1) * 2 + 1];
                    mma16816(acc[mi][ni], afr[mi], b0, b1);
                }
            }
        }
    }

    // epilogue: acc -> global + bias
    const int row0 = mblk + warp_m + (lane >> 2);
    const int col0 = nblk + warp_n + (lane & 3) * 2;
    float2 bb[4];
#pragma unroll
    for (int ni = 0; ni < 4; ni++) {
        int n = col0 + ni * 8;
        bb[ni].x = __ldg(&bias[n]);
        bb[ni].y = __ldg(&bias[n + 1]);
    }
#pragma unroll
    for (int mi = 0; mi < 4; mi++) {
        int r0 = row0 + mi * 16;
#pragma unroll
        for (int ni = 0; ni < 4; ni++) {
            int n = col0 + ni * 8;
            float2 v0 = make_float2(acc[mi][ni][0] + bb[ni].x, acc[mi][ni][1] + bb[ni].y);
            float2 v1 = make_float2(acc[mi][ni][2] + bb[ni].x, acc[mi][ni][3] + bb[ni].y);
            *reinterpret_cast<float2*>(C + (size_t)r0 * D_ + n)       = v0;
            *reinterpret_cast<float2*>(C + (size_t)(r0 + 8) * D_ + n) = v1;
        }
    }
}

// ---------------------------------------------------------------------------
// Fused attention per (bs, head) — writes fp16 hi/lo split for the O GEMM
// ---------------------------------------------------------------------------
__global__ __launch_bounds__(128) void attn_kernel(const float* __restrict__ Q,
                                                   const float* __restrict__ K,
                                                   const float* __restrict__ V,
                                                   const float* __restrict__ upen,
                                                   __half* __restrict__ O) {
    int bs = blockIdx.x, h = blockIdx.y;
    __shared__ float Qs[32][64];
    __shared__ float Ks[32][64];
    __shared__ float Vs[32][64];
    __shared__ float Sc[32][33];

    int tid = threadIdx.x;
    const float* qb = Q + (size_t)(bs * T_) * D_ + h * HD_;
    const float* kb = K + (size_t)(bs * T_) * D_ + h * HD_;
    const float* vb = V + (size_t)(bs * T_) * D_ + h * HD_;

    for (int i = tid; i < 512; i += 128) {
        int r = i >> 4, c = (i & 15) * 4;
        *reinterpret_cast<float4*>(&Qs[r][c]) = *reinterpret_cast<const float4*>(&qb[(size_t)r * D_ + c]);
        *reinterpret_cast<float4*>(&Ks[r][c]) = *reinterpret_cast<const float4*>(&kb[(size_t)r * D_ + c]);
        *reinterpret_cast<float4*>(&Vs[r][c]) = *reinterpret_cast<const float4*>(&vb[(size_t)r * D_ + c]);
    }
    __syncthreads();

    for (int i = tid; i < 1024; i += 128) {
        int q = i >> 5, k = i & 31;
        float s = 0.f;
#pragma unroll
        for (int d = 0; d < HD_; d++) s += Qs[q][d] * Ks[k][d];
        Sc[q][k] = s * 0.125f - upen[bs * T_ + k];
    }
    __syncthreads();

    if (tid < 32) {
        float mx = -1e30f;
#pragma unroll
        for (int k = 0; k < 32; k++) mx = fmaxf(mx, Sc[tid][k]);
        float sum = 0.f;
#pragma unroll
        for (int k = 0; k < 32; k++) { float e = __expf(Sc[tid][k] - mx); Sc[tid][k] = e; sum += e; }
        float inv = 1.f / sum;
#pragma unroll
        for (int k = 0; k < 32; k++) Sc[tid][k] *= inv;
    }
    __syncthreads();

    __half* ob = O + (size_t)(bs * T_) * K2_ + h * HD_;
    for (int i = tid; i < 2048; i += 128) {
        int t = i >> 6, d = i & 63;
        float s = 0.f;
#pragma unroll
        for (int k = 0; k < 32; k++) s += Sc[t][k] * Vs[k][d];
        __half hi = __float2half(s);
        __half lo = __float2half(s - __half2float(hi));
        size_t base = (size_t)t * K2_ + d;
        ob[base]      = hi;
        ob[base + D_] = lo;
    }
}

// ---------------------------------------------------------------------------
extern "C" void kernel_launch(void* const* d_in, const int* in_sizes, int n_in,
                              void* d_out, int out_size) {
    const float* h   = (const float*)d_in[0];
    const float* u   = (const float*)d_in[1];
    const float* lam = (const float*)d_in[2];
    const float* Wq  = (const float*)d_in[3];
    const float* bq  = (const float*)d_in[4];
    const float* Wk  = (const float*)d_in[5];
    const float* bk  = (const float*)d_in[6];
    const float* Wv  = (const float*)d_in[7];
    const float* bv  = (const float*)d_in[8];
    const float* Wo  = (const float*)d_in[9];
    const float* bo  = (const float*)d_in[10];
    float* out = (float*)d_out;

    __half *hsp, *asp, *wq, *wk, *wv, *wo;
    float *Qb, *Kb, *Vb, *oseq, *upen;
    cudaGetSymbolAddress((void**)&hsp,  g_hsplit);
    cudaGetSymbolAddress((void**)&asp,  g_asplit);
    cudaGetSymbolAddress((void**)&wq,   g_wq);
    cudaGetSymbolAddress((void**)&wk,   g_wk);
    cudaGetSymbolAddress((void**)&wv,   g_wv);
    cudaGetSymbolAddress((void**)&wo,   g_wo);
    cudaGetSymbolAddress((void**)&Qb,   g_Q);
    cudaGetSymbolAddress((void**)&Kb,   g_K);
    cudaGetSymbolAddress((void**)&Vb,   g_V);
    cudaGetSymbolAddress((void**)&oseq, g_oseq);
    cudaGetSymbolAddress((void**)&upen, g_upen);

    cudaFuncSetAttribute(gemm_mma, cudaFuncAttributeMaxDynamicSharedMemorySize,
                         3 * STAGE_BYTES);

    dim3 tgrid(8, 24, 128), tblk(32, 32);
    transpose_in_split<<<tgrid, tblk>>>(h, hsp);
    upen_kernel<<<128, 256>>>(u, lam, upen);
    wsplit<<<(D_ * D_) / 256, 256>>>(Wq, wq);
    wsplit<<<(D_ * D_) / 256, 256>>>(Wk, wk);
    wsplit<<<(D_ * D_) / 256, 256>>>(Wv, wv);
    wsplit<<<(D_ * D_) / 256, 256>>>(Wo, wo);

    dim3 ggrid(D_ / BN, M_ / BM);          // (6, 256)
    size_t smem = 3 * STAGE_BYTES;
    gemm_mma<<<ggrid, 256, smem>>>(hsp, wq, bq, Qb);
    gemm_mma<<<ggrid, 256, smem>>>(hsp, wk, bk, Kb);
    gemm_mma<<<ggrid, 256, smem>>>(hsp, wv, bv, Vb);

    dim3 agrid(BS_, NH_);
    attn_kernel<<<agrid, 128>>>(Qb, Kb, Vb, upen, asp);

    gemm_mma<<<ggrid, 256, smem>>>(asp, wo, bo, oseq);

    transpose_out<<<tgrid, tblk>>>(oseq, out);
}

// round 6
// speedup vs baseline: 3.2277x; 1.1416x over previous
#include <cuda_runtime.h>
#include <cuda_fp16.h>
#include <cstdint>

// Problem constants
#define B_   4
#define T_   32
#define D_   768
#define P_   256
#define BS_  1024
#define M_   32768
#define NH_  12
#define HD_  64
#define K2_  1536          // 2 * 768 (fp16 hi/lo split on the A side)
#define NQKV 2304          // fused Q|K|V output width

// GEMM tiling: 128x256x64, 8 warps (2x4), warp tile 64x64
#define BM   128
#define BN   256
#define BK   64
#define NKT  (K2_ / BK)    // 24
#define A_TILE_BYTES (BM * 128)          // 16384 (BK=64 fp16 -> 128B rows)
#define B_TILE_BYTES (BN * 128)          // 32768
#define STAGE_BYTES (A_TILE_BYTES + B_TILE_BYTES)  // 49152
#define A_OFF 0
#define B_OFF A_TILE_BYTES

#define SW128(b) ((b) ^ (((b) >> 3) & 0x70))

// ---------------- scratch (device globals; no cudaMalloc allowed) ----------
__device__ __half g_hsplit[(size_t)M_ * K2_];    // h_seq [hi, lo]
__device__ __half g_asplit[(size_t)M_ * K2_];    // attention out [hi, lo]
__device__ __half g_wqkv[(size_t)NQKV * K2_];    // fused Wq|Wk|Wv, [w, w] dup
__device__ __half g_wo  [(size_t)D_ * K2_];
__device__ float g_bqkv[NQKV];
__device__ float g_QKV [(size_t)M_ * NQKV];      // fused Q|K|V
__device__ float g_oseq[(size_t)M_ * D_];
__device__ float g_upen[M_];

// ---------------- PTX helpers (base-PTX, sm_80-era) ------------------------
__device__ __forceinline__ uint32_t smem_u32(const void* p) {
    uint32_t a;
    asm("{ .reg .u64 t; cvta.to.shared.u64 t, %1; cvt.u32.u64 %0, t; }"
        : "=r"(a) : "l"(p));
    return a;
}

__device__ __forceinline__ void cp16(uint32_t dst, const void* src) {
    asm volatile("cp.async.cg.shared.global [%0], [%1], 16;" :: "r"(dst), "l"(src));
}
#define CP_COMMIT() asm volatile("cp.async.commit_group;" ::: "memory")
#define CP_WAIT(n)  asm volatile("cp.async.wait_group %0;" :: "n"(n) : "memory")

__device__ __forceinline__ void ldsm4(uint32_t (&r)[4], uint32_t addr) {
    asm volatile("ldmatrix.sync.aligned.m8n8.x4.shared.b16 {%0,%1,%2,%3}, [%4];"
                 : "=r"(r[0]), "=r"(r[1]), "=r"(r[2]), "=r"(r[3]) : "r"(addr));
}

__device__ __forceinline__ void mma16816(float (&d)[4], const uint32_t (&a)[4],
                                         uint32_t b0, uint32_t b1) {
    asm volatile(
        "mma.sync.aligned.m16n8k16.row.col.f32.f16.f16.f32 "
        "{%0,%1,%2,%3}, {%4,%5,%6,%7}, {%8,%9}, {%0,%1,%2,%3};"
        : "+f"(d[0]), "+f"(d[1]), "+f"(d[2]), "+f"(d[3])
        : "r"(a[0]), "r"(a[1]), "r"(a[2]), "r"(a[3]), "r"(b0), "r"(b1));
}

// ---------------------------------------------------------------------------
// transpose + fp16 hi/lo split
// ---------------------------------------------------------------------------
__global__ __launch_bounds__(1024) void transpose_in_split(const float* __restrict__ src,
                                                           __half* __restrict__ dst) {
    __shared__ float tile[32][33];
    int bt = blockIdx.z, b = bt >> 5, t = bt & 31;
    int dblk = blockIdx.y * 32, pblk = blockIdx.x * 32;

    int d = dblk + threadIdx.y, p = pblk + threadIdx.x;
    tile[threadIdx.y][threadIdx.x] = src[((size_t)bt * D_ + d) * P_ + p];
    __syncthreads();
    int d2 = dblk + threadIdx.x, p2 = pblk + threadIdx.y;
    float v = tile[threadIdx.x][threadIdx.y];
    __half hi = __float2half(v);
    __half lo = __float2half(v - __half2float(hi));
    size_t base = (((size_t)(b * P_ + p2)) * T_ + t) * K2_ + d2;
    dst[base]      = hi;
    dst[base + D_] = lo;
}

// ---------------------------------------------------------------------------
// weight convert: W (N x D fp32) -> Ws (N x K2) = [w, w] fp16 duplicated
// ---------------------------------------------------------------------------
__global__ __launch_bounds__(256) void wsplit(const float* __restrict__ W,
                                              __half* __restrict__ Ws) {
    int i = blockIdx.x * 256 + threadIdx.x;
    int n = i / D_, d = i % D_;
    __half w = __float2half(W[i]);
    size_t base = (size_t)n * K2_ + d;
    Ws[base]      = w;
    Ws[base + D_] = w;
}

__global__ __launch_bounds__(256) void pack_bias(const float* __restrict__ bq,
                                                 const float* __restrict__ bk,
                                                 const float* __restrict__ bv,
                                                 float* __restrict__ dst) {
    int i = blockIdx.x * 256 + threadIdx.x;
    if (i >= NQKV) return;
    float v = (i < D_) ? bq[i] : (i < 2 * D_) ? bk[i - D_] : bv[i - 2 * D_];
    dst[i] = v;
}

// ---------------------------------------------------------------------------
// (bs, t, d) -> (B,T,D,P)
// ---------------------------------------------------------------------------
__global__ __launch_bounds__(1024) void transpose_out(const float* __restrict__ src,
                                                      float* __restrict__ dst) {
    __shared__ float tile[32][33];
    int bt = blockIdx.z, b = bt >> 5, t = bt & 31;
    int dblk = blockIdx.y * 32, pblk = blockIdx.x * 32;

    int d = dblk + threadIdx.x, p = pblk + threadIdx.y;
    tile[threadIdx.y][threadIdx.x] = src[(((size_t)(b * P_ + p)) * T_ + t) * D_ + d];
    __syncthreads();
    int p2 = pblk + threadIdx.x, d2 = dblk + threadIdx.y;
    dst[((size_t)bt * D_ + d2) * P_ + p2] = tile[threadIdx.x][threadIdx.y];
}

// ---------------------------------------------------------------------------
// u_pen
// ---------------------------------------------------------------------------
__global__ __launch_bounds__(256) void upen_kernel(const float* __restrict__ u,
                                                   const float* __restrict__ lam,
                                                   float* __restrict__ upen) {
    int bt = blockIdx.x, b = bt >> 5, t = bt & 31;
    int p = threadIdx.x;
    const float* up = u + (size_t)bt * D_ * P_ + p;
    float acc = 0.f;
#pragma unroll 8
    for (int d = 0; d < D_; d++) acc += up[(size_t)d * P_];
    upen[(b * P_ + p) * T_ + t] = lam[(size_t)bt * P_ + p] * acc * (1.0f / (float)D_);
}

// ---------------------------------------------------------------------------
// HMMA GEMM:  C[M, ldc] tile = A'[M,1536] @ Ws'[ldc,1536]^T + bias
// 128x256x64 tile, 3-stage cp.async, 8 warps x (64x64) warp tiles, SW128.
// ---------------------------------------------------------------------------
__global__ __launch_bounds__(256) void gemm_mma(const __half* __restrict__ A,
                                                const __half* __restrict__ Wt,
                                                const float* __restrict__ bias,
                                                float* __restrict__ C,
                                                int ldc) {
    extern __shared__ __align__(128) char dyn[];
    const uint32_t dynb = smem_u32(dyn);

    const int tid  = threadIdx.x;
    const int wid  = tid >> 5;
    const int lane = tid & 31;
    const int mblk = blockIdx.y * BM;
    const int nblk = blockIdx.x * BN;

    const int warp_m = (wid >> 2) * 64;   // 0 or 64
    const int warp_n = (wid & 3) * 64;    // 0,64,128,192

    const __half* Ab = A  + (size_t)mblk * K2_;
    const __half* Bb = Wt + (size_t)nblk * K2_;

    // 3072 x 16B chunks per stage / 256 threads = 12 per thread
    auto load_tile = [&](int stage, int kt) {
        uint32_t sb = dynb + stage * STAGE_BYTES;
        const __half* Ak = Ab + kt * BK;
        const __half* Bk = Bb + kt * BK;
#pragma unroll
        for (int i = 0; i < 12; ++i) {
            int c = tid + 256 * i;
            if (c < 1024) {                       // A: 128 rows x 8 chunks
                int r = c >> 3, kc = c & 7;
                cp16(sb + A_OFF + SW128(r * 128 + kc * 16),
                     Ak + (size_t)r * K2_ + kc * 8);
            } else {                              // B: 256 rows x 8 chunks
                int c2 = c - 1024;
                int r = c2 >> 3, kc = c2 & 7;
                cp16(sb + B_OFF + SW128(r * 128 + kc * 16),
                     Bk + (size_t)r * K2_ + kc * 8);
            }
        }
        CP_COMMIT();
    };

    // ldmatrix lane address components
    const int a_row = warp_m + (lane & 15);
    const int a_kh  = lane >> 4;                       // 0/1 -> 16B col within k16
    const int b_row = warp_n + (lane & 7) + ((lane >> 4) << 3);
    const int b_kh  = (lane >> 3) & 1;

    float acc[4][8][4];
#pragma unroll
    for (int mi = 0; mi < 4; mi++)
#pragma unroll
        for (int ni = 0; ni < 8; ni++)
#pragma unroll
            for (int e = 0; e < 4; e++) acc[mi][ni][e] = 0.f;

    load_tile(0, 0);
    load_tile(1, 1);

    for (int kt = 0; kt < NKT; ++kt) {
        const int cur = kt % 3;

        if (kt < NKT - 1) CP_WAIT(1); else CP_WAIT(0);
        __syncthreads();

        if (kt + 2 < NKT) load_tile((kt + 2) % 3, kt + 2);

        const uint32_t sb = dynb + cur * STAGE_BYTES;
#pragma unroll
        for (int s = 0; s < 4; ++s) {             // four k16 steps per BK=64
            uint32_t afr[4][4];
            uint32_t bfr[4][4];
#pragma unroll
            for (int mi = 0; mi < 4; mi++)
                ldsm4(afr[mi], sb + A_OFF +
                      SW128((a_row + mi * 16) * 128 + (s * 2 + a_kh) * 16));
#pragma unroll
            for (int nj = 0; nj < 4; nj++)
                ldsm4(bfr[nj], sb + B_OFF +
                      SW128((b_row + nj * 16) * 128 + (s * 2 + b_kh) * 16));
#pragma unroll
            for (int mi = 0; mi < 4; mi++) {
#pragma unroll
                for (int ni = 0; ni < 8; ni++) {
                    uint32_t b0 = bfr[ni >> 1][(ni & 1) * 2 + 0];
                    uint32_t b1 = bfr[ni >> 1][(ni & 1) * 2 + 1];
                    mma16816(acc[mi][ni], afr[mi], b0, b1);
                }
            }
        }
    }

    // epilogue
    const int row0 = mblk + warp_m + (lane >> 2);
    const int col0 = nblk + warp_n + (lane & 3) * 2;
    float2 bb[8];
#pragma unroll
    for (int ni = 0; ni < 8; ni++) {
        int n = col0 + ni * 8;
        bb[ni].x = __ldg(&bias[n]);
        bb[ni].y = __ldg(&bias[n + 1]);
    }
#pragma unroll
    for (int mi = 0; mi < 4; mi++) {
        int r0 = row0 + mi * 16;
#pragma unroll
        for (int ni = 0; ni < 8; ni++) {
            int n = col0 + ni * 8;
            float2 v0 = make_float2(acc[mi][ni][0] + bb[ni].x, acc[mi][ni][1] + bb[ni].y);
            float2 v1 = make_float2(acc[mi][ni][2] + bb[ni].x, acc[mi][ni][3] + bb[ni].y);
            *reinterpret_cast<float2*>(C + (size_t)r0 * ldc + n)       = v0;
            *reinterpret_cast<float2*>(C + (size_t)(r0 + 8) * ldc + n) = v1;
        }
    }
}

// ---------------------------------------------------------------------------
// Fused attention per (bs, head), reads fused QKV (stride NQKV)
// ---------------------------------------------------------------------------
__global__ __launch_bounds__(128) void attn_kernel(const float* __restrict__ QKV,
                                                   const float* __restrict__ upen,
                                                   __half* __restrict__ O) {
    int bs = blockIdx.x, h = blockIdx.y;
    __shared__ float Qs[32][64];
    __shared__ float Ks[32][64];
    __shared__ float Vs[32][64];
    __shared__ float Sc[32][33];

    int tid = threadIdx.x;
    const float* qb = QKV + (size_t)(bs * T_) * NQKV + h * HD_;
    const float* kb = qb + D_;
    const float* vb = qb + 2 * D_;

    for (int i = tid; i < 512; i += 128) {
        int r = i >> 4, c = (i & 15) * 4;
        *reinterpret_cast<float4*>(&Qs[r][c]) = *reinterpret_cast<const float4*>(&qb[(size_t)r * NQKV + c]);
        *reinterpret_cast<float4*>(&Ks[r][c]) = *reinterpret_cast<const float4*>(&kb[(size_t)r * NQKV + c]);
        *reinterpret_cast<float4*>(&Vs[r][c]) = *reinterpret_cast<const float4*>(&vb[(size_t)r * NQKV + c]);
    }
    __syncthreads();

    for (int i = tid; i < 1024; i += 128) {
        int q = i >> 5, k = i & 31;
        float s = 0.f;
#pragma unroll
        for (int d = 0; d < HD_; d++) s += Qs[q][d] * Ks[k][d];
        Sc[q][k] = s * 0.125f - upen[bs * T_ + k];
    }
    __syncthreads();

    if (tid < 32) {
        float mx = -1e30f;
#pragma unroll
        for (int k = 0; k < 32; k++) mx = fmaxf(mx, Sc[tid][k]);
        float sum = 0.f;
#pragma unroll
        for (int k = 0; k < 32; k++) { float e = __expf(Sc[tid][k] - mx); Sc[tid][k] = e; sum += e; }
        float inv = 1.f / sum;
#pragma unroll
        for (int k = 0; k < 32; k++) Sc[tid][k] *= inv;
    }
    __syncthreads();

    __half* ob = O + (size_t)(bs * T_) * K2_ + h * HD_;
    for (int i = tid; i < 2048; i += 128) {
        int t = i >> 6, d = i & 63;
        float s = 0.f;
#pragma unroll
        for (int k = 0; k < 32; k++) s += Sc[t][k] * Vs[k][d];
        __half hi = __float2half(s);
        __half lo = __float2half(s - __half2float(hi));
        size_t base = (size_t)t * K2_ + d;
        ob[base]      = hi;
        ob[base + D_] = lo;
    }
}

// ---------------------------------------------------------------------------
extern "C" void kernel_launch(void* const* d_in, const int* in_sizes, int n_in,
                              void* d_out, int out_size) {
    const float* h   = (const float*)d_in[0];
    const float* u   = (const float*)d_in[1];
    const float* lam = (const float*)d_in[2];
    const float* Wq  = (const float*)d_in[3];
    const float* bq  = (const float*)d_in[4];
    const float* Wk  = (const float*)d_in[5];
    const float* bk  = (const float*)d_in[6];
    const float* Wv  = (const float*)d_in[7];
    const float* bv  = (const float*)d_in[8];
    const float* Wo  = (const float*)d_in[9];
    const float* bo  = (const float*)d_in[10];
    float* out = (float*)d_out;

    __half *hsp, *asp, *wqkv, *wo;
    float *bqkv, *QKV, *oseq, *upen;
    cudaGetSymbolAddress((void**)&hsp,  g_hsplit);
    cudaGetSymbolAddress((void**)&asp,  g_asplit);
    cudaGetSymbolAddress((void**)&wqkv, g_wqkv);
    cudaGetSymbolAddress((void**)&wo,   g_wo);
    cudaGetSymbolAddress((void**)&bqkv, g_bqkv);
    cudaGetSymbolAddress((void**)&QKV,  g_QKV);
    cudaGetSymbolAddress((void**)&oseq, g_oseq);
    cudaGetSymbolAddress((void**)&upen, g_upen);

    cudaFuncSetAttribute(gemm_mma, cudaFuncAttributeMaxDynamicSharedMemorySize,
                         3 * STAGE_BYTES);

    dim3 tgrid(8, 24, 128), tblk(32, 32);
    transpose_in_split<<<tgrid, tblk>>>(h, hsp);
    upen_kernel<<<128, 256>>>(u, lam, upen);
    wsplit<<<(D_ * D_) / 256, 256>>>(Wq, wqkv);
    wsplit<<<(D_ * D_) / 256, 256>>>(Wk, wqkv + (size_t)D_ * K2_);
    wsplit<<<(D_ * D_) / 256, 256>>>(Wv, wqkv + (size_t)2 * D_ * K2_);
    wsplit<<<(D_ * D_) / 256, 256>>>(Wo, wo);
    pack_bias<<<(NQKV + 255) / 256, 256>>>(bq, bk, bv, bqkv);

    size_t smem = 3 * STAGE_BYTES;

    // fused QKV projection: C[M, 2304]
    dim3 qgrid(NQKV / BN, M_ / BM);        // (9, 256)
    gemm_mma<<<qgrid, 256, smem>>>(hsp, wqkv, bqkv, QKV, NQKV);

    dim3 agrid(BS_, NH_);
    attn_kernel<<<agrid, 128>>>(QKV, upen, asp);

    // O projection: C[M, 768]
    dim3 ogrid(D_ / BN, M_ / BM);          // (3, 256)
    gemm_mma<<<ogrid, 256, smem>>>(asp, wo, bo, oseq, D_);

    transpose_out<<<tgrid, tblk>>>(oseq, out);
}

// round 7
// speedup vs baseline: 3.4541x; 1.0702x over previous
#include <cuda_runtime.h>
#include <cuda_fp16.h>
#include <cstdint>

// Problem constants
#define B_   4
#define T_   32
#define D_   768
#define P_   256
#define BS_  1024
#define M_   32768
#define NH_  12
#define HD_  64
#define K2_  1536          // A stored as [hi(768) | lo(768)]
#define NQKV 2304          // fused Q|K|V output width

// GEMM tiling: 128x256, K-loop over 768 in BK=64, 8 warps (2x4), warp 64x64
#define BM   128
#define BN   256
#define BK   64
#define NKT  (D_ / BK)     // 12
#define AH_OFF 0
#define AL_OFF 16384
#define B_OFF  32768
#define STAGE_BYTES 65536  // A_hi 16K + A_lo 16K + B 32K

#define SW128(b) ((b) ^ (((b) >> 3) & 0x70))

// ---------------- scratch (device globals; no cudaMalloc allowed) ----------
__device__ __half g_hsplit[(size_t)M_ * K2_];    // h_seq [hi | lo]
__device__ __half g_asplit[(size_t)M_ * K2_];    // attention out [hi | lo]
__device__ __half g_wqkv[(size_t)NQKV * D_];     // fused Wq|Wk|Wv fp16
__device__ __half g_wo  [(size_t)D_ * D_];
__device__ float g_bqkv[NQKV];
__device__ float g_QKV [(size_t)M_ * NQKV];      // fused Q|K|V
__device__ float g_oseq[(size_t)M_ * D_];
__device__ float g_upen[M_];

// ---------------- PTX helpers (base-PTX, sm_80-era) ------------------------
__device__ __forceinline__ uint32_t smem_u32(const void* p) {
    uint32_t a;
    asm("{ .reg .u64 t; cvta.to.shared.u64 t, %1; cvt.u32.u64 %0, t; }"
        : "=r"(a) : "l"(p));
    return a;
}

__device__ __forceinline__ void cp16(uint32_t dst, const void* src) {
    asm volatile("cp.async.cg.shared.global [%0], [%1], 16;" :: "r"(dst), "l"(src));
}
#define CP_COMMIT() asm volatile("cp.async.commit_group;" ::: "memory")
#define CP_WAIT(n)  asm volatile("cp.async.wait_group %0;" :: "n"(n) : "memory")

__device__ __forceinline__ void ldsm4(uint32_t (&r)[4], uint32_t addr) {
    asm volatile("ldmatrix.sync.aligned.m8n8.x4.shared.b16 {%0,%1,%2,%3}, [%4];"
                 : "=r"(r[0]), "=r"(r[1]), "=r"(r[2]), "=r"(r[3]) : "r"(addr));
}

__device__ __forceinline__ void mma16816(float (&d)[4], const uint32_t (&a)[4],
                                         uint32_t b0, uint32_t b1) {
    asm volatile(
        "mma.sync.aligned.m16n8k16.row.col.f32.f16.f16.f32 "
        "{%0,%1,%2,%3}, {%4,%5,%6,%7}, {%8,%9}, {%0,%1,%2,%3};"
        : "+f"(d[0]), "+f"(d[1]), "+f"(d[2]), "+f"(d[3])
        : "r"(a[0]), "r"(a[1]), "r"(a[2]), "r"(a[3]), "r"(b0), "r"(b1));
}

// ---------------------------------------------------------------------------
// transpose + fp16 hi/lo split
// ---------------------------------------------------------------------------
__global__ __launch_bounds__(1024) void transpose_in_split(const float* __restrict__ src,
                                                           __half* __restrict__ dst) {
    __shared__ float tile[32][33];
    int bt = blockIdx.z, b = bt >> 5, t = bt & 31;
    int dblk = blockIdx.y * 32, pblk = blockIdx.x * 32;

    int d = dblk + threadIdx.y, p = pblk + threadIdx.x;
    tile[threadIdx.y][threadIdx.x] = src[((size_t)bt * D_ + d) * P_ + p];
    __syncthreads();
    int d2 = dblk + threadIdx.x, p2 = pblk + threadIdx.y;
    float v = tile[threadIdx.x][threadIdx.y];
    __half hi = __float2half(v);
    __half lo = __float2half(v - __half2float(hi));
    size_t base = (((size_t)(b * P_ + p2)) * T_ + t) * K2_ + d2;
    dst[base]      = hi;
    dst[base + D_] = lo;
}

// ---------------------------------------------------------------------------
// weight convert: W (N x D fp32) -> fp16 (single copy, no duplication)
// ---------------------------------------------------------------------------
__global__ __launch_bounds__(256) void wconv(const float* __restrict__ W,
                                             __half* __restrict__ Ws) {
    int i = blockIdx.x * 256 + threadIdx.x;
    Ws[i] = __float2half(W[i]);
}

__global__ __launch_bounds__(256) void pack_bias(const float* __restrict__ bq,
                                                 const float* __restrict__ bk,
                                                 const float* __restrict__ bv,
                                                 float* __restrict__ dst) {
    int i = blockIdx.x * 256 + threadIdx.x;
    if (i >= NQKV) return;
    float v = (i < D_) ? bq[i] : (i < 2 * D_) ? bk[i - D_] : bv[i - 2 * D_];
    dst[i] = v;
}

// ---------------------------------------------------------------------------
// (bs, t, d) -> (B,T,D,P)
// ---------------------------------------------------------------------------
__global__ __launch_bounds__(1024) void transpose_out(const float* __restrict__ src,
                                                      float* __restrict__ dst) {
    __shared__ float tile[32][33];
    int bt = blockIdx.z, b = bt >> 5, t = bt & 31;
    int dblk = blockIdx.y * 32, pblk = blockIdx.x * 32;

    int d = dblk + threadIdx.x, p = pblk + threadIdx.y;
    tile[threadIdx.y][threadIdx.x] = src[(((size_t)(b * P_ + p)) * T_ + t) * D_ + d];
    __syncthreads();
    int p2 = pblk + threadIdx.x, d2 = dblk + threadIdx.y;
    dst[((size_t)bt * D_ + d2) * P_ + p2] = tile[threadIdx.x][threadIdx.y];
}

// ---------------------------------------------------------------------------
// u_pen
// ---------------------------------------------------------------------------
__global__ __launch_bounds__(256) void upen_kernel(const float* __restrict__ u,
                                                   const float* __restrict__ lam,
                                                   float* __restrict__ upen) {
    int bt = blockIdx.x, b = bt >> 5, t = bt & 31;
    int p = threadIdx.x;
    const float* up = u + (size_t)bt * D_ * P_ + p;
    float acc = 0.f;
#pragma unroll 8
    for (int d = 0; d < D_; d++) acc += up[(size_t)d * P_];
    upen[(b * P_ + p) * T_ + t] = lam[(size_t)bt * P_ + p] * acc * (1.0f / (float)D_);
}

// ---------------------------------------------------------------------------
// HMMA GEMM with B-fragment reuse:
//   C = (A_hi + A_lo) @ W^T + bias,  K = 768
// Per k16 step: ldsm B once, MMA with a_hi then a_lo into same accumulator.
// 128x256 tile, BK=64, 3-stage cp.async, 8 warps x (64x64), SW128 smem.
// ---------------------------------------------------------------------------
__global__ __launch_bounds__(256) void gemm_mma(const __half* __restrict__ A,
                                                const __half* __restrict__ Wt,
                                                const float* __restrict__ bias,
                                                float* __restrict__ C,
                                                int ldc) {
    extern __shared__ __align__(128) char dyn[];
    const uint32_t dynb = smem_u32(dyn);

    const int tid  = threadIdx.x;
    const int wid  = tid >> 5;
    const int lane = tid & 31;
    const int mblk = blockIdx.y * BM;
    const int nblk = blockIdx.x * BN;

    const int warp_m = (wid >> 2) * 64;   // 0 or 64
    const int warp_n = (wid & 3) * 64;    // 0,64,128,192

    const __half* Ab = A  + (size_t)mblk * K2_;       // row stride K2 (hi|lo)
    const __half* Bb = Wt + (size_t)nblk * D_;        // row stride 768

    // 4096 x 16B chunks per stage / 256 threads = 16 per thread
    auto load_tile = [&](int stage, int kt) {
        uint32_t sb = dynb + stage * STAGE_BYTES;
        const __half* Ah = Ab + kt * BK;              // hi cols
        const __half* Al = Ah + D_;                   // lo cols
        const __half* Bk = Bb + kt * BK;
#pragma unroll
        for (int i = 0; i < 16; ++i) {
            int c = tid + 256 * i;
            if (c < 1024) {                           // A_hi: 128 rows x 8
                int r = c >> 3, kc = c & 7;
                cp16(sb + AH_OFF + SW128(r * 128 + kc * 16),
                     Ah + (size_t)r * K2_ + kc * 8);
            } else if (c < 2048) {                    // A_lo
                int c2 = c - 1024;
                int r = c2 >> 3, kc = c2 & 7;
                cp16(sb + AL_OFF + SW128(r * 128 + kc * 16),
                     Al + (size_t)r * K2_ + kc * 8);
            } else {                                  // B: 256 rows x 8
                int c2 = c - 2048;
                int r = c2 >> 3, kc = c2 & 7;
                cp16(sb + B_OFF + SW128(r * 128 + kc * 16),
                     Bk + (size_t)r * D_ + kc * 8);
            }
        }
        CP_COMMIT();
    };

    // ldmatrix lane address components
    const int a_row = warp_m + (lane & 15);
    const int a_kh  = lane >> 4;
    const int b_row = warp_n + (lane & 7) + ((lane >> 4) << 3);
    const int b_kh  = (lane >> 3) & 1;

    float acc[4][8][4];
#pragma unroll
    for (int mi = 0; mi < 4; mi++)
#pragma unroll
        for (int ni = 0; ni < 8; ni++)
#pragma unroll
            for (int e = 0; e < 4; e++) acc[mi][ni][e] = 0.f;

    load_tile(0, 0);
    load_tile(1, 1);

    for (int kt = 0; kt < NKT; ++kt) {
        const int cur = kt % 3;

        if (kt < NKT - 1) CP_WAIT(1); else CP_WAIT(0);
        __syncthreads();

        if (kt + 2 < NKT) load_tile((kt + 2) % 3, kt + 2);

        const uint32_t sb = dynb + cur * STAGE_BYTES;
#pragma unroll
        for (int s = 0; s < 4; ++s) {             // four k16 steps per BK=64
            uint32_t bfr[4][4];
#pragma unroll
            for (int nj = 0; nj < 4; nj++)
                ldsm4(bfr[nj], sb + B_OFF +
                      SW128((b_row + nj * 16) * 128 + (s * 2 + b_kh) * 16));
            // part 0: A_hi, part 1: A_lo — same B fragments, same accumulator
#pragma unroll
            for (int part = 0; part < 2; ++part) {
                const uint32_t a_off = part ? AL_OFF : AH_OFF;
                uint32_t afr[4][4];
#pragma unroll
                for (int mi = 0; mi < 4; mi++)
                    ldsm4(afr[mi], sb + a_off +
                          SW128((a_row + mi * 16) * 128 + (s * 2 + a_kh) * 16));
#pragma unroll
                for (int mi = 0; mi < 4; mi++) {
#pragma unroll
                    for (int ni = 0; ni < 8; ni++) {
                        uint32_t b0 = bfr[ni >> 1][(ni & 1) * 2 + 0];
                        uint32_t b1 = bfr[ni >> 1][(ni & 1) * 2 + 1];
                        mma16816(acc[mi][ni], afr[mi], b0, b1);
                    }
                }
            }
        }
    }

    // epilogue
    const int row0 = mblk + warp_m + (lane >> 2);
    const int col0 = nblk + warp_n + (lane & 3) * 2;
    float2 bb[8];
#pragma unroll
    for (int ni = 0; ni < 8; ni++) {
        int n = col0 + ni * 8;
        bb[ni].x = __ldg(&bias[n]);
        bb[ni].y = __ldg(&bias[n + 1]);
    }
#pragma unroll
    for (int mi = 0; mi < 4; mi++) {
        int r0 = row0 + mi * 16;
#pragma unroll
        for (int ni = 0; ni < 8; ni++) {
            int n = col0 + ni * 8;
            float2 v0 = make_float2(acc[mi][ni][0] + bb[ni].x, acc[mi][ni][1] + bb[ni].y);
            float2 v1 = make_float2(acc[mi][ni][2] + bb[ni].x, acc[mi][ni][3] + bb[ni].y);
            *reinterpret_cast<float2*>(C + (size_t)r0 * ldc + n)       = v0;
            *reinterpret_cast<float2*>(C + (size_t)(r0 + 8) * ldc + n) = v1;
        }
    }
}

// ---------------------------------------------------------------------------
// Fused attention per (bs, head), reads fused QKV (stride NQKV)
// ---------------------------------------------------------------------------
__global__ __launch_bounds__(128) void attn_kernel(const float* __restrict__ QKV,
                                                   const float* __restrict__ upen,
                                                   __half* __restrict__ O) {
    int bs = blockIdx.x, h = blockIdx.y;
    __shared__ float Qs[32][64];
    __shared__ float Ks[32][64];
    __shared__ float Vs[32][64];
    __shared__ float Sc[32][33];

    int tid = threadIdx.x;
    const float* qb = QKV + (size_t)(bs * T_) * NQKV + h * HD_;
    const float* kb = qb + D_;
    const float* vb = qb + 2 * D_;

    for (int i = tid; i < 512; i += 128) {
        int r = i >> 4, c = (i & 15) * 4;
        *reinterpret_cast<float4*>(&Qs[r][c]) = *reinterpret_cast<const float4*>(&qb[(size_t)r * NQKV + c]);
        *reinterpret_cast<float4*>(&Ks[r][c]) = *reinterpret_cast<const float4*>(&kb[(size_t)r * NQKV + c]);
        *reinterpret_cast<float4*>(&Vs[r][c]) = *reinterpret_cast<const float4*>(&vb[(size_t)r * NQKV + c]);
    }
    __syncthreads();

    for (int i = tid; i < 1024; i += 128) {
        int q = i >> 5, k = i & 31;
        float s = 0.f;
#pragma unroll
        for (int d = 0; d < HD_; d++) s += Qs[q][d] * Ks[k][d];
        Sc[q][k] = s * 0.125f - upen[bs * T_ + k];
    }
    __syncthreads();

    if (tid < 32) {
        float mx = -1e30f;
#pragma unroll
        for (int k = 0; k < 32; k++) mx = fmaxf(mx, Sc[tid][k]);
        float sum = 0.f;
#pragma unroll
        for (int k = 0; k < 32; k++) { float e = __expf(Sc[tid][k] - mx); Sc[tid][k] = e; sum += e; }
        float inv = 1.f / sum;
#pragma unroll
        for (int k = 0; k < 32; k++) Sc[tid][k] *= inv;
    }
    __syncthreads();

    __half* ob = O + (size_t)(bs * T_) * K2_ + h * HD_;
    for (int i = tid; i < 2048; i += 128) {
        int t = i >> 6, d = i & 63;
        float s = 0.f;
#pragma unroll
        for (int k = 0; k < 32; k++) s += Sc[t][k] * Vs[k][d];
        __half hi = __float2half(s);
        __half lo = __float2half(s - __half2float(hi));
        size_t base = (size_t)t * K2_ + d;
        ob[base]      = hi;
        ob[base + D_] = lo;
    }
}

// ---------------------------------------------------------------------------
extern "C" void kernel_launch(void* const* d_in, const int* in_sizes, int n_in,
                              void* d_out, int out_size) {
    const float* h   = (const float*)d_in[0];
    const float* u   = (const float*)d_in[1];
    const float* lam = (const float*)d_in[2];
    const float* Wq  = (const float*)d_in[3];
    const float* bq  = (const float*)d_in[4];
    const float* Wk  = (const float*)d_in[5];
    const float* bk  = (const float*)d_in[6];
    const float* Wv  = (const float*)d_in[7];
    const float* bv  = (const float*)d_in[8];
    const float* Wo  = (const float*)d_in[9];
    const float* bo  = (const float*)d_in[10];
    float* out = (float*)d_out;

    __half *hsp, *asp, *wqkv, *wo;
    float *bqkv, *QKV, *oseq, *upen;
    cudaGetSymbolAddress((void**)&hsp,  g_hsplit);
    cudaGetSymbolAddress((void**)&asp,  g_asplit);
    cudaGetSymbolAddress((void**)&wqkv, g_wqkv);
    cudaGetSymbolAddress((void**)&wo,   g_wo);
    cudaGetSymbolAddress((void**)&bqkv, g_bqkv);
    cudaGetSymbolAddress((void**)&QKV,  g_QKV);
    cudaGetSymbolAddress((void**)&oseq, g_oseq);
    cudaGetSymbolAddress((void**)&upen, g_upen);

    cudaFuncSetAttribute(gemm_mma, cudaFuncAttributeMaxDynamicSharedMemorySize,
                         3 * STAGE_BYTES);

    dim3 tgrid(8, 24, 128), tblk(32, 32);
    transpose_in_split<<<tgrid, tblk>>>(h, hsp);
    upen_kernel<<<128, 256>>>(u, lam, upen);
    wconv<<<(D_ * D_) / 256, 256>>>(Wq, wqkv);
    wconv<<<(D_ * D_) / 256, 256>>>(Wk, wqkv + (size_t)D_ * D_);
    wconv<<<(D_ * D_) / 256, 256>>>(Wv, wqkv + (size_t)2 * D_ * D_);
    wconv<<<(D_ * D_) / 256, 256>>>(Wo, wo);
    pack_bias<<<(NQKV + 255) / 256, 256>>>(bq, bk, bv, bqkv);

    size_t smem = 3 * STAGE_BYTES;

    // fused QKV projection: C[M, 2304]
    dim3 qgrid(NQKV / BN, M_ / BM);        // (9, 256)
    gemm_mma<<<qgrid, 256, smem>>>(hsp, wqkv, bqkv, QKV, NQKV);

    dim3 agrid(BS_, NH_);
    attn_kernel<<<agrid, 128>>>(QKV, upen, asp);

    // O projection: C[M, 768]
    dim3 ogrid(D_ / BN, M_ / BM);          // (3, 256)
    gemm_mma<<<ogrid, 256, smem>>>(asp, wo, bo, oseq, D_);

    transpose_out<<<tgrid, tblk>>>(oseq, out);
}

// round 8
// speedup vs baseline: 3.7723x; 1.0921x over previous
#include <cuda_runtime.h>
#include <cuda_fp16.h>
#include <cstdint>

// Problem constants
#define B_   4
#define T_   32
#define D_   768
#define P_   256
#define BS_  1024
#define M_   32768
#define NH_  12
#define HD_  64
#define K2_  1536          // A stored as [hi(768) | lo(768)] for QKV GEMM
#define NQKV 2304          // fused Q|K|V output width

// GEMM tiling: 128x256, BK=64, 16 warps (4x4), warp tile 32x64
#define BM   128
#define BN   256
#define BK   64
#define NKT  (D_ / BK)     // 12

#define SW128(b) ((b) ^ (((b) >> 3) & 0x70))

// ---------------- scratch (device globals; no cudaMalloc allowed) ----------
__device__ __half g_hsplit[(size_t)M_ * K2_];    // h_seq [hi | lo]
__device__ __half g_aout  [(size_t)M_ * D_];     // attention out (single fp16)
__device__ __half g_wqkv[(size_t)NQKV * D_];     // fused Wq|Wk|Wv fp16
__device__ __half g_wo  [(size_t)D_ * D_];
__device__ float g_bqkv[NQKV];
__device__ float g_QKV [(size_t)M_ * NQKV];      // fused Q|K|V
__device__ float g_oseq[(size_t)M_ * D_];
__device__ float g_upen[M_];

// ---------------- PTX helpers (base-PTX, sm_80-era) ------------------------
__device__ __forceinline__ uint32_t smem_u32(const void* p) {
    uint32_t a;
    asm("{ .reg .u64 t; cvta.to.shared.u64 t, %1; cvt.u32.u64 %0, t; }"
        : "=r"(a) : "l"(p));
    return a;
}

__device__ __forceinline__ void cp16(uint32_t dst, const void* src) {
    asm volatile("cp.async.cg.shared.global [%0], [%1], 16;" :: "r"(dst), "l"(src));
}
#define CP_COMMIT() asm volatile("cp.async.commit_group;" ::: "memory")
#define CP_WAIT(n)  asm volatile("cp.async.wait_group %0;" :: "n"(n) : "memory")

__device__ __forceinline__ void ldsm4(uint32_t (&r)[4], uint32_t addr) {
    asm volatile("ldmatrix.sync.aligned.m8n8.x4.shared.b16 {%0,%1,%2,%3}, [%4];"
                 : "=r"(r[0]), "=r"(r[1]), "=r"(r[2]), "=r"(r[3]) : "r"(addr));
}

__device__ __forceinline__ void mma16816(float (&d)[4], const uint32_t (&a)[4],
                                         uint32_t b0, uint32_t b1) {
    asm volatile(
        "mma.sync.aligned.m16n8k16.row.col.f32.f16.f16.f32 "
        "{%0,%1,%2,%3}, {%4,%5,%6,%7}, {%8,%9}, {%0,%1,%2,%3};"
        : "+f"(d[0]), "+f"(d[1]), "+f"(d[2]), "+f"(d[3])
        : "r"(a[0]), "r"(a[1]), "r"(a[2]), "r"(a[3]), "r"(b0), "r"(b1));
}

// ---------------------------------------------------------------------------
// transpose + fp16 hi/lo split
// ---------------------------------------------------------------------------
__global__ __launch_bounds__(1024) void transpose_in_split(const float* __restrict__ src,
                                                           __half* __restrict__ dst) {
    __shared__ float tile[32][33];
    int bt = blockIdx.z, b = bt >> 5, t = bt & 31;
    int dblk = blockIdx.y * 32, pblk = blockIdx.x * 32;

    int d = dblk + threadIdx.y, p = pblk + threadIdx.x;
    tile[threadIdx.y][threadIdx.x] = src[((size_t)bt * D_ + d) * P_ + p];
    __syncthreads();
    int d2 = dblk + threadIdx.x, p2 = pblk + threadIdx.y;
    float v = tile[threadIdx.x][threadIdx.y];
    __half hi = __float2half(v);
    __half lo = __float2half(v - __half2float(hi));
    size_t base = (((size_t)(b * P_ + p2)) * T_ + t) * K2_ + d2;
    dst[base]      = hi;
    dst[base + D_] = lo;
}

// ---------------------------------------------------------------------------
// weight convert: W (N x D fp32) -> fp16
// ---------------------------------------------------------------------------
__global__ __launch_bounds__(256) void wconv(const float* __restrict__ W,
                                             __half* __restrict__ Ws) {
    int i = blockIdx.x * 256 + threadIdx.x;
    Ws[i] = __float2half(W[i]);
}

__global__ __launch_bounds__(256) void pack_bias(const float* __restrict__ bq,
                                                 const float* __restrict__ bk,
                                                 const float* __restrict__ bv,
                                                 float* __restrict__ dst) {
    int i = blockIdx.x * 256 + threadIdx.x;
    if (i >= NQKV) return;
    float v = (i < D_) ? bq[i] : (i < 2 * D_) ? bk[i - D_] : bv[i - 2 * D_];
    dst[i] = v;
}

// ---------------------------------------------------------------------------
// (bs, t, d) -> (B,T,D,P)
// ---------------------------------------------------------------------------
__global__ __launch_bounds__(1024) void transpose_out(const float* __restrict__ src,
                                                      float* __restrict__ dst) {
    __shared__ float tile[32][33];
    int bt = blockIdx.z, b = bt >> 5, t = bt & 31;
    int dblk = blockIdx.y * 32, pblk = blockIdx.x * 32;

    int d = dblk + threadIdx.x, p = pblk + threadIdx.y;
    tile[threadIdx.y][threadIdx.x] = src[(((size_t)(b * P_ + p)) * T_ + t) * D_ + d];
    __syncthreads();
    int p2 = pblk + threadIdx.x, d2 = dblk + threadIdx.y;
    dst[((size_t)bt * D_ + d2) * P_ + p2] = tile[threadIdx.x][threadIdx.y];
}

// ---------------------------------------------------------------------------
// u_pen
// ---------------------------------------------------------------------------
__global__ __launch_bounds__(256) void upen_kernel(const float* __restrict__ u,
                                                   const float* __restrict__ lam,
                                                   float* __restrict__ upen) {
    int bt = blockIdx.x, b = bt >> 5, t = bt & 31;
    int p = threadIdx.x;
    const float* up = u + (size_t)bt * D_ * P_ + p;
    float acc = 0.f;
#pragma unroll 8
    for (int d = 0; d < D_; d++) acc += up[(size_t)d * P_];
    upen[(b * P_ + p) * T_ + t] = lam[(size_t)bt * P_ + p] * acc * (1.0f / (float)D_);
}

// ---------------------------------------------------------------------------
// HMMA GEMM, templated on PARTS (A split terms sharing one B fragment):
//   PARTS=2:  C = (A_hi + A_lo) @ W^T + bias   (A row stride lda = 1536)
//   PARTS=1:  C = A @ W^T + bias               (A row stride lda = 768)
// 128x256 tile, BK=64, 3-stage cp.async, 16 warps x (32x64), SW128 smem.
// ---------------------------------------------------------------------------
template <int PARTS>
__global__ __launch_bounds__(512) void gemm_mma(const __half* __restrict__ A,
                                                const __half* __restrict__ Wt,
                                                const float* __restrict__ bias,
                                                float* __restrict__ C,
                                                int lda, int ldc) {
    constexpr int A_BYTES = PARTS * 16384;           // per-stage A bytes
    constexpr int STG = A_BYTES + 32768;             // stage bytes
    constexpr int B_OFFS = A_BYTES;
    constexpr int NCHUNK = STG / 16;                 // 16B chunks per stage
    constexpr int ITERS = NCHUNK / 512;

    extern __shared__ __align__(128) char dyn[];
    const uint32_t dynb = smem_u32(dyn);

    const int tid  = threadIdx.x;
    const int wid  = tid >> 5;
    const int lane = tid & 31;
    const int mblk = blockIdx.y * BM;
    const int nblk = blockIdx.x * BN;

    const int warp_m = (wid >> 2) * 32;   // 0,32,64,96
    const int warp_n = (wid & 3) * 64;    // 0,64,128,192

    const __half* Ab = A  + (size_t)mblk * lda;
    const __half* Bb = Wt + (size_t)nblk * D_;

    auto load_tile = [&](int stage, int kt) {
        uint32_t sb = dynb + stage * STG;
        const __half* Ak = Ab + kt * BK;
        const __half* Bk = Bb + kt * BK;
#pragma unroll
        for (int i = 0; i < ITERS; ++i) {
            int c = tid + 512 * i;
            if (c < PARTS * 1024) {                  // A parts: 128 rows x 8 each
                int part = c >> 10;                  // 0 or 1
                int c2 = c & 1023;
                int r = c2 >> 3, kc = c2 & 7;
                cp16(sb + part * 16384 + SW128(r * 128 + kc * 16),
                     Ak + part * D_ + (size_t)r * lda + kc * 8);
            } else {                                 // B: 256 rows x 8
                int c2 = c - PARTS * 1024;
                int r = c2 >> 3, kc = c2 & 7;
                cp16(sb + B_OFFS + SW128(r * 128 + kc * 16),
                     Bk + (size_t)r * D_ + kc * 8);
            }
        }
        CP_COMMIT();
    };

    const int a_row = warp_m + (lane & 15);
    const int a_kh  = lane >> 4;
    const int b_row = warp_n + (lane & 7) + ((lane >> 4) << 3);
    const int b_kh  = (lane >> 3) & 1;

    float acc[2][8][4];
#pragma unroll
    for (int mi = 0; mi < 2; mi++)
#pragma unroll
        for (int ni = 0; ni < 8; ni++)
#pragma unroll
            for (int e = 0; e < 4; e++) acc[mi][ni][e] = 0.f;

    load_tile(0, 0);
    load_tile(1, 1);

    for (int kt = 0; kt < NKT; ++kt) {
        const int cur = kt % 3;

        if (kt < NKT - 1) CP_WAIT(1); else CP_WAIT(0);
        __syncthreads();

        if (kt + 2 < NKT) load_tile((kt + 2) % 3, kt + 2);

        const uint32_t sb = dynb + cur * STG;
#pragma unroll
        for (int s = 0; s < 4; ++s) {             // four k16 steps per BK=64
            uint32_t bfr[4][4];
#pragma unroll
            for (int nj = 0; nj < 4; nj++)
                ldsm4(bfr[nj], sb + B_OFFS +
                      SW128((b_row + nj * 16) * 128 + (s * 2 + b_kh) * 16));
#pragma unroll
            for (int part = 0; part < PARTS; ++part) {
                uint32_t afr[2][4];
#pragma unroll
                for (int mi = 0; mi < 2; mi++)
                    ldsm4(afr[mi], sb + part * 16384 +
                          SW128((a_row + mi * 16) * 128 + (s * 2 + a_kh) * 16));
#pragma unroll
                for (int mi = 0; mi < 2; mi++) {
#pragma unroll
                    for (int ni = 0; ni < 8; ni++) {
                        uint32_t b0 = bfr[ni >> 1][(ni & 1) * 2 + 0];
                        uint32_t b1 = bfr[ni >> 1][(ni & 1) * 2 + 1];
                        mma16816(acc[mi][ni], afr[mi], b0, b1);
                    }
                }
            }
        }
    }

    // epilogue
    const int row0 = mblk + warp_m + (lane >> 2);
    const int col0 = nblk + warp_n + (lane & 3) * 2;
    float2 bb[8];
#pragma unroll
    for (int ni = 0; ni < 8; ni++) {
        int n = col0 + ni * 8;
        bb[ni].x = __ldg(&bias[n]);
        bb[ni].y = __ldg(&bias[n + 1]);
    }
#pragma unroll
    for (int mi = 0; mi < 2; mi++) {
        int r0 = row0 + mi * 16;
#pragma unroll
        for (int ni = 0; ni < 8; ni++) {
            int n = col0 + ni * 8;
            float2 v0 = make_float2(acc[mi][ni][0] + bb[ni].x, acc[mi][ni][1] + bb[ni].y);
            float2 v1 = make_float2(acc[mi][ni][2] + bb[ni].x, acc[mi][ni][3] + bb[ni].y);
            *reinterpret_cast<float2*>(C + (size_t)r0 * ldc + n)       = v0;
            *reinterpret_cast<float2*>(C + (size_t)(r0 + 8) * ldc + n) = v1;
        }
    }
}

// ---------------------------------------------------------------------------
// Fused attention per (bs, head): reads fused QKV (fp32, stride NQKV),
// writes single fp16 (feeds 1-part O GEMM).
// ---------------------------------------------------------------------------
__global__ __launch_bounds__(128) void attn_kernel(const float* __restrict__ QKV,
                                                   const float* __restrict__ upen,
                                                   __half* __restrict__ O) {
    int bs = blockIdx.x, h = blockIdx.y;
    __shared__ float Qs[32][64];
    __shared__ float Ks[32][64];
    __shared__ float Vs[32][64];
    __shared__ float Sc[32][33];

    int tid = threadIdx.x;
    const float* qb = QKV + (size_t)(bs * T_) * NQKV + h * HD_;
    const float* kb = qb + D_;
    const float* vb = qb + 2 * D_;

    for (int i = tid; i < 512; i += 128) {
        int r = i >> 4, c = (i & 15) * 4;
        *reinterpret_cast<float4*>(&Qs[r][c]) = *reinterpret_cast<const float4*>(&qb[(size_t)r * NQKV + c]);
        *reinterpret_cast<float4*>(&Ks[r][c]) = *reinterpret_cast<const float4*>(&kb[(size_t)r * NQKV + c]);
        *reinterpret_cast<float4*>(&Vs[r][c]) = *reinterpret_cast<const float4*>(&vb[(size_t)r * NQKV + c]);
    }
    __syncthreads();

    for (int i = tid; i < 1024; i += 128) {
        int q = i >> 5, k = i & 31;
        float s = 0.f;
#pragma unroll
        for (int d = 0; d < HD_; d++) s += Qs[q][d] * Ks[k][d];
        Sc[q][k] = s * 0.125f - upen[bs * T_ + k];
    }
    __syncthreads();

    if (tid < 32) {
        float mx = -1e30f;
#pragma unroll
        for (int k = 0; k < 32; k++) mx = fmaxf(mx, Sc[tid][k]);
        float sum = 0.f;
#pragma unroll
        for (int k = 0; k < 32; k++) { float e = __expf(Sc[tid][k] - mx); Sc[tid][k] = e; sum += e; }
        float inv = 1.f / sum;
#pragma unroll
        for (int k = 0; k < 32; k++) Sc[tid][k] *= inv;
    }
    __syncthreads();

    __half* ob = O + (size_t)(bs * T_) * D_ + h * HD_;
    for (int i = tid; i < 2048; i += 128) {
        int t = i >> 6, d = i & 63;
        float s = 0.f;
#pragma unroll
        for (int k = 0; k < 32; k++) s += Sc[t][k] * Vs[k][d];
        ob[(size_t)t * D_ + d] = __float2half(s);
    }
}

// ---------------------------------------------------------------------------
extern "C" void kernel_launch(void* const* d_in, const int* in_sizes, int n_in,
                              void* d_out, int out_size) {
    const float* h   = (const float*)d_in[0];
    const float* u   = (const float*)d_in[1];
    const float* lam = (const float*)d_in[2];
    const float* Wq  = (const float*)d_in[3];
    const float* bq  = (const float*)d_in[4];
    const float* Wk  = (const float*)d_in[5];
    const float* bk  = (const float*)d_in[6];
    const float* Wv  = (const float*)d_in[7];
    const float* bv  = (const float*)d_in[8];
    const float* Wo  = (const float*)d_in[9];
    const float* bo  = (const float*)d_in[10];
    float* out = (float*)d_out;

    __half *hsp, *aout, *wqkv, *wo;
    float *bqkv, *QKV, *oseq, *upen;
    cudaGetSymbolAddress((void**)&hsp,  g_hsplit);
    cudaGetSymbolAddress((void**)&aout, g_aout);
    cudaGetSymbolAddress((void**)&wqkv, g_wqkv);
    cudaGetSymbolAddress((void**)&wo,   g_wo);
    cudaGetSymbolAddress((void**)&bqkv, g_bqkv);
    cudaGetSymbolAddress((void**)&QKV,  g_QKV);
    cudaGetSymbolAddress((void**)&oseq, g_oseq);
    cudaGetSymbolAddress((void**)&upen, g_upen);

    cudaFuncSetAttribute(gemm_mma<2>, cudaFuncAttributeMaxDynamicSharedMemorySize,
                         3 * (2 * 16384 + 32768));
    cudaFuncSetAttribute(gemm_mma<1>, cudaFuncAttributeMaxDynamicSharedMemorySize,
                         3 * (1 * 16384 + 32768));

    dim3 tgrid(8, 24, 128), tblk(32, 32);
    transpose_in_split<<<tgrid, tblk>>>(h, hsp);
    upen_kernel<<<128, 256>>>(u, lam, upen);
    wconv<<<(D_ * D_) / 256, 256>>>(Wq, wqkv);
    wconv<<<(D_ * D_) / 256, 256>>>(Wk, wqkv + (size_t)D_ * D_);
    wconv<<<(D_ * D_) / 256, 256>>>(Wv, wqkv + (size_t)2 * D_ * D_);
    wconv<<<(D_ * D_) / 256, 256>>>(Wo, wo);
    pack_bias<<<(NQKV + 255) / 256, 256>>>(bq, bk, bv, bqkv);

    // fused QKV projection: C[M, 2304], A = [hi|lo] split
    dim3 qgrid(NQKV / BN, M_ / BM);        // (9, 256)
    gemm_mma<2><<<qgrid, 512, 3 * (2 * 16384 + 32768)>>>(hsp, wqkv, bqkv, QKV, K2_, NQKV);

    dim3 agrid(BS_, NH_);
    attn_kernel<<<agrid, 128>>>(QKV, upen, aout);

    // O projection: C[M, 768], A single fp16
    dim3 ogrid(D_ / BN, M_ / BM);          // (3, 256)
    gemm_mma<1><<<ogrid, 512, 3 * (1 * 16384 + 32768)>>>(aout, wo, bo, oseq, D_, D_);

    transpose_out<<<tgrid, tblk>>>(oseq, out);
}

// round 9
// speedup vs baseline: 4.5909x; 1.2170x over previous
#include <cuda_runtime.h>
#include <cuda_fp16.h>
#include <cstdint>

// Problem constants
#define B_   4
#define T_   32
#define D_   768
#define P_   256
#define BS_  1024
#define M_   32768
#define NH_  12
#define HD_  64
#define NQKV 2304          // fused Q|K|V output width

// GEMM tiling: 128x256, BK=64, 16 warps (4x4), warp tile 32x64
#define BM   128
#define BN   256
#define BK   64
#define NKT  (D_ / BK)     // 12
#define STG_BYTES 49152    // A 16K + B 32K
#define B_OFFS 16384

#define SW128(b) ((b) ^ (((b) >> 3) & 0x70))

// ---------------- scratch (device globals; no cudaMalloc allowed) ----------
__device__ __half g_hh  [(size_t)M_ * D_];       // h_seq fp16
__device__ __half g_aout[(size_t)M_ * D_];       // attention out fp16
__device__ __half g_wqkv[(size_t)NQKV * D_];     // fused Wq|Wk|Wv fp16
__device__ __half g_wo  [(size_t)D_ * D_];
__device__ float  g_bqkv[NQKV];
__device__ __half g_QKV [(size_t)M_ * NQKV];     // fused Q|K|V fp16
__device__ float  g_oseq[(size_t)M_ * D_];
__device__ float  g_upen[M_];

// ---------------- PTX helpers (base-PTX, sm_80-era) ------------------------
__device__ __forceinline__ uint32_t smem_u32(const void* p) {
    uint32_t a;
    asm("{ .reg .u64 t; cvta.to.shared.u64 t, %1; cvt.u32.u64 %0, t; }"
        : "=r"(a) : "l"(p));
    return a;
}

__device__ __forceinline__ void cp16(uint32_t dst, const void* src) {
    asm volatile("cp.async.cg.shared.global [%0], [%1], 16;" :: "r"(dst), "l"(src));
}
#define CP_COMMIT() asm volatile("cp.async.commit_group;" ::: "memory")
#define CP_WAIT(n)  asm volatile("cp.async.wait_group %0;" :: "n"(n) : "memory")

__device__ __forceinline__ void ldsm4(uint32_t (&r)[4], uint32_t addr) {
    asm volatile("ldmatrix.sync.aligned.m8n8.x4.shared.b16 {%0,%1,%2,%3}, [%4];"
                 : "=r"(r[0]), "=r"(r[1]), "=r"(r[2]), "=r"(r[3]) : "r"(addr));
}

__device__ __forceinline__ void mma16816(float (&d)[4], const uint32_t (&a)[4],
                                         uint32_t b0, uint32_t b1) {
    asm volatile(
        "mma.sync.aligned.m16n8k16.row.col.f32.f16.f16.f32 "
        "{%0,%1,%2,%3}, {%4,%5,%6,%7}, {%8,%9}, {%0,%1,%2,%3};"
        : "+f"(d[0]), "+f"(d[1]), "+f"(d[2]), "+f"(d[3])
        : "r"(a[0]), "r"(a[1]), "r"(a[2]), "r"(a[3]), "r"(b0), "r"(b1));
}

// output store helpers (fp32 or fp16 C)
__device__ __forceinline__ void store2(float* p, float x, float y) {
    *reinterpret_cast<float2*>(p) = make_float2(x, y);
}
__device__ __forceinline__ void store2(__half* p, float x, float y) {
    *reinterpret_cast<__half2*>(p) = __floats2half2_rn(x, y);
}

// ---------------------------------------------------------------------------
// transpose to (bs, t, d) + fp16 convert
// ---------------------------------------------------------------------------
__global__ __launch_bounds__(1024) void transpose_in_h(const float* __restrict__ src,
                                                       __half* __restrict__ dst) {
    __shared__ float tile[32][33];
    int bt = blockIdx.z, b = bt >> 5, t = bt & 31;
    int dblk = blockIdx.y * 32, pblk = blockIdx.x * 32;

    int d = dblk + threadIdx.y, p = pblk + threadIdx.x;
    tile[threadIdx.y][threadIdx.x] = src[((size_t)bt * D_ + d) * P_ + p];
    __syncthreads();
    int d2 = dblk + threadIdx.x, p2 = pblk + threadIdx.y;
    dst[(((size_t)(b * P_ + p2)) * T_ + t) * D_ + d2] =
        __float2half(tile[threadIdx.x][threadIdx.y]);
}

// ---------------------------------------------------------------------------
// weight convert: fp32 -> fp16
// ---------------------------------------------------------------------------
__global__ __launch_bounds__(256) void wconv(const float* __restrict__ W,
                                             __half* __restrict__ Ws) {
    int i = blockIdx.x * 256 + threadIdx.x;
    Ws[i] = __float2half(W[i]);
}

__global__ __launch_bounds__(256) void pack_bias(const float* __restrict__ bq,
                                                 const float* __restrict__ bk,
                                                 const float* __restrict__ bv,
                                                 float* __restrict__ dst) {
    int i = blockIdx.x * 256 + threadIdx.x;
    if (i >= NQKV) return;
    float v = (i < D_) ? bq[i] : (i < 2 * D_) ? bk[i - D_] : bv[i - 2 * D_];
    dst[i] = v;
}

// ---------------------------------------------------------------------------
// (bs, t, d) -> (B,T,D,P)
// ---------------------------------------------------------------------------
__global__ __launch_bounds__(1024) void transpose_out(const float* __restrict__ src,
                                                      float* __restrict__ dst) {
    __shared__ float tile[32][33];
    int bt = blockIdx.z, b = bt >> 5, t = bt & 31;
    int dblk = blockIdx.y * 32, pblk = blockIdx.x * 32;

    int d = dblk + threadIdx.x, p = pblk + threadIdx.y;
    tile[threadIdx.y][threadIdx.x] = src[(((size_t)(b * P_ + p)) * T_ + t) * D_ + d];
    __syncthreads();
    int p2 = pblk + threadIdx.x, d2 = dblk + threadIdx.y;
    dst[((size_t)bt * D_ + d2) * P_ + p2] = tile[threadIdx.x][threadIdx.y];
}

// ---------------------------------------------------------------------------
// u_pen
// ---------------------------------------------------------------------------
__global__ __launch_bounds__(256) void upen_kernel(const float* __restrict__ u,
                                                   const float* __restrict__ lam,
                                                   float* __restrict__ upen) {
    int bt = blockIdx.x, b = bt >> 5, t = bt & 31;
    int p = threadIdx.x;
    const float* up = u + (size_t)bt * D_ * P_ + p;
    float acc = 0.f;
#pragma unroll 8
    for (int d = 0; d < D_; d++) acc += up[(size_t)d * P_];
    upen[(b * P_ + p) * T_ + t] = lam[(size_t)bt * P_ + p] * acc * (1.0f / (float)D_);
}

// ---------------------------------------------------------------------------
// HMMA GEMM:  C[M, ldc-tile] = A[M,768] @ W[ldc,768]^T + bias
// 128x256 tile, BK=64, 3-stage cp.async, 16 warps x (32x64), SW128 smem.
// TO = float (O proj) or __half (QKV proj).
// ---------------------------------------------------------------------------
template <typename TO>
__global__ __launch_bounds__(512) void gemm_mma(const __half* __restrict__ A,
                                                const __half* __restrict__ Wt,
                                                const float* __restrict__ bias,
                                                TO* __restrict__ C,
                                                int ldc) {
    extern __shared__ __align__(128) char dyn[];
    const uint32_t dynb = smem_u32(dyn);

    const int tid  = threadIdx.x;
    const int wid  = tid >> 5;
    const int lane = tid & 31;
    const int mblk = blockIdx.y * BM;
    const int nblk = blockIdx.x * BN;

    const int warp_m = (wid >> 2) * 32;   // 0,32,64,96
    const int warp_n = (wid & 3) * 64;    // 0,64,128,192

    const __half* Ab = A  + (size_t)mblk * D_;
    const __half* Bb = Wt + (size_t)nblk * D_;

    // 3072 x 16B chunks per stage / 512 threads = 6 per thread
    auto load_tile = [&](int stage, int kt) {
        uint32_t sb = dynb + stage * STG_BYTES;
        const __half* Ak = Ab + kt * BK;
        const __half* Bk = Bb + kt * BK;
#pragma unroll
        for (int i = 0; i < 6; ++i) {
            int c = tid + 512 * i;
            if (c < 1024) {                           // A: 128 rows x 8
                int r = c >> 3, kc = c & 7;
                cp16(sb + SW128(r * 128 + kc * 16),
                     Ak + (size_t)r * D_ + kc * 8);
            } else {                                  // B: 256 rows x 8
                int c2 = c - 1024;
                int r = c2 >> 3, kc = c2 & 7;
                cp16(sb + B_OFFS + SW128(r * 128 + kc * 16),
                     Bk + (size_t)r * D_ + kc * 8);
            }
        }
        CP_COMMIT();
    };

    const int a_row = warp_m + (lane & 15);
    const int a_kh  = lane >> 4;
    const int b_row = warp_n + (lane & 7) + ((lane >> 4) << 3);
    const int b_kh  = (lane >> 3) & 1;

    float acc[2][8][4];
#pragma unroll
    for (int mi = 0; mi < 2; mi++)
#pragma unroll
        for (int ni = 0; ni < 8; ni++)
#pragma unroll
            for (int e = 0; e < 4; e++) acc[mi][ni][e] = 0.f;

    load_tile(0, 0);
    load_tile(1, 1);

    for (int kt = 0; kt < NKT; ++kt) {
        const int cur = kt % 3;

        if (kt < NKT - 1) CP_WAIT(1); else CP_WAIT(0);
        __syncthreads();

        if (kt + 2 < NKT) load_tile((kt + 2) % 3, kt + 2);

        const uint32_t sb = dynb + cur * STG_BYTES;
#pragma unroll
        for (int s = 0; s < 4; ++s) {             // four k16 steps per BK=64
            uint32_t bfr[4][4];
#pragma unroll
            for (int nj = 0; nj < 4; nj++)
                ldsm4(bfr[nj], sb + B_OFFS +
                      SW128((b_row + nj * 16) * 128 + (s * 2 + b_kh) * 16));
            uint32_t afr[2][4];
#pragma unroll
            for (int mi = 0; mi < 2; mi++)
                ldsm4(afr[mi], sb +
                      SW128((a_row + mi * 16) * 128 + (s * 2 + a_kh) * 16));
#pragma unroll
            for (int mi = 0; mi < 2; mi++) {
#pragma unroll
                for (int ni = 0; ni < 8; ni++) {
                    uint32_t b0 = bfr[ni >> 1][(ni & 1) * 2 + 0];
                    uint32_t b1 = bfr[ni >> 1][(ni & 1) * 2 + 1];
                    mma16816(acc[mi][ni], afr[mi], b0, b1);
                }
            }
        }
    }

    // epilogue
    const int row0 = mblk + warp_m + (lane >> 2);
    const int col0 = nblk + warp_n + (lane & 3) * 2;
    float2 bb[8];
#pragma unroll
    for (int ni = 0; ni < 8; ni++) {
        int n = col0 + ni * 8;
        bb[ni].x = __ldg(&bias[n]);
        bb[ni].y = __ldg(&bias[n + 1]);
    }
#pragma unroll
    for (int mi = 0; mi < 2; mi++) {
        int r0 = row0 + mi * 16;
#pragma unroll
        for (int ni = 0; ni < 8; ni++) {
            int n = col0 + ni * 8;
            store2(C + (size_t)r0 * ldc + n,
                   acc[mi][ni][0] + bb[ni].x, acc[mi][ni][1] + bb[ni].y);
            store2(C + (size_t)(r0 + 8) * ldc + n,
                   acc[mi][ni][2] + bb[ni].x, acc[mi][ni][3] + bb[ni].y);
        }
    }
}

// ---------------------------------------------------------------------------
// Fused attention per (bs, head): reads fused QKV (fp16, stride NQKV),
// fp32 compute, writes fp16.
// ---------------------------------------------------------------------------
__global__ __launch_bounds__(128) void attn_kernel(const __half* __restrict__ QKV,
                                                   const float* __restrict__ upen,
                                                   __half* __restrict__ O) {
    int bs = blockIdx.x, h = blockIdx.y;
    __shared__ float Qs[32][64];
    __shared__ float Ks[32][64];
    __shared__ float Vs[32][64];
    __shared__ float Sc[32][33];

    int tid = threadIdx.x;
    const __half* base = QKV + (size_t)(bs * T_) * NQKV + h * HD_;

    // 3 tensors x 32 rows x 8 chunks(8 halfs) = 768 chunks; 6 per thread
    for (int i = tid; i < 768; i += 128) {
        int t3 = i >> 8;               // 0=Q,1=K,2=V
        int idx = i & 255;
        int r = idx >> 3, c = (idx & 7) * 8;
        const __half* src = base + t3 * D_ + (size_t)r * NQKV + c;
        uint4 raw = *reinterpret_cast<const uint4*>(src);
        const __half2* hp = reinterpret_cast<const __half2*>(&raw);
        float* dst = (t3 == 0 ? &Qs[r][c] : t3 == 1 ? &Ks[r][c] : &Vs[r][c]);
#pragma unroll
        for (int j = 0; j < 4; j++) {
            float2 f = __half22float2(hp[j]);
            dst[j * 2]     = f.x;
            dst[j * 2 + 1] = f.y;
        }
    }
    __syncthreads();

    for (int i = tid; i < 1024; i += 128) {
        int q = i >> 5, k = i & 31;
        float s = 0.f;
#pragma unroll
        for (int d = 0; d < HD_; d++) s += Qs[q][d] * Ks[k][d];
        Sc[q][k] = s * 0.125f - upen[bs * T_ + k];
    }
    __syncthreads();

    if (tid < 32) {
        float mx = -1e30f;
#pragma unroll
        for (int k = 0; k < 32; k++) mx = fmaxf(mx, Sc[tid][k]);
        float sum = 0.f;
#pragma unroll
        for (int k = 0; k < 32; k++) { float e = __expf(Sc[tid][k] - mx); Sc[tid][k] = e; sum += e; }
        float inv = 1.f / sum;
#pragma unroll
        for (int k = 0; k < 32; k++) Sc[tid][k] *= inv;
    }
    __syncthreads();

    __half* ob = O + (size_t)(bs * T_) * D_ + h * HD_;
    for (int i = tid; i < 2048; i += 128) {
        int t = i >> 6, d = i & 63;
        float s = 0.f;
#pragma unroll
        for (int k = 0; k < 32; k++) s += Sc[t][k] * Vs[k][d];
        ob[(size_t)t * D_ + d] = __float2half(s);
    }
}

// ---------------------------------------------------------------------------
extern "C" void kernel_launch(void* const* d_in, const int* in_sizes, int n_in,
                              void* d_out, int out_size) {
    const float* h   = (const float*)d_in[0];
    const float* u   = (const float*)d_in[1];
    const float* lam = (const float*)d_in[2];
    const float* Wq  = (const float*)d_in[3];
    const float* bq  = (const float*)d_in[4];
    const float* Wk  = (const float*)d_in[5];
    const float* bk  = (const float*)d_in[6];
    const float* Wv  = (const float*)d_in[7];
    const float* bv  = (const float*)d_in[8];
    const float* Wo  = (const float*)d_in[9];
    const float* bo  = (const float*)d_in[10];
    float* out = (float*)d_out;

    __half *hh, *aout, *wqkv, *wo, *QKVh;
    float *bqkv, *oseq, *upen;
    cudaGetSymbolAddress((void**)&hh,   g_hh);
    cudaGetSymbolAddress((void**)&aout, g_aout);
    cudaGetSymbolAddress((void**)&wqkv, g_wqkv);
    cudaGetSymbolAddress((void**)&wo,   g_wo);
    cudaGetSymbolAddress((void**)&bqkv, g_bqkv);
    cudaGetSymbolAddress((void**)&QKVh, g_QKV);
    cudaGetSymbolAddress((void**)&oseq, g_oseq);
    cudaGetSymbolAddress((void**)&upen, g_upen);

    cudaFuncSetAttribute(gemm_mma<__half>, cudaFuncAttributeMaxDynamicSharedMemorySize,
                         3 * STG_BYTES);
    cudaFuncSetAttribute(gemm_mma<float>, cudaFuncAttributeMaxDynamicSharedMemorySize,
                         3 * STG_BYTES);

    dim3 tgrid(8, 24, 128), tblk(32, 32);
    transpose_in_h<<<tgrid, tblk>>>(h, hh);
    upen_kernel<<<128, 256>>>(u, lam, upen);
    wconv<<<(D_ * D_) / 256, 256>>>(Wq, wqkv);
    wconv<<<(D_ * D_) / 256, 256>>>(Wk, wqkv + (size_t)D_ * D_);
    wconv<<<(D_ * D_) / 256, 256>>>(Wv, wqkv + (size_t)2 * D_ * D_);
    wconv<<<(D_ * D_) / 256, 256>>>(Wo, wo);
    pack_bias<<<(NQKV + 255) / 256, 256>>>(bq, bk, bv, bqkv);

    // fused QKV projection: C[M, 2304] fp16
    dim3 qgrid(NQKV / BN, M_ / BM);        // (9, 256)
    gemm_mma<__half><<<qgrid, 512, 3 * STG_BYTES>>>(hh, wqkv, bqkv, QKVh, NQKV);

    dim3 agrid(BS_, NH_);
    attn_kernel<<<agrid, 128>>>(QKVh, upen, aout);

    // O projection: C[M, 768] fp32
    dim3 ogrid(D_ / BN, M_ / BM);          // (3, 256)
    gemm_mma<float><<<ogrid, 512, 3 * STG_BYTES>>>(aout, wo, bo, oseq, D_);

    transpose_out<<<tgrid, tblk>>>(oseq, out);
}

// round 11
// speedup vs baseline: 5.7033x; 1.2423x over previous
#include <cuda_runtime.h>
#include <cuda_fp16.h>
#include <cstdint>

// Problem constants
#define B_   4
#define T_   32
#define D_   768
#define P_   256
#define BS_  1024
#define M_   32768
#define NH_  12
#define HD_  64
#define NQKV 2304          // fused Q|K|V output width

// GEMM tiling: 128x256, BK=64, 16 warps (4x4), warp tile 32x64
#define BM   128
#define BN   256
#define BK   64
#define NKT  (D_ / BK)     // 12
#define STG_BYTES 49152    // A 16K + B 32K
#define B_OFFS 16384

#define SW128(b) ((b) ^ (((b) >> 3) & 0x70))

// Attention smem layout (per warp): Q 32x72h, K 32x72h, Vt 64x40h
#define QK_STRIDE_B 144    // 72 halves
#define VT_STRIDE_B 80     // 40 halves
#define AQ_OFF 0
#define AK_OFF 4608
#define AVT_OFF 9216
#define AWARP_BYTES 14336
#define AUPEN_OFF (4 * AWARP_BYTES)
#define ATTN_SMEM (AUPEN_OFF + 128)

// ---------------- scratch (device globals; no cudaMalloc allowed) ----------
__device__ __half g_hh  [(size_t)M_ * D_];       // h_seq fp16
__device__ __half g_aout[(size_t)M_ * D_];       // attention out fp16
__device__ __half g_wqkv[(size_t)NQKV * D_];     // fused Wq|Wk|Wv fp16
__device__ __half g_wo  [(size_t)D_ * D_];
__device__ float  g_bqkv[NQKV];
__device__ __half g_QKV [(size_t)M_ * NQKV];     // fused Q|K|V fp16
__device__ float  g_oseq[(size_t)M_ * D_];
__device__ float  g_upen[M_];

// ---------------- PTX helpers (base-PTX, sm_80-era) ------------------------
__device__ __forceinline__ uint32_t smem_u32(const void* p) {
    uint32_t a;
    asm("{ .reg .u64 t; cvta.to.shared.u64 t, %1; cvt.u32.u64 %0, t; }"
        : "=r"(a) : "l"(p));
    return a;
}

__device__ __forceinline__ void cp16(uint32_t dst, const void* src) {
    asm volatile("cp.async.cg.shared.global [%0], [%1], 16;" :: "r"(dst), "l"(src));
}
#define CP_COMMIT() asm volatile("cp.async.commit_group;" ::: "memory")
#define CP_WAIT(n)  asm volatile("cp.async.wait_group %0;" :: "n"(n) : "memory")

__device__ __forceinline__ void ldsm4(uint32_t (&r)[4], uint32_t addr) {
    asm volatile("ldmatrix.sync.aligned.m8n8.x4.shared.b16 {%0,%1,%2,%3}, [%4];"
                 : "=r"(r[0]), "=r"(r[1]), "=r"(r[2]), "=r"(r[3]) : "r"(addr));
}

__device__ __forceinline__ void mma16816(float (&d)[4], const uint32_t (&a)[4],
                                         uint32_t b0, uint32_t b1) {
    asm volatile(
        "mma.sync.aligned.m16n8k16.row.col.f32.f16.f16.f32 "
        "{%0,%1,%2,%3}, {%4,%5,%6,%7}, {%8,%9}, {%0,%1,%2,%3};"
        : "+f"(d[0]), "+f"(d[1]), "+f"(d[2]), "+f"(d[3])
        : "r"(a[0]), "r"(a[1]), "r"(a[2]), "r"(a[3]), "r"(b0), "r"(b1));
}

__device__ __forceinline__ uint32_t packh2(float x, float y) {
    __half2 h = __floats2half2_rn(x, y);
    return *reinterpret_cast<uint32_t*>(&h);
}

// output store helpers (fp32 or fp16 C)
__device__ __forceinline__ void store2(float* p, float x, float y) {
    *reinterpret_cast<float2*>(p) = make_float2(x, y);
}
__device__ __forceinline__ void store2(__half* p, float x, float y) {
    *reinterpret_cast<__half2*>(p) = __floats2half2_rn(x, y);
}

// ---------------------------------------------------------------------------
// transpose to (bs, t, d) + fp16 convert
// ---------------------------------------------------------------------------
__global__ __launch_bounds__(1024) void transpose_in_h(const float* __restrict__ src,
                                                       __half* __restrict__ dst) {
    __shared__ float tile[32][33];
    int bt = blockIdx.z, b = bt >> 5, t = bt & 31;
    int dblk = blockIdx.y * 32, pblk = blockIdx.x * 32;

    int d = dblk + threadIdx.y, p = pblk + threadIdx.x;
    tile[threadIdx.y][threadIdx.x] = src[((size_t)bt * D_ + d) * P_ + p];
    __syncthreads();
    int d2 = dblk + threadIdx.x, p2 = pblk + threadIdx.y;
    dst[(((size_t)(b * P_ + p2)) * T_ + t) * D_ + d2] =
        __float2half(tile[threadIdx.x][threadIdx.y]);
}

// ---------------------------------------------------------------------------
// weight convert: fp32 -> fp16
// ---------------------------------------------------------------------------
__global__ __launch_bounds__(256) void wconv(const float* __restrict__ W,
                                             __half* __restrict__ Ws) {
    int i = blockIdx.x * 256 + threadIdx.x;
    Ws[i] = __float2half(W[i]);
}

__global__ __launch_bounds__(256) void pack_bias(const float* __restrict__ bq,
                                                 const float* __restrict__ bk,
                                                 const float* __restrict__ bv,
                                                 float* __restrict__ dst) {
    int i = blockIdx.x * 256 + threadIdx.x;
    if (i >= NQKV) return;
    float v = (i < D_) ? bq[i] : (i < 2 * D_) ? bk[i - D_] : bv[i - 2 * D_];
    dst[i] = v;
}

// ---------------------------------------------------------------------------
// (bs, t, d) -> (B,T,D,P)
// ---------------------------------------------------------------------------
__global__ __launch_bounds__(1024) void transpose_out(const float* __restrict__ src,
                                                      float* __restrict__ dst) {
    __shared__ float tile[32][33];
    int bt = blockIdx.z, b = bt >> 5, t = bt & 31;
    int dblk = blockIdx.y * 32, pblk = blockIdx.x * 32;

    int d = dblk + threadIdx.x, p = pblk + threadIdx.y;
    tile[threadIdx.y][threadIdx.x] = src[(((size_t)(b * P_ + p)) * T_ + t) * D_ + d];
    __syncthreads();
    int p2 = pblk + threadIdx.x, d2 = dblk + threadIdx.y;
    dst[((size_t)bt * D_ + d2) * P_ + p2] = tile[threadIdx.x][threadIdx.y];
}

// ---------------------------------------------------------------------------
// u_pen
// ---------------------------------------------------------------------------
__global__ __launch_bounds__(256) void upen_kernel(const float* __restrict__ u,
                                                   const float* __restrict__ lam,
                                                   float* __restrict__ upen) {
    int bt = blockIdx.x, b = bt >> 5, t = bt & 31;
    int p = threadIdx.x;
    const float* up = u + (size_t)bt * D_ * P_ + p;
    float acc = 0.f;
#pragma unroll 8
    for (int d = 0; d < D_; d++) acc += up[(size_t)d * P_];
    upen[(b * P_ + p) * T_ + t] = lam[(size_t)bt * P_ + p] * acc * (1.0f / (float)D_);
}

// ---------------------------------------------------------------------------
// HMMA GEMM:  C[M, ldc-tile] = A[M,768] @ W[ldc,768]^T + bias
// 128x256 tile, BK=64, 3-stage cp.async, 16 warps x (32x64), SW128 smem.
// ---------------------------------------------------------------------------
template <typename TO>
__global__ __launch_bounds__(512) void gemm_mma(const __half* __restrict__ A,
                                                const __half* __restrict__ Wt,
                                                const float* __restrict__ bias,
                                                TO* __restrict__ C,
                                                int ldc) {
    extern __shared__ __align__(128) char dyn[];
    const uint32_t dynb = smem_u32(dyn);

    const int tid  = threadIdx.x;
    const int wid  = tid >> 5;
    const int lane = tid & 31;
    const int mblk = blockIdx.y * BM;
    const int nblk = blockIdx.x * BN;

    const int warp_m = (wid >> 2) * 32;
    const int warp_n = (wid & 3) * 64;

    const __half* Ab = A  + (size_t)mblk * D_;
    const __half* Bb = Wt + (size_t)nblk * D_;

    auto load_tile = [&](int stage, int kt) {
        uint32_t sb = dynb + stage * STG_BYTES;
        const __half* Ak = Ab + kt * BK;
        const __half* Bk = Bb + kt * BK;
#pragma unroll
        for (int i = 0; i < 6; ++i) {
            int c = tid + 512 * i;
            if (c < 1024) {
                int r = c >> 3, kc = c & 7;
                cp16(sb + SW128(r * 128 + kc * 16),
                     Ak + (size_t)r * D_ + kc * 8);
            } else {
                int c2 = c - 1024;
                int r = c2 >> 3, kc = c2 & 7;
                cp16(sb + B_OFFS + SW128(r * 128 + kc * 16),
                     Bk + (size_t)r * D_ + kc * 8);
            }
        }
        CP_COMMIT();
    };

    const int a_row = warp_m + (lane & 15);
    const int a_kh  = lane >> 4;
    const int b_row = warp_n + (lane & 7) + ((lane >> 4) << 3);
    const int b_kh  = (lane >> 3) & 1;

    float acc[2][8][4];
#pragma unroll
    for (int mi = 0; mi < 2; mi++)
#pragma unroll
        for (int ni = 0; ni < 8; ni++)
#pragma unroll
            for (int e = 0; e < 4; e++) acc[mi][ni][e] = 0.f;

    load_tile(0, 0);
    load_tile(1, 1);

    for (int kt = 0; kt < NKT; ++kt) {
        const int cur = kt % 3;

        if (kt < NKT - 1) CP_WAIT(1); else CP_WAIT(0);
        __syncthreads();

        if (kt + 2 < NKT) load_tile((kt + 2) % 3, kt + 2);

        const uint32_t sb = dynb + cur * STG_BYTES;
#pragma unroll
        for (int s = 0; s < 4; ++s) {
            uint32_t bfr[4][4];
#pragma unroll
            for (int nj = 0; nj < 4; nj++)
                ldsm4(bfr[nj], sb + B_OFFS +
                      SW128((b_row + nj * 16) * 128 + (s * 2 + b_kh) * 16));
            uint32_t afr[2][4];
#pragma unroll
            for (int mi = 0; mi < 2; mi++)
                ldsm4(afr[mi], sb +
                      SW128((a_row + mi * 16) * 128 + (s * 2 + a_kh) * 16));
#pragma unroll
            for (int mi = 0; mi < 2; mi++) {
#pragma unroll
                for (int ni = 0; ni < 8; ni++) {
                    uint32_t b0 = bfr[ni >> 1][(ni & 1) * 2 + 0];
                    uint32_t b1 = bfr[ni >> 1][(ni & 1) * 2 + 1];
                    mma16816(acc[mi][ni], afr[mi], b0, b1);
                }
            }
        }
    }

    const int row0 = mblk + warp_m + (lane >> 2);
    const int col0 = nblk + warp_n + (lane & 3) * 2;
    float2 bb[8];
#pragma unroll
    for (int ni = 0; ni < 8; ni++) {
        int n = col0 + ni * 8;
        bb[ni].x = __ldg(&bias[n]);
        bb[ni].y = __ldg(&bias[n + 1]);
    }
#pragma unroll
    for (int mi = 0; mi < 2; mi++) {
        int r0 = row0 + mi * 16;
#pragma unroll
        for (int ni = 0; ni < 8; ni++) {
            int n = col0 + ni * 8;
            store2(C + (size_t)r0 * ldc + n,
                   acc[mi][ni][0] + bb[ni].x, acc[mi][ni][1] + bb[ni].y);
            store2(C + (size_t)(r0 + 8) * ldc + n,
                   acc[mi][ni][2] + bb[ni].x, acc[mi][ni][3] + bb[ni].y);
        }
    }
}

// ---------------------------------------------------------------------------
// HMMA attention: 1 warp per (bs, head). Block = 4 warps; grid (BS, 3).
// S = Q K^T (HMMA) -> register softmax -> O = P V (HMMA, V transposed in smem)
// ---------------------------------------------------------------------------
__global__ __launch_bounds__(128) void attn_mma(const __half* __restrict__ QKV,
                                                const float* __restrict__ upen,
                                                __half* __restrict__ O) {
    extern __shared__ __align__(128) char asm_[];
    const int bs   = blockIdx.x;
    const int wid  = threadIdx.x >> 5;
    const int lane = threadIdx.x & 31;
    const int head = blockIdx.y * 4 + wid;

    char* wb = asm_ + wid * AWARP_BYTES;
    const uint32_t wbase = smem_u32(asm_) + wid * AWARP_BYTES;
    float* us = reinterpret_cast<float*>(asm_ + AUPEN_OFF);

    if (threadIdx.x < 32) us[threadIdx.x] = upen[bs * T_ + threadIdx.x];

    // ---- stage Q, K (32x64h, stride 72h) and Vt (64x32h transposed, stride 40h)
    const __half* hb = QKV + (size_t)(bs * T_) * NQKV + head * HD_;
#pragma unroll
    for (int i = 0; i < 8; ++i) {
        int id = lane + 32 * i;
        int r = id >> 3, c = id & 7;                  // row, 16B chunk
        const __half* qsrc = hb + (size_t)r * NQKV + c * 8;
        *reinterpret_cast<uint4*>(wb + AQ_OFF + r * QK_STRIDE_B + c * 16) =
            *reinterpret_cast<const uint4*>(qsrc);
        *reinterpret_cast<uint4*>(wb + AK_OFF + r * QK_STRIDE_B + c * 16) =
            *reinterpret_cast<const uint4*>(qsrc + D_);
        uint4 vv = *reinterpret_cast<const uint4*>(qsrc + 2 * D_);
        const __half* vh = reinterpret_cast<const __half*>(&vv);
#pragma unroll
        for (int j = 0; j < 8; ++j)                    // Vt[d][t] = V[t][d]
            *reinterpret_cast<__half*>(wb + AVT_OFF + (c * 8 + j) * VT_STRIDE_B + r * 2) = vh[j];
    }
    __syncthreads();

    const int a_kh  = lane >> 4;
    const int b_row = (lane & 7) + ((lane >> 4) << 3);
    const int b_kh  = (lane >> 3) & 1;
    const int col0  = (lane & 3) * 2;

    // ---- S = Q K^T  (M=32, N=32, K=64)
    float S[2][4][4];
#pragma unroll
    for (int mi = 0; mi < 2; mi++)
#pragma unroll
        for (int ni = 0; ni < 4; ni++)
#pragma unroll
            for (int e = 0; e < 4; e++) S[mi][ni][e] = 0.f;

#pragma unroll
    for (int s = 0; s < 4; ++s) {
        uint32_t bfr[2][4];
#pragma unroll
        for (int nj = 0; nj < 2; nj++)
            ldsm4(bfr[nj], wbase + AK_OFF +
                  (b_row + nj * 16) * QK_STRIDE_B + (s * 2 + b_kh) * 16);
        uint32_t afr[2][4];
#pragma unroll
        for (int mi = 0; mi < 2; mi++)
            ldsm4(afr[mi], wbase + AQ_OFF +
                  ((lane & 15) + mi * 16) * QK_STRIDE_B + (s * 2 + a_kh) * 16);
#pragma unroll
        for (int mi = 0; mi < 2; mi++)
#pragma unroll
            for (int ni = 0; ni < 4; ni++)
                mma16816(S[mi][ni], afr[mi],
                         bfr[ni >> 1][(ni & 1) * 2], bfr[ni >> 1][(ni & 1) * 2 + 1]);
    }

    // ---- scale + upen + softmax (rows rA = lane>>2 + 16mi, rB = rA + 8)
    float uv[4][2];
#pragma unroll
    for (int ni = 0; ni < 4; ni++) {
        uv[ni][0] = us[8 * ni + col0];
        uv[ni][1] = us[8 * ni + col0 + 1];
    }
    float mA[2] = {-1e30f, -1e30f}, mB[2] = {-1e30f, -1e30f};
#pragma unroll
    for (int mi = 0; mi < 2; mi++)
#pragma unroll
        for (int ni = 0; ni < 4; ni++) {
            S[mi][ni][0] = S[mi][ni][0] * 0.125f - uv[ni][0];
            S[mi][ni][1] = S[mi][ni][1] * 0.125f - uv[ni][1];
            S[mi][ni][2] = S[mi][ni][2] * 0.125f - uv[ni][0];
            S[mi][ni][3] = S[mi][ni][3] * 0.125f - uv[ni][1];
            mA[mi] = fmaxf(mA[mi], fmaxf(S[mi][ni][0], S[mi][ni][1]));
            mB[mi] = fmaxf(mB[mi], fmaxf(S[mi][ni][2], S[mi][ni][3]));
        }
#pragma unroll
    for (int off = 1; off <= 2; off <<= 1) {
#pragma unroll
        for (int mi = 0; mi < 2; mi++) {
            mA[mi] = fmaxf(mA[mi], __shfl_xor_sync(0xffffffffu, mA[mi], off));
            mB[mi] = fmaxf(mB[mi], __shfl_xor_sync(0xffffffffu, mB[mi], off));
        }
    }
    float sA[2] = {0.f, 0.f}, sB[2] = {0.f, 0.f};
#pragma unroll
    for (int mi = 0; mi < 2; mi++)
#pragma unroll
        for (int ni = 0; ni < 4; ni++) {
            S[mi][ni][0] = __expf(S[mi][ni][0] - mA[mi]);
            S[mi][ni][1] = __expf(S[mi][ni][1] - mA[mi]);
            S[mi][ni][2] = __expf(S[mi][ni][2] - mB[mi]);
            S[mi][ni][3] = __expf(S[mi][ni][3] - mB[mi]);
            sA[mi] += S[mi][ni][0] + S[mi][ni][1];
            sB[mi] += S[mi][ni][2] + S[mi][ni][3];
        }
#pragma unroll
    for (int off = 1; off <= 2; off <<= 1) {
#pragma unroll
        for (int mi = 0; mi < 2; mi++) {
            sA[mi] += __shfl_xor_sync(0xffffffffu, sA[mi], off);
            sB[mi] += __shfl_xor_sync(0xffffffffu, sB[mi], off);
        }
    }
    uint32_t p01[2][4], p23[2][4];
#pragma unroll
    for (int mi = 0; mi < 2; mi++) {
        float iA = 1.f / sA[mi], iB = 1.f / sB[mi];
#pragma unroll
        for (int ni = 0; ni < 4; ni++) {
            p01[mi][ni] = packh2(S[mi][ni][0] * iA, S[mi][ni][1] * iA);
            p23[mi][ni] = packh2(S[mi][ni][2] * iB, S[mi][ni][3] * iB);
        }
    }

    // ---- O = P V  (M=32, N=64, K=32), B from Vt
    float o[2][8][4];
#pragma unroll
    for (int mi = 0; mi < 2; mi++)
#pragma unroll
        for (int ni = 0; ni < 8; ni++)
#pragma unroll
            for (int e = 0; e < 4; e++) o[mi][ni][e] = 0.f;

#pragma unroll
    for (int s = 0; s < 2; ++s) {
        uint32_t bfr[4][4];
#pragma unroll
        for (int nj = 0; nj < 4; nj++)
            ldsm4(bfr[nj], wbase + AVT_OFF +
                  (b_row + nj * 16) * VT_STRIDE_B + (s * 2 + b_kh) * 16);
#pragma unroll
        for (int mi = 0; mi < 2; mi++) {
            uint32_t a[4] = {p01[mi][2 * s], p23[mi][2 * s],
                             p01[mi][2 * s + 1], p23[mi][2 * s + 1]};
#pragma unroll
            for (int ni = 0; ni < 8; ni++)
                mma16816(o[mi][ni], a,
                         bfr[ni >> 1][(ni & 1) * 2], bfr[ni >> 1][(ni & 1) * 2 + 1]);
        }
    }

    // ---- store O fp16
    __half* ob = O + (size_t)(bs * T_) * D_ + head * HD_;
#pragma unroll
    for (int mi = 0; mi < 2; mi++) {
        int rA = (lane >> 2) + 16 * mi;
#pragma unroll
        for (int ni = 0; ni < 8; ni++) {
            int d = 8 * ni + col0;
            store2(ob + (size_t)rA * D_ + d,       o[mi][ni][0], o[mi][ni][1]);
            store2(ob + (size_t)(rA + 8) * D_ + d, o[mi][ni][2], o[mi][ni][3]);
        }
    }
}

// ---------------------------------------------------------------------------
extern "C" void kernel_launch(void* const* d_in, const int* in_sizes, int n_in,
                              void* d_out, int out_size) {
    const float* h   = (const float*)d_in[0];
    const float* u   = (const float*)d_in[1];
    const float* lam = (const float*)d_in[2];
    const float* Wq  = (const float*)d_in[3];
    const float* bq  = (const float*)d_in[4];
    const float* Wk  = (const float*)d_in[5];
    const float* bk  = (const float*)d_in[6];
    const float* Wv  = (const float*)d_in[7];
    const float* bv  = (const float*)d_in[8];
    const float* Wo  = (const float*)d_in[9];
    const float* bo  = (const float*)d_in[10];
    float* out = (float*)d_out;

    __half *hh, *aout, *wqkv, *wo, *QKVh;
    float *bqkv, *oseq, *upen;
    cudaGetSymbolAddress((void**)&hh,   g_hh);
    cudaGetSymbolAddress((void**)&aout, g_aout);
    cudaGetSymbolAddress((void**)&wqkv, g_wqkv);
    cudaGetSymbolAddress((void**)&wo,   g_wo);
    cudaGetSymbolAddress((void**)&bqkv, g_bqkv);
    cudaGetSymbolAddress((void**)&QKVh, g_QKV);
    cudaGetSymbolAddress((void**)&oseq, g_oseq);
    cudaGetSymbolAddress((void**)&upen, g_upen);

    cudaFuncSetAttribute(gemm_mma<__half>, cudaFuncAttributeMaxDynamicSharedMemorySize,
                         3 * STG_BYTES);
    cudaFuncSetAttribute(gemm_mma<float>, cudaFuncAttributeMaxDynamicSharedMemorySize,
                         3 * STG_BYTES);
    cudaFuncSetAttribute(attn_mma, cudaFuncAttributeMaxDynamicSharedMemorySize,
                         ATTN_SMEM);

    dim3 tgrid(8, 24, 128), tblk(32, 32);
    transpose_in_h<<<tgrid, tblk>>>(h, hh);
    upen_kernel<<<128, 256>>>(u, lam, upen);
    wconv<<<(D_ * D_) / 256, 256>>>(Wq, wqkv);
    wconv<<<(D_ * D_) / 256, 256>>>(Wk, wqkv + (size_t)D_ * D_);
    wconv<<<(D_ * D_) / 256, 256>>>(Wv, wqkv + (size_t)2 * D_ * D_);
    wconv<<<(D_ * D_) / 256, 256>>>(Wo, wo);
    pack_bias<<<(NQKV + 255) / 256, 256>>>(bq, bk, bv, bqkv);

    // fused QKV projection: C[M, 2304] fp16
    dim3 qgrid(NQKV / BN, M_ / BM);        // (9, 256)
    gemm_mma<__half><<<qgrid, 512, 3 * STG_BYTES>>>(hh, wqkv, bqkv, QKVh, NQKV);

    dim3 agrid(BS_, 3);
    attn_mma<<<agrid, 128, ATTN_SMEM>>>(QKVh, upen, aout);

    // O projection: C[M, 768] fp32
    dim3 ogrid(D_ / BN, M_ / BM);          // (3, 256)
    gemm_mma<float><<<ogrid, 512, 3 * STG_BYTES>>>(aout, wo, bo, oseq, D_);

    transpose_out<<<tgrid, tblk>>>(oseq, out);
}

// round 12
// speedup vs baseline: 6.2366x; 1.0935x over previous
#include <cuda_runtime.h>
#include <cuda_fp16.h>
#include <cstdint>

// Problem constants
#define B_   4
#define T_   32
#define D_   768
#define P_   256
#define BS_  1024
#define M_   32768
#define NH_  12
#define HD_  64
#define NQKV 2304          // fused Q|K|V output width

// GEMM tiling: 128x128, BK=64, 8 warps (4m x 2n), warp tile 32x64, 2 CTAs/SM
#define BM   128
#define BN   128
#define BK   64
#define NKT  (D_ / BK)     // 12
#define STG_BYTES 32768    // A 16K + B 16K
#define B_OFFS 16384

#define SW128(b) ((b) ^ (((b) >> 3) & 0x70))

// Attention smem layout (per warp): Q 32x72h, K 32x72h, Vt 64x40h
#define QK_STRIDE_B 144
#define VT_STRIDE_B 80
#define AQ_OFF 0
#define AK_OFF 4608
#define AVT_OFF 9216
#define AWARP_BYTES 14336
#define AUPEN_OFF (4 * AWARP_BYTES)
#define ATTN_SMEM (AUPEN_OFF + 128)

// ---------------- scratch (device globals; no cudaMalloc allowed) ----------
__device__ __half g_hh  [(size_t)M_ * D_];       // h_seq fp16
__device__ __half g_aout[(size_t)M_ * D_];       // attention out fp16
__device__ __half g_wqkv[(size_t)NQKV * D_];     // fused Wq|Wk|Wv fp16
__device__ __half g_wo  [(size_t)D_ * D_];
__device__ float  g_bqkv[NQKV];
__device__ __half g_QKV [(size_t)M_ * NQKV];     // fused Q|K|V fp16
__device__ float  g_oseq[(size_t)M_ * D_];
__device__ float  g_upen[M_];

// ---------------- PTX helpers (base-PTX, sm_80-era) ------------------------
__device__ __forceinline__ uint32_t smem_u32(const void* p) {
    uint32_t a;
    asm("{ .reg .u64 t; cvta.to.shared.u64 t, %1; cvt.u32.u64 %0, t; }"
        : "=r"(a) : "l"(p));
    return a;
}

__device__ __forceinline__ void cp16(uint32_t dst, const void* src) {
    asm volatile("cp.async.cg.shared.global [%0], [%1], 16;" :: "r"(dst), "l"(src));
}
#define CP_COMMIT() asm volatile("cp.async.commit_group;" ::: "memory")
#define CP_WAIT(n)  asm volatile("cp.async.wait_group %0;" :: "n"(n) : "memory")

__device__ __forceinline__ void ldsm4(uint32_t (&r)[4], uint32_t addr) {
    asm volatile("ldmatrix.sync.aligned.m8n8.x4.shared.b16 {%0,%1,%2,%3}, [%4];"
                 : "=r"(r[0]), "=r"(r[1]), "=r"(r[2]), "=r"(r[3]) : "r"(addr));
}

__device__ __forceinline__ void mma16816(float (&d)[4], const uint32_t (&a)[4],
                                         uint32_t b0, uint32_t b1) {
    asm volatile(
        "mma.sync.aligned.m16n8k16.row.col.f32.f16.f16.f32 "
        "{%0,%1,%2,%3}, {%4,%5,%6,%7}, {%8,%9}, {%0,%1,%2,%3};"
        : "+f"(d[0]), "+f"(d[1]), "+f"(d[2]), "+f"(d[3])
        : "r"(a[0]), "r"(a[1]), "r"(a[2]), "r"(a[3]), "r"(b0), "r"(b1));
}

__device__ __forceinline__ uint32_t packh2(float x, float y) {
    __half2 h = __floats2half2_rn(x, y);
    return *reinterpret_cast<uint32_t*>(&h);
}

__device__ __forceinline__ void store2(float* p, float x, float y) {
    *reinterpret_cast<float2*>(p) = make_float2(x, y);
}
__device__ __forceinline__ void store2(__half* p, float x, float y) {
    *reinterpret_cast<__half2*>(p) = __floats2half2_rn(x, y);
}

// ---------------------------------------------------------------------------
// transpose to (bs, t, d) + fp16 convert
// ---------------------------------------------------------------------------
__global__ __launch_bounds__(1024) void transpose_in_h(const float* __restrict__ src,
                                                       __half* __restrict__ dst) {
    __shared__ float tile[32][33];
    int bt = blockIdx.z, b = bt >> 5, t = bt & 31;
    int dblk = blockIdx.y * 32, pblk = blockIdx.x * 32;

    int d = dblk + threadIdx.y, p = pblk + threadIdx.x;
    tile[threadIdx.y][threadIdx.x] = src[((size_t)bt * D_ + d) * P_ + p];
    __syncthreads();
    int d2 = dblk + threadIdx.x, p2 = pblk + threadIdx.y;
    dst[(((size_t)(b * P_ + p2)) * T_ + t) * D_ + d2] =
        __float2half(tile[threadIdx.x][threadIdx.y]);
}

// ---------------------------------------------------------------------------
// all-4 weight convert: fp32 -> fp16, float4-vectorized
// ---------------------------------------------------------------------------
__global__ __launch_bounds__(256) void wconv4(const float* __restrict__ Wq,
                                              const float* __restrict__ Wk,
                                              const float* __restrict__ Wv,
                                              const float* __restrict__ Wo,
                                              __half* __restrict__ wqkv,
                                              __half* __restrict__ wo) {
    int idx = blockIdx.x * 256 + threadIdx.x;        // float4 index
    int w = blockIdx.y;
    const float* src = (w == 0) ? Wq : (w == 1) ? Wk : (w == 2) ? Wv : Wo;
    __half* dst = (w == 3) ? wo : wqkv + (size_t)w * D_ * D_;
    float4 v = *reinterpret_cast<const float4*>(src + idx * 4);
    __half2 h0 = __floats2half2_rn(v.x, v.y);
    __half2 h1 = __floats2half2_rn(v.z, v.w);
    uint2 o = make_uint2(*reinterpret_cast<uint32_t*>(&h0),
                         *reinterpret_cast<uint32_t*>(&h1));
    *reinterpret_cast<uint2*>(dst + idx * 4) = o;
}

__global__ __launch_bounds__(256) void pack_bias(const float* __restrict__ bq,
                                                 const float* __restrict__ bk,
                                                 const float* __restrict__ bv,
                                                 float* __restrict__ dst) {
    int i = blockIdx.x * 256 + threadIdx.x;
    if (i >= NQKV) return;
    float v = (i < D_) ? bq[i] : (i < 2 * D_) ? bk[i - D_] : bv[i - 2 * D_];
    dst[i] = v;
}

// ---------------------------------------------------------------------------
// (bs, t, d) -> (B,T,D,P)
// ---------------------------------------------------------------------------
__global__ __launch_bounds__(1024) void transpose_out(const float* __restrict__ src,
                                                      float* __restrict__ dst) {
    __shared__ float tile[32][33];
    int bt = blockIdx.z, b = bt >> 5, t = bt & 31;
    int dblk = blockIdx.y * 32, pblk = blockIdx.x * 32;

    int d = dblk + threadIdx.x, p = pblk + threadIdx.y;
    tile[threadIdx.y][threadIdx.x] = src[(((size_t)(b * P_ + p)) * T_ + t) * D_ + d];
    __syncthreads();
    int p2 = pblk + threadIdx.x, d2 = dblk + threadIdx.y;
    dst[((size_t)bt * D_ + d2) * P_ + p2] = tile[threadIdx.x][threadIdx.y];
}

// ---------------------------------------------------------------------------
// u_pen
// ---------------------------------------------------------------------------
__global__ __launch_bounds__(256) void upen_kernel(const float* __restrict__ u,
                                                   const float* __restrict__ lam,
                                                   float* __restrict__ upen) {
    int bt = blockIdx.x, b = bt >> 5, t = bt & 31;
    int p = threadIdx.x;
    const float* up = u + (size_t)bt * D_ * P_ + p;
    float acc = 0.f;
#pragma unroll 8
    for (int d = 0; d < D_; d++) acc += up[(size_t)d * P_];
    upen[(b * P_ + p) * T_ + t] = lam[(size_t)bt * P_ + p] * acc * (1.0f / (float)D_);
}

// ---------------------------------------------------------------------------
// HMMA GEMM:  C[M, ldc-tile] = A[M,768] @ W[ldc,768]^T + bias
// 128x128 tile, BK=64, 3-stage cp.async, 8 warps x (32x64), 2 CTAs/SM.
// ---------------------------------------------------------------------------
template <typename TO>
__global__ __launch_bounds__(256, 2) void gemm_mma(const __half* __restrict__ A,
                                                   const __half* __restrict__ Wt,
                                                   const float* __restrict__ bias,
                                                   TO* __restrict__ C,
                                                   int ldc) {
    extern __shared__ __align__(128) char dyn[];
    const uint32_t dynb = smem_u32(dyn);

    const int tid  = threadIdx.x;
    const int wid  = tid >> 5;
    const int lane = tid & 31;
    const int mblk = blockIdx.y * BM;
    const int nblk = blockIdx.x * BN;

    const int warp_m = (wid >> 1) * 32;   // 0,32,64,96
    const int warp_n = (wid & 1) * 64;    // 0,64

    const __half* Ab = A  + (size_t)mblk * D_;
    const __half* Bb = Wt + (size_t)nblk * D_;

    // 2048 x 16B chunks per stage / 256 threads = 8 per thread
    auto load_tile = [&](int stage, int kt) {
        uint32_t sb = dynb + stage * STG_BYTES;
        const __half* Ak = Ab + kt * BK;
        const __half* Bk = Bb + kt * BK;
#pragma unroll
        for (int i = 0; i < 8; ++i) {
            int c = tid + 256 * i;
            if (c < 1024) {                           // A: 128 rows x 8
                int r = c >> 3, kc = c & 7;
                cp16(sb + SW128(r * 128 + kc * 16),
                     Ak + (size_t)r * D_ + kc * 8);
            } else {                                  // B: 128 rows x 8
                int c2 = c - 1024;
                int r = c2 >> 3, kc = c2 & 7;
                cp16(sb + B_OFFS + SW128(r * 128 + kc * 16),
                     Bk + (size_t)r * D_ + kc * 8);
            }
        }
        CP_COMMIT();
    };

    const int a_row = warp_m + (lane & 15);
    const int a_kh  = lane >> 4;
    const int b_row = warp_n + (lane & 7) + ((lane >> 4) << 3);
    const int b_kh  = (lane >> 3) & 1;

    float acc[2][8][4];
#pragma unroll
    for (int mi = 0; mi < 2; mi++)
#pragma unroll
        for (int ni = 0; ni < 8; ni++)
#pragma unroll
            for (int e = 0; e < 4; e++) acc[mi][ni][e] = 0.f;

    load_tile(0, 0);
    load_tile(1, 1);

    for (int kt = 0; kt < NKT; ++kt) {
        const int cur = kt % 3;

        if (kt < NKT - 1) CP_WAIT(1); else CP_WAIT(0);
        __syncthreads();

        if (kt + 2 < NKT) load_tile((kt + 2) % 3, kt + 2);

        const uint32_t sb = dynb + cur * STG_BYTES;
#pragma unroll
        for (int s = 0; s < 4; ++s) {
            uint32_t bfr[4][4];
#pragma unroll
            for (int nj = 0; nj < 4; nj++)
                ldsm4(bfr[nj], sb + B_OFFS +
                      SW128((b_row + nj * 16) * 128 + (s * 2 + b_kh) * 16));
            uint32_t afr[2][4];
#pragma unroll
            for (int mi = 0; mi < 2; mi++)
                ldsm4(afr[mi], sb +
                      SW128((a_row + mi * 16) * 128 + (s * 2 + a_kh) * 16));
#pragma unroll
            for (int mi = 0; mi < 2; mi++) {
#pragma unroll
                for (int ni = 0; ni < 8; ni++) {
                    uint32_t b0 = bfr[ni >> 1][(ni & 1) * 2 + 0];
                    uint32_t b1 = bfr[ni >> 1][(ni & 1) * 2 + 1];
                    mma16816(acc[mi][ni], afr[mi], b0, b1);
                }
            }
        }
    }

    const int row0 = mblk + warp_m + (lane >> 2);
    const int col0 = nblk + warp_n + (lane & 3) * 2;
    float2 bb[8];
#pragma unroll
    for (int ni = 0; ni < 8; ni++) {
        int n = col0 + ni * 8;
        bb[ni].x = __ldg(&bias[n]);
        bb[ni].y = __ldg(&bias[n + 1]);
    }
#pragma unroll
    for (int mi = 0; mi < 2; mi++) {
        int r0 = row0 + mi * 16;
#pragma unroll
        for (int ni = 0; ni < 8; ni++) {
            int n = col0 + ni * 8;
            store2(C + (size_t)r0 * ldc + n,
                   acc[mi][ni][0] + bb[ni].x, acc[mi][ni][1] + bb[ni].y);
            store2(C + (size_t)(r0 + 8) * ldc + n,
                   acc[mi][ni][2] + bb[ni].x, acc[mi][ni][3] + bb[ni].y);
        }
    }
}

// ---------------------------------------------------------------------------
// HMMA attention: 1 warp per (bs, head). Block = 4 warps; grid (BS, 3).
// ---------------------------------------------------------------------------
__global__ __launch_bounds__(128) void attn_mma(const __half* __restrict__ QKV,
                                                const float* __restrict__ upen,
                                                __half* __restrict__ O) {
    extern __shared__ __align__(128) char asm_[];
    const int bs   = blockIdx.x;
    const int wid  = threadIdx.x >> 5;
    const int lane = threadIdx.x & 31;
    const int head = blockIdx.y * 4 + wid;

    char* wb = asm_ + wid * AWARP_BYTES;
    const uint32_t wbase = smem_u32(asm_) + wid * AWARP_BYTES;
    float* us = reinterpret_cast<float*>(asm_ + AUPEN_OFF);

    if (threadIdx.x < 32) us[threadIdx.x] = upen[bs * T_ + threadIdx.x];

    const __half* hb = QKV + (size_t)(bs * T_) * NQKV + head * HD_;
#pragma unroll
    for (int i = 0; i < 8; ++i) {
        int id = lane + 32 * i;
        int r = id >> 3, c = id & 7;
        const __half* qsrc = hb + (size_t)r * NQKV + c * 8;
        *reinterpret_cast<uint4*>(wb + AQ_OFF + r * QK_STRIDE_B + c * 16) =
            *reinterpret_cast<const uint4*>(qsrc);
        *reinterpret_cast<uint4*>(wb + AK_OFF + r * QK_STRIDE_B + c * 16) =
            *reinterpret_cast<const uint4*>(qsrc + D_);
        uint4 vv = *reinterpret_cast<const uint4*>(qsrc + 2 * D_);
        const __half* vh = reinterpret_cast<const __half*>(&vv);
#pragma unroll
        for (int j = 0; j < 8; ++j)
            *reinterpret_cast<__half*>(wb + AVT_OFF + (c * 8 + j) * VT_STRIDE_B + r * 2) = vh[j];
    }
    __syncthreads();

    const int a_kh  = lane >> 4;
    const int b_row = (lane & 7) + ((lane >> 4) << 3);
    const int b_kh  = (lane >> 3) & 1;
    const int col0  = (lane & 3) * 2;

    float S[2][4][4];
#pragma unroll
    for (int mi = 0; mi < 2; mi++)
#pragma unroll
        for (int ni = 0; ni < 4; ni++)
#pragma unroll
            for (int e = 0; e < 4; e++) S[mi][ni][e] = 0.f;

#pragma unroll
    for (int s = 0; s < 4; ++s) {
        uint32_t bfr[2][4];
#pragma unroll
        for (int nj = 0; nj < 2; nj++)
            ldsm4(bfr[nj], wbase + AK_OFF +
                  (b_row + nj * 16) * QK_STRIDE_B + (s * 2 + b_kh) * 16);
        uint32_t afr[2][4];
#pragma unroll
        for (int mi = 0; mi < 2; mi++)
            ldsm4(afr[mi], wbase + AQ_OFF +
                  ((lane & 15) + mi * 16) * QK_STRIDE_B + (s * 2 + a_kh) * 16);
#pragma unroll
        for (int mi = 0; mi < 2; mi++)
#pragma unroll
            for (int ni = 0; ni < 4; ni++)
                mma16816(S[mi][ni], afr[mi],
                         bfr[ni >> 1][(ni & 1) * 2], bfr[ni >> 1][(ni & 1) * 2 + 1]);
    }

    float uv[4][2];
#pragma unroll
    for (int ni = 0; ni < 4; ni++) {
        uv[ni][0] = us[8 * ni + col0];
        uv[ni][1] = us[8 * ni + col0 + 1];
    }
    float mA[2] = {-1e30f, -1e30f}, mB[2] = {-1e30f, -1e30f};
#pragma unroll
    for (int mi = 0; mi < 2; mi++)
#pragma unroll
        for (int ni = 0; ni < 4; ni++) {
            S[mi][ni][0] = S[mi][ni][0] * 0.125f - uv[ni][0];
            S[mi][ni][1] = S[mi][ni][1] * 0.125f - uv[ni][1];
            S[mi][ni][2] = S[mi][ni][2] * 0.125f - uv[ni][0];
            S[mi][ni][3] = S[mi][ni][3] * 0.125f - uv[ni][1];
            mA[mi] = fmaxf(mA[mi], fmaxf(S[mi][ni][0], S[mi][ni][1]));
            mB[mi] = fmaxf(mB[mi], fmaxf(S[mi][ni][2], S[mi][ni][3]));
        }
#pragma unroll
    for (int off = 1; off <= 2; off <<= 1) {
#pragma unroll
        for (int mi = 0; mi < 2; mi++) {
            mA[mi] = fmaxf(mA[mi], __shfl_xor_sync(0xffffffffu, mA[mi], off));
            mB[mi] = fmaxf(mB[mi], __shfl_xor_sync(0xffffffffu, mB[mi], off));
        }
    }
    float sA[2] = {0.f, 0.f}, sB[2] = {0.f, 0.f};
#pragma unroll
    for (int mi = 0; mi < 2; mi++)
#pragma unroll
        for (int ni = 0; ni < 4; ni++) {
            S[mi][ni][0] = __expf(S[mi][ni][0] - mA[mi]);
            S[mi][ni][1] = __expf(S[mi][ni][1] - mA[mi]);
            S[mi][ni][2] = __expf(S[mi][ni][2] - mB[mi]);
            S[mi][ni][3] = __expf(S[mi][ni][3] - mB[mi]);
            sA[mi] += S[mi][ni][0] + S[mi][ni][1];
            sB[mi] += S[mi][ni][2] + S[mi][ni][3];
        }
#pragma unroll
    for (int off = 1; off <= 2; off <<= 1) {
#pragma unroll
        for (int mi = 0; mi < 2; mi++) {
            sA[mi] += __shfl_xor_sync(0xffffffffu, sA[mi], off);
            sB[mi] += __shfl_xor_sync(0xffffffffu, sB[mi], off);
        }
    }
    uint32_t p01[2][4], p23[2][4];
#pragma unroll
    for (int mi = 0; mi < 2; mi++) {
        float iA = 1.f / sA[mi], iB = 1.f / sB[mi];
#pragma unroll
        for (int ni = 0; ni < 4; ni++) {
            p01[mi][ni] = packh2(S[mi][ni][0] * iA, S[mi][ni][1] * iA);
            p23[mi][ni] = packh2(S[mi][ni][2] * iB, S[mi][ni][3] * iB);
        }
    }

    float o[2][8][4];
#pragma unroll
    for (int mi = 0; mi < 2; mi++)
#pragma unroll
        for (int ni = 0; ni < 8; ni++)
#pragma unroll
            for (int e = 0; e < 4; e++) o[mi][ni][e] = 0.f;

#pragma unroll
    for (int s = 0; s < 2; ++s) {
        uint32_t bfr[4][4];
#pragma unroll
        for (int nj = 0; nj < 4; nj++)
            ldsm4(bfr[nj], wbase + AVT_OFF +
                  (b_row + nj * 16) * VT_STRIDE_B + (s * 2 + b_kh) * 16);
#pragma unroll
        for (int mi = 0; mi < 2; mi++) {
            uint32_t a[4] = {p01[mi][2 * s], p23[mi][2 * s],
                             p01[mi][2 * s + 1], p23[mi][2 * s + 1]};
#pragma unroll
            for (int ni = 0; ni < 8; ni++)
                mma16816(o[mi][ni], a,
                         bfr[ni >> 1][(ni & 1) * 2], bfr[ni >> 1][(ni & 1) * 2 + 1]);
        }
    }

    __half* ob = O + (size_t)(bs * T_) * D_ + head * HD_;
#pragma unroll
    for (int mi = 0; mi < 2; mi++) {
        int rA = (lane >> 2) + 16 * mi;
#pragma unroll
        for (int ni = 0; ni < 8; ni++) {
            int d = 8 * ni + col0;
            store2(ob + (size_t)rA * D_ + d,       o[mi][ni][0], o[mi][ni][1]);
            store2(ob + (size_t)(rA + 8) * D_ + d, o[mi][ni][2], o[mi][ni][3]);
        }
    }
}

// ---------------------------------------------------------------------------
extern "C" void kernel_launch(void* const* d_in, const int* in_sizes, int n_in,
                              void* d_out, int out_size) {
    const float* h   = (const float*)d_in[0];
    const float* u   = (const float*)d_in[1];
    const float* lam = (const float*)d_in[2];
    const float* Wq  = (const float*)d_in[3];
    const float* bq  = (const float*)d_in[4];
    const float* Wk  = (const float*)d_in[5];
    const float* bk  = (const float*)d_in[6];
    const float* Wv  = (const float*)d_in[7];
    const float* bv  = (const float*)d_in[8];
    const float* Wo  = (const float*)d_in[9];
    const float* bo  = (const float*)d_in[10];
    float* out = (float*)d_out;

    __half *hh, *aout, *wqkv, *wo, *QKVh;
    float *bqkv, *oseq, *upen;
    cudaGetSymbolAddress((void**)&hh,   g_hh);
    cudaGetSymbolAddress((void**)&aout, g_aout);
    cudaGetSymbolAddress((void**)&wqkv, g_wqkv);
    cudaGetSymbolAddress((void**)&wo,   g_wo);
    cudaGetSymbolAddress((void**)&bqkv, g_bqkv);
    cudaGetSymbolAddress((void**)&QKVh, g_QKV);
    cudaGetSymbolAddress((void**)&oseq, g_oseq);
    cudaGetSymbolAddress((void**)&upen, g_upen);

    cudaFuncSetAttribute(gemm_mma<__half>, cudaFuncAttributeMaxDynamicSharedMemorySize,
                         3 * STG_BYTES);
    cudaFuncSetAttribute(gemm_mma<float>, cudaFuncAttributeMaxDynamicSharedMemorySize,
                         3 * STG_BYTES);
    cudaFuncSetAttribute(attn_mma, cudaFuncAttributeMaxDynamicSharedMemorySize,
                         ATTN_SMEM);

    dim3 tgrid(8, 24, 128), tblk(32, 32);
    transpose_in_h<<<tgrid, tblk>>>(h, hh);
    upen_kernel<<<128, 256>>>(u, lam, upen);
    dim3 wgrid((D_ * D_) / 1024, 4);
    wconv4<<<wgrid, 256>>>(Wq, Wk, Wv, Wo, wqkv, wo);
    pack_bias<<<(NQKV + 255) / 256, 256>>>(bq, bk, bv, bqkv);

    // fused QKV projection: C[M, 2304] fp16
    dim3 qgrid(NQKV / BN, M_ / BM);        // (18, 256)
    gemm_mma<__half><<<qgrid, 256, 3 * STG_BYTES>>>(hh, wqkv, bqkv, QKVh, NQKV);

    dim3 agrid(BS_, 3);
    attn_mma<<<agrid, 128, ATTN_SMEM>>>(QKVh, upen, aout);

    // O projection: C[M, 768] fp32
    dim3 ogrid(D_ / BN, M_ / BM);          // (6, 256)
    gemm_mma<float><<<ogrid, 256, 3 * STG_BYTES>>>(aout, wo, bo, oseq, D_);

    transpose_out<<<tgrid, tblk>>>(oseq, out);
}

// round 14
// speedup vs baseline: 6.9265x; 1.1106x over previous
#include <cuda_runtime.h>
#include <cuda_fp16.h>
#include <cstdint>

// Problem constants
#define B_   4
#define T_   32
#define D_   768
#define P_   256
#define BS_  1024
#define M_   32768
#define NH_  12
#define HD_  64
#define NQKV 2304          // fused Q|K|V output width

// Sequence-major layout: row m = t*BS_ + bs   (bs = b*P_ + p)

// GEMM tiling: 128x128, BK=64, 8 warps (4m x 2n), warp tile 32x64, 2 CTAs/SM
#define BM   128
#define BN   128
#define BK   64
#define NKT  (D_ / BK)     // 12
#define STG_BYTES 32768    // A 16K + B 16K
#define B_OFFS 16384

#define SW128(b) ((b) ^ (((b) >> 3) & 0x70))

// Attention smem layout (per warp): Q 32x72h, K 32x72h, Vt 64x40h
#define QK_STRIDE_B 144
#define VT_STRIDE_B 80
#define AQ_OFF 0
#define AK_OFF 4608
#define AVT_OFF 9216
#define AWARP_BYTES 14336
#define AUPEN_OFF (4 * AWARP_BYTES)
#define ATTN_SMEM (AUPEN_OFF + 128)

// ---------------- scratch (device globals; no cudaMalloc allowed) ----------
__device__ __half g_hh  [(size_t)M_ * D_];       // h_seq fp16, [t][bs][d]
__device__ __half g_aout[(size_t)M_ * D_];       // attention out fp16, [t][bs][d]
__device__ __half g_wqkv[(size_t)NQKV * D_];     // fused Wq|Wk|Wv fp16
__device__ __half g_wo  [(size_t)D_ * D_];
__device__ float  g_bqkv[NQKV];
__device__ __half g_QKV [(size_t)M_ * NQKV];     // fused Q|K|V fp16, [t][bs]
__device__ float  g_upen[M_];                    // [bs][t]

// ---------------- PTX helpers (base-PTX, sm_80-era) ------------------------
__device__ __forceinline__ uint32_t smem_u32(const void* p) {
    uint32_t a;
    asm("{ .reg .u64 t; cvta.to.shared.u64 t, %1; cvt.u32.u64 %0, t; }"
        : "=r"(a) : "l"(p));
    return a;
}

__device__ __forceinline__ void cp16(uint32_t dst, const void* src) {
    asm volatile("cp.async.cg.shared.global [%0], [%1], 16;" :: "r"(dst), "l"(src));
}
#define CP_COMMIT() asm volatile("cp.async.commit_group;" ::: "memory")
#define CP_WAIT(n)  asm volatile("cp.async.wait_group %0;" :: "n"(n) : "memory")

__device__ __forceinline__ void ldsm4(uint32_t (&r)[4], uint32_t addr) {
    asm volatile("ldmatrix.sync.aligned.m8n8.x4.shared.b16 {%0,%1,%2,%3}, [%4];"
                 : "=r"(r[0]), "=r"(r[1]), "=r"(r[2]), "=r"(r[3]) : "r"(addr));
}

__device__ __forceinline__ void mma16816(float (&d)[4], const uint32_t (&a)[4],
                                         uint32_t b0, uint32_t b1) {
    asm volatile(
        "mma.sync.aligned.m16n8k16.row.col.f32.f16.f16.f32 "
        "{%0,%1,%2,%3}, {%4,%5,%6,%7}, {%8,%9}, {%0,%1,%2,%3};"
        : "+f"(d[0]), "+f"(d[1]), "+f"(d[2]), "+f"(d[3])
        : "r"(a[0]), "r"(a[1]), "r"(a[2]), "r"(a[3]), "r"(b0), "r"(b1));
}

__device__ __forceinline__ uint32_t packh2(float x, float y) {
    __half2 h = __floats2half2_rn(x, y);
    return *reinterpret_cast<uint32_t*>(&h);
}

__device__ __forceinline__ void store2(float* p, float x, float y) {
    *reinterpret_cast<float2*>(p) = make_float2(x, y);
}
__device__ __forceinline__ void store2(__half* p, float x, float y) {
    *reinterpret_cast<__half2*>(p) = __floats2half2_rn(x, y);
}

// ---------------------------------------------------------------------------
// transpose to [t][bs][d] + fp16 convert
// ---------------------------------------------------------------------------
__global__ __launch_bounds__(1024) void transpose_in_h(const float* __restrict__ src,
                                                       __half* __restrict__ dst) {
    __shared__ float tile[32][33];
    int bt = blockIdx.z, b = bt >> 5, t = bt & 31;
    int dblk = blockIdx.y * 32, pblk = blockIdx.x * 32;

    int d = dblk + threadIdx.y, p = pblk + threadIdx.x;
    tile[threadIdx.y][threadIdx.x] = src[((size_t)bt * D_ + d) * P_ + p];
    __syncthreads();
    int d2 = dblk + threadIdx.x, p2 = pblk + threadIdx.y;
    dst[((size_t)t * BS_ + b * P_ + p2) * D_ + d2] =
        __float2half(tile[threadIdx.x][threadIdx.y]);
}

// ---------------------------------------------------------------------------
// all-4 weight convert: fp32 -> fp16, float4-vectorized
// ---------------------------------------------------------------------------
__global__ __launch_bounds__(256) void wconv4(const float* __restrict__ Wq,
                                              const float* __restrict__ Wk,
                                              const float* __restrict__ Wv,
                                              const float* __restrict__ Wo,
                                              __half* __restrict__ wqkv,
                                              __half* __restrict__ wo) {
    int idx = blockIdx.x * 256 + threadIdx.x;
    int w = blockIdx.y;
    const float* src = (w == 0) ? Wq : (w == 1) ? Wk : (w == 2) ? Wv : Wo;
    __half* dst = (w == 3) ? wo : wqkv + (size_t)w * D_ * D_;
    float4 v = *reinterpret_cast<const float4*>(src + idx * 4);
    __half2 h0 = __floats2half2_rn(v.x, v.y);
    __half2 h1 = __floats2half2_rn(v.z, v.w);
    uint2 o = make_uint2(*reinterpret_cast<uint32_t*>(&h0),
                         *reinterpret_cast<uint32_t*>(&h1));
    *reinterpret_cast<uint2*>(dst + idx * 4) = o;
}

__global__ __launch_bounds__(256) void pack_bias(const float* __restrict__ bq,
                                                 const float* __restrict__ bk,
                                                 const float* __restrict__ bv,
                                                 float* __restrict__ dst) {
    int i = blockIdx.x * 256 + threadIdx.x;
    if (i >= NQKV) return;
    float v = (i < D_) ? bq[i] : (i < 2 * D_) ? bk[i - D_] : bv[i - 2 * D_];
    dst[i] = v;
}

// ---------------------------------------------------------------------------
// u_pen   [bs][t]
// ---------------------------------------------------------------------------
__global__ __launch_bounds__(256) void upen_kernel(const float* __restrict__ u,
                                                   const float* __restrict__ lam,
                                                   float* __restrict__ upen) {
    int bt = blockIdx.x, b = bt >> 5, t = bt & 31;
    int p = threadIdx.x;
    const float* up = u + (size_t)bt * D_ * P_ + p;
    float acc = 0.f;
#pragma unroll 8
    for (int d = 0; d < D_; d++) acc += up[(size_t)d * P_];
    upen[(b * P_ + p) * T_ + t] = lam[(size_t)bt * P_ + p] * acc * (1.0f / (float)D_);
}

// ---------------------------------------------------------------------------
// HMMA GEMM (QKV):  C[m, n] = A[m,768] @ W^T + bias, C fp16 stride NQKV
// 128x128 tile, BK=64, 3-stage cp.async, 8 warps x (32x64), 2 CTAs/SM.
// ---------------------------------------------------------------------------
__global__ __launch_bounds__(256, 2) void gemm_qkv(const __half* __restrict__ A,
                                                   const __half* __restrict__ Wt,
                                                   const float* __restrict__ bias,
                                                   __half* __restrict__ C) {
    extern __shared__ __align__(128) char dyn[];
    const uint32_t dynb = smem_u32(dyn);

    const int tid  = threadIdx.x;
    const int wid  = tid >> 5;
    const int lane = tid & 31;
    const int mblk = blockIdx.y * BM;
    const int nblk = blockIdx.x * BN;

    const int warp_m = (wid >> 1) * 32;
    const int warp_n = (wid & 1) * 64;

    const __half* Ab = A  + (size_t)mblk * D_;
    const __half* Bb = Wt + (size_t)nblk * D_;

    auto load_tile = [&](int stage, int kt) {
        uint32_t sb = dynb + stage * STG_BYTES;
        const __half* Ak = Ab + kt * BK;
        const __half* Bk = Bb + kt * BK;
#pragma unroll
        for (int i = 0; i < 8; ++i) {
            int c = tid + 256 * i;
            if (c < 1024) {
                int r = c >> 3, kc = c & 7;
                cp16(sb + SW128(r * 128 + kc * 16),
                     Ak + (size_t)r * D_ + kc * 8);
            } else {
                int c2 = c - 1024;
                int r = c2 >> 3, kc = c2 & 7;
                cp16(sb + B_OFFS + SW128(r * 128 + kc * 16),
                     Bk + (size_t)r * D_ + kc * 8);
            }
        }
        CP_COMMIT();
    };

    const int a_row = warp_m + (lane & 15);
    const int a_kh  = lane >> 4;
    const int b_row = warp_n + (lane & 7) + ((lane >> 4) << 3);
    const int b_kh  = (lane >> 3) & 1;

    float acc[2][8][4];
#pragma unroll
    for (int mi = 0; mi < 2; mi++)
#pragma unroll
        for (int ni = 0; ni < 8; ni++)
#pragma unroll
            for (int e = 0; e < 4; e++) acc[mi][ni][e] = 0.f;

    load_tile(0, 0);
    load_tile(1, 1);

    for (int kt = 0; kt < NKT; ++kt) {
        const int cur = kt % 3;
        if (kt < NKT - 1) CP_WAIT(1); else CP_WAIT(0);
        __syncthreads();
        if (kt + 2 < NKT) load_tile((kt + 2) % 3, kt + 2);

        const uint32_t sb = dynb + cur * STG_BYTES;
#pragma unroll
        for (int s = 0; s < 4; ++s) {
            uint32_t bfr[4][4];
#pragma unroll
            for (int nj = 0; nj < 4; nj++)
                ldsm4(bfr[nj], sb + B_OFFS +
                      SW128((b_row + nj * 16) * 128 + (s * 2 + b_kh) * 16));
            uint32_t afr[2][4];
#pragma unroll
            for (int mi = 0; mi < 2; mi++)
                ldsm4(afr[mi], sb +
                      SW128((a_row + mi * 16) * 128 + (s * 2 + a_kh) * 16));
#pragma unroll
            for (int mi = 0; mi < 2; mi++) {
#pragma unroll
                for (int ni = 0; ni < 8; ni++) {
                    uint32_t b0 = bfr[ni >> 1][(ni & 1) * 2 + 0];
                    uint32_t b1 = bfr[ni >> 1][(ni & 1) * 2 + 1];
                    mma16816(acc[mi][ni], afr[mi], b0, b1);
                }
            }
        }
    }

    const int row0 = mblk + warp_m + (lane >> 2);
    const int col0 = nblk + warp_n + (lane & 3) * 2;
    float2 bb[8];
#pragma unroll
    for (int ni = 0; ni < 8; ni++) {
        int n = col0 + ni * 8;
        bb[ni].x = __ldg(&bias[n]);
        bb[ni].y = __ldg(&bias[n + 1]);
    }
#pragma unroll
    for (int mi = 0; mi < 2; mi++) {
        int r0 = row0 + mi * 16;
#pragma unroll
        for (int ni = 0; ni < 8; ni++) {
            int n = col0 + ni * 8;
            store2(C + (size_t)r0 * NQKV + n,
                   acc[mi][ni][0] + bb[ni].x, acc[mi][ni][1] + bb[ni].y);
            store2(C + (size_t)(r0 + 8) * NQKV + n,
                   acc[mi][ni][2] + bb[ni].x, acc[mi][ni][3] + bb[ni].y);
        }
    }
}

// ---------------------------------------------------------------------------
// HMMA GEMM (O proj) with FUSED TRANSPOSE epilogue:
// A = aout [t][bs][d] fp16; writes directly to final out (B,T,D,P) fp32.
// m-block (128 rows) = fixed (t, b), p in [p0, p0+128).
// ---------------------------------------------------------------------------
__global__ __launch_bounds__(256, 2) void gemm_oproj(const __half* __restrict__ A,
                                                     const __half* __restrict__ Wt,
                                                     const float* __restrict__ bias,
                                                     float* __restrict__ out) {
    extern __shared__ __align__(128) char dyn[];
    const uint32_t dynb = smem_u32(dyn);

    const int tid  = threadIdx.x;
    const int wid  = tid >> 5;
    const int lane = tid & 31;
    const int mblk = blockIdx.y * BM;
    const int nblk = blockIdx.x * BN;

    const int warp_m = (wid >> 1) * 32;
    const int warp_n = (wid & 1) * 64;

    const __half* Ab = A  + (size_t)mblk * D_;
    const __half* Bb = Wt + (size_t)nblk * D_;

    auto load_tile = [&](int stage, int kt) {
        uint32_t sb = dynb + stage * STG_BYTES;
        const __half* Ak = Ab + kt * BK;
        const __half* Bk = Bb + kt * BK;
#pragma unroll
        for (int i = 0; i < 8; ++i) {
            int c = tid + 256 * i;
            if (c < 1024) {
                int r = c >> 3, kc = c & 7;
                cp16(sb + SW128(r * 128 + kc * 16),
                     Ak + (size_t)r * D_ + kc * 8);
            } else {
                int c2 = c - 1024;
                int r = c2 >> 3, kc = c2 & 7;
                cp16(sb + B_OFFS + SW128(r * 128 + kc * 16),
                     Bk + (size_t)r * D_ + kc * 8);
            }
        }
        CP_COMMIT();
    };

    const int a_row = warp_m + (lane & 15);
    const int a_kh  = lane >> 4;
    const int b_row = warp_n + (lane & 7) + ((lane >> 4) << 3);
    const int b_kh  = (lane >> 3) & 1;

    float acc[2][8][4];
#pragma unroll
    for (int mi = 0; mi < 2; mi++)
#pragma unroll
        for (int ni = 0; ni < 8; ni++)
#pragma unroll
            for (int e = 0; e < 4; e++) acc[mi][ni][e] = 0.f;

    load_tile(0, 0);
    load_tile(1, 1);

    for (int kt = 0; kt < NKT; ++kt) {
        const int cur = kt % 3;
        if (kt < NKT - 1) CP_WAIT(1); else CP_WAIT(0);
        __syncthreads();
        if (kt + 2 < NKT) load_tile((kt + 2) % 3, kt + 2);

        const uint32_t sb = dynb + cur * STG_BYTES;
#pragma unroll
        for (int s = 0; s < 4; ++s) {
            uint32_t bfr[4][4];
#pragma unroll
            for (int nj = 0; nj < 4; nj++)
                ldsm4(bfr[nj], sb + B_OFFS +
                      SW128((b_row + nj * 16) * 128 + (s * 2 + b_kh) * 16));
            uint32_t afr[2][4];
#pragma unroll
            for (int mi = 0; mi < 2; mi++)
                ldsm4(afr[mi], sb +
                      SW128((a_row + mi * 16) * 128 + (s * 2 + a_kh) * 16));
#pragma unroll
            for (int mi = 0; mi < 2; mi++) {
#pragma unroll
                for (int ni = 0; ni < 8; ni++) {
                    uint32_t b0 = bfr[ni >> 1][(ni & 1) * 2 + 0];
                    uint32_t b1 = bfr[ni >> 1][(ni & 1) * 2 + 1];
                    mma16816(acc[mi][ni], afr[mi], b0, b1);
                }
            }
        }
    }

    // ---- fused transpose epilogue ----
    // stage[dp][dn] (stride 129 floats; odd stride -> scalar 4B stores only)
    float* stage = reinterpret_cast<float*>(dyn);
    const int rloc0 = warp_m + (lane >> 2);
    const int nloc0 = warp_n + (lane & 3) * 2;
    float2 bb[8];
#pragma unroll
    for (int ni = 0; ni < 8; ni++) {
        int n = nblk + nloc0 + ni * 8;
        bb[ni].x = __ldg(&bias[n]);
        bb[ni].y = __ldg(&bias[n + 1]);
    }
    __syncthreads();   // all warps done reading pipeline smem
#pragma unroll
    for (int mi = 0; mi < 2; mi++) {
        int r0 = rloc0 + mi * 16;
#pragma unroll
        for (int ni = 0; ni < 8; ni++) {
            int n = nloc0 + ni * 8;
            stage[(size_t)r0 * 129 + n]           = acc[mi][ni][0] + bb[ni].x;
            stage[(size_t)r0 * 129 + n + 1]       = acc[mi][ni][1] + bb[ni].y;
            stage[(size_t)(r0 + 8) * 129 + n]     = acc[mi][ni][2] + bb[ni].x;
            stage[(size_t)(r0 + 8) * 129 + n + 1] = acc[mi][ni][3] + bb[ni].y;
        }
    }
    __syncthreads();

    // m = t*1024 + b*256 + p :  t, b, p0 constant per tile
    const int t  = mblk >> 10;
    const int b  = (mblk & 1023) >> 8;
    const int p0 = mblk & 255;
    float* obase = out + ((size_t)(b * T_ + t) * D_ + nblk) * P_ + p0;
    // 128 dn x 32 float4 = 4096 chunks / 256 threads = 16 each
#pragma unroll
    for (int i = 0; i < 16; ++i) {
        int c = tid + 256 * i;
        int dn = c >> 5, f4 = c & 31;
        float4 v;
        v.x = stage[(size_t)(f4 * 4 + 0) * 129 + dn];
        v.y = stage[(size_t)(f4 * 4 + 1) * 129 + dn];
        v.z = stage[(size_t)(f4 * 4 + 2) * 129 + dn];
        v.w = stage[(size_t)(f4 * 4 + 3) * 129 + dn];
        *reinterpret_cast<float4*>(obase + (size_t)dn * P_ + f4 * 4) = v;
    }
}

// ---------------------------------------------------------------------------
// HMMA attention: 1 warp per (bs, head); rows at stride BS_*NQKV ([t][bs]).
// ---------------------------------------------------------------------------
__global__ __launch_bounds__(128) void attn_mma(const __half* __restrict__ QKV,
                                                const float* __restrict__ upen,
                                                __half* __restrict__ O) {
    extern __shared__ __align__(128) char asm_[];
    const int bs   = blockIdx.x;
    const int wid  = threadIdx.x >> 5;
    const int lane = threadIdx.x & 31;
    const int head = blockIdx.y * 4 + wid;

    char* wb = asm_ + wid * AWARP_BYTES;
    const uint32_t wbase = smem_u32(asm_) + wid * AWARP_BYTES;
    float* us = reinterpret_cast<float*>(asm_ + AUPEN_OFF);

    if (threadIdx.x < 32) us[threadIdx.x] = upen[bs * T_ + threadIdx.x];

    const __half* hb = QKV + (size_t)bs * NQKV + head * HD_;
    const size_t rstride = (size_t)BS_ * NQKV;
#pragma unroll
    for (int i = 0; i < 8; ++i) {
        int id = lane + 32 * i;
        int r = id >> 3, c = id & 7;
        const __half* qsrc = hb + (size_t)r * rstride + c * 8;
        *reinterpret_cast<uint4*>(wb + AQ_OFF + r * QK_STRIDE_B + c * 16) =
            *reinterpret_cast<const uint4*>(qsrc);
        *reinterpret_cast<uint4*>(wb + AK_OFF + r * QK_STRIDE_B + c * 16) =
            *reinterpret_cast<const uint4*>(qsrc + D_);
        uint4 vv = *reinterpret_cast<const uint4*>(qsrc + 2 * D_);
        const __half* vh = reinterpret_cast<const __half*>(&vv);
#pragma unroll
        for (int j = 0; j < 8; ++j)
            *reinterpret_cast<__half*>(wb + AVT_OFF + (c * 8 + j) * VT_STRIDE_B + r * 2) = vh[j];
    }
    __syncthreads();

    const int a_kh  = lane >> 4;
    const int b_row = (lane & 7) + ((lane >> 4) << 3);
    const int b_kh  = (lane >> 3) & 1;
    const int col0  = (lane & 3) * 2;

    float S[2][4][4];
#pragma unroll
    for (int mi = 0; mi < 2; mi++)
#pragma unroll
        for (int ni = 0; ni < 4; ni++)
#pragma unroll
            for (int e = 0; e < 4; e++) S[mi][ni][e] = 0.f;

#pragma unroll
    for (int s = 0; s < 4; ++s) {
        uint32_t bfr[2][4];
#pragma unroll
        for (int nj = 0; nj < 2; nj++)
            ldsm4(bfr[nj], wbase + AK_OFF +
                  (b_row + nj * 16) * QK_STRIDE_B + (s * 2 + b_kh) * 16);
        uint32_t afr[2][4];
#pragma unroll
        for (int mi = 0; mi < 2; mi++)
            ldsm4(afr[mi], wbase + AQ_OFF +
                  ((lane & 15) + mi * 16) * QK_STRIDE_B + (s * 2 + a_kh) * 16);
#pragma unroll
        for (int mi = 0; mi < 2; mi++)
#pragma unroll
            for (int ni = 0; ni < 4; ni++)
                mma16816(S[mi][ni], afr[mi],
                         bfr[ni >> 1][(ni & 1) * 2], bfr[ni >> 1][(ni & 1) * 2 + 1]);
    }

    float uv[4][2];
#pragma unroll
    for (int ni = 0; ni < 4; ni++) {
        uv[ni][0] = us[8 * ni + col0];
        uv[ni][1] = us[8 * ni + col0 + 1];
    }
    float mA[2] = {-1e30f, -1e30f}, mB[2] = {-1e30f, -1e30f};
#pragma unroll
    for (int mi = 0; mi < 2; mi++)
#pragma unroll
        for (int ni = 0; ni < 4; ni++) {
            S[mi][ni][0] = S[mi][ni][0] * 0.125f - uv[ni][0];
            S[mi][ni][1] = S[mi][ni][1] * 0.125f - uv[ni][1];
            S[mi][ni][2] = S[mi][ni][2] * 0.125f - uv[ni][0];
            S[mi][ni][3] = S[mi][ni][3] * 0.125f - uv[ni][1];
            mA[mi] = fmaxf(mA[mi], fmaxf(S[mi][ni][0], S[mi][ni][1]));
            mB[mi] = fmaxf(mB[mi], fmaxf(S[mi][ni][2], S[mi][ni][3]));
        }
#pragma unroll
    for (int off = 1; off <= 2; off <<= 1) {
#pragma unroll
        for (int mi = 0; mi < 2; mi++) {
            mA[mi] = fmaxf(mA[mi], __shfl_xor_sync(0xffffffffu, mA[mi], off));
            mB[mi] = fmaxf(mB[mi], __shfl_xor_sync(0xffffffffu, mB[mi], off));
        }
    }
    float sA[2] = {0.f, 0.f}, sB[2] = {0.f, 0.f};
#pragma unroll
    for (int mi = 0; mi < 2; mi++)
#pragma unroll
        for (int ni = 0; ni < 4; ni++) {
            S[mi][ni][0] = __expf(S[mi][ni][0] - mA[mi]);
            S[mi][ni][1] = __expf(S[mi][ni][1] - mA[mi]);
            S[mi][ni][2] = __expf(S[mi][ni][2] - mB[mi]);
            S[mi][ni][3] = __expf(S[mi][ni][3] - mB[mi]);
            sA[mi] += S[mi][ni][0] + S[mi][ni][1];
            sB[mi] += S[mi][ni][2] + S[mi][ni][3];
        }
#pragma unroll
    for (int off = 1; off <= 2; off <<= 1) {
#pragma unroll
        for (int mi = 0; mi < 2; mi++) {
            sA[mi] += __shfl_xor_sync(0xffffffffu, sA[mi], off);
            sB[mi] += __shfl_xor_sync(0xffffffffu, sB[mi], off);
        }
    }
    uint32_t p01[2][4], p23[2][4];
#pragma unroll
    for (int mi = 0; mi < 2; mi++) {
        float iA = 1.f / sA[mi], iB = 1.f / sB[mi];
#pragma unroll
        for (int ni = 0; ni < 4; ni++) {
            p01[mi][ni] = packh2(S[mi][ni][0] * iA, S[mi][ni][1] * iA);
            p23[mi][ni] = packh2(S[mi][ni][2] * iB, S[mi][ni][3] * iB);
        }
    }

    float o[2][8][4];
#pragma unroll
    for (int mi = 0; mi < 2; mi++)
#pragma unroll
        for (int ni = 0; ni < 8; ni++)
#pragma unroll
            for (int e = 0; e < 4; e++) o[mi][ni][e] = 0.f;

#pragma unroll
    for (int s = 0; s < 2; ++s) {
        uint32_t bfr[4][4];
#pragma unroll
        for (int nj = 0; nj < 4; nj++)
            ldsm4(bfr[nj], wbase + AVT_OFF +
                  (b_row + nj * 16) * VT_STRIDE_B + (s * 2 + b_kh) * 16);
#pragma unroll
        for (int mi = 0; mi < 2; mi++) {
            uint32_t a[4] = {p01[mi][2 * s], p23[mi][2 * s],
                             p01[mi][2 * s + 1], p23[mi][2 * s + 1]};
#pragma unroll
            for (int ni = 0; ni < 8; ni++)
                mma16816(o[mi][ni], a,
                         bfr[ni >> 1][(ni & 1) * 2], bfr[ni >> 1][(ni & 1) * 2 + 1]);
        }
    }

    // store O in [t][bs][d] layout
    __half* ob = O + (size_t)bs * D_ + head * HD_;
    const size_t ostride = (size_t)BS_ * D_;
#pragma unroll
    for (int mi = 0; mi < 2; mi++) {
        int rA = (lane >> 2) + 16 * mi;
#pragma unroll
        for (int ni = 0; ni < 8; ni++) {
            int d = 8 * ni + col0;
            store2(ob + (size_t)rA * ostride + d,       o[mi][ni][0], o[mi][ni][1]);
            store2(ob + (size_t)(rA + 8) * ostride + d, o[mi][ni][2], o[mi][ni][3]);
        }
    }
}

// ---------------------------------------------------------------------------
extern "C" void kernel_launch(void* const* d_in, const int* in_sizes, int n_in,
                              void* d_out, int out_size) {
    const float* h   = (const float*)d_in[0];
    const float* u   = (const float*)d_in[1];
    const float* lam = (const float*)d_in[2];
    const float* Wq  = (const float*)d_in[3];
    const float* bq  = (const float*)d_in[4];
    const float* Wk  = (const float*)d_in[5];
    const float* bk  = (const float*)d_in[6];
    const float* Wv  = (const float*)d_in[7];
    const float* bv  = (const float*)d_in[8];
    const float* Wo  = (const float*)d_in[9];
    const float* bo  = (const float*)d_in[10];
    float* out = (float*)d_out;

    __half *hh, *aout, *wqkv, *wo, *QKVh;
    float *bqkv, *upen;
    cudaGetSymbolAddress((void**)&hh,   g_hh);
    cudaGetSymbolAddress((void**)&aout, g_aout);
    cudaGetSymbolAddress((void**)&wqkv, g_wqkv);
    cudaGetSymbolAddress((void**)&wo,   g_wo);
    cudaGetSymbolAddress((void**)&bqkv, g_bqkv);
    cudaGetSymbolAddress((void**)&QKVh, g_QKV);
    cudaGetSymbolAddress((void**)&upen, g_upen);

    cudaFuncSetAttribute(gemm_qkv, cudaFuncAttributeMaxDynamicSharedMemorySize,
                         3 * STG_BYTES);
    cudaFuncSetAttribute(gemm_oproj, cudaFuncAttributeMaxDynamicSharedMemorySize,
                         3 * STG_BYTES);
    cudaFuncSetAttribute(attn_mma, cudaFuncAttributeMaxDynamicSharedMemorySize,
                         ATTN_SMEM);

    dim3 tgrid(8, 24, 128), tblk(32, 32);
    transpose_in_h<<<tgrid, tblk>>>(h, hh);
    upen_kernel<<<128, 256>>>(u, lam, upen);
    dim3 wgrid((D_ * D_) / 1024, 4);
    wconv4<<<wgrid, 256>>>(Wq, Wk, Wv, Wo, wqkv, wo);
    pack_bias<<<(NQKV + 255) / 256, 256>>>(bq, bk, bv, bqkv);

    // fused QKV projection: C[M, 2304] fp16
    dim3 qgrid(NQKV / BN, M_ / BM);        // (18, 256)
    gemm_qkv<<<qgrid, 256, 3 * STG_BYTES>>>(hh, wqkv, bqkv, QKVh);

    dim3 agrid(BS_, 3);
    attn_mma<<<agrid, 128, ATTN_SMEM>>>(QKVh, upen, aout);

    // O projection with fused transpose -> writes final out directly
    dim3 ogrid(D_ / BN, M_ / BM);          // (6, 256)
    gemm_oproj<<<ogrid, 256, 3 * STG_BYTES>>>(aout, wo, bo, out);
}

// round 15
// speedup vs baseline: 7.7844x; 1.1239x over previous
#include <cuda_runtime.h>
#include <cuda_fp16.h>
#include <cstdint>

// Problem constants
#define B_   4
#define T_   32
#define D_   768
#define P_   256
#define BS_  1024
#define M_   32768
#define NH_  12
#define HD_  64
#define NQKV 2304          // fused Q|K|V output width

// hh / QKV rows: m = bs*T + t   (attention-friendly)
// aout rows:     m = t*BS + bs  (oproj fused-transpose-friendly)

// GEMM tiling: 128x128, BK=64, 8 warps (4m x 2n), warp tile 32x64, 2 CTAs/SM
#define BM   128
#define BN   128
#define BK   64
#define NKT  (D_ / BK)     // 12
#define STG_BYTES 32768    // A 16K + B 16K
#define B_OFFS 16384

#define SW128(b) ((b) ^ (((b) >> 3) & 0x70))

// Attention smem layout (per warp): Q 32x72h, K 32x72h, Vt 64x40h
#define QK_STRIDE_B 144
#define VT_STRIDE_B 80
#define AQ_OFF 0
#define AK_OFF 4608
#define AVT_OFF 9216
#define AWARP_BYTES 14336
#define AUPEN_OFF (4 * AWARP_BYTES)
#define ATTN_SMEM (AUPEN_OFF + 128)

// ---------------- scratch (device globals; no cudaMalloc allowed) ----------
__device__ __half g_hh  [(size_t)M_ * D_];       // h_seq fp16, [bs][t][d]
__device__ __half g_aout[(size_t)M_ * D_];       // attention out fp16, [t][bs][d]
__device__ __half g_wqkv[(size_t)NQKV * D_];     // fused Wq|Wk|Wv fp16
__device__ __half g_wo  [(size_t)D_ * D_];
__device__ float  g_bqkv[NQKV];
__device__ __half g_QKV [(size_t)M_ * NQKV];     // fused Q|K|V fp16, [bs][t]
__device__ float  g_upen[M_];                    // [bs][t]

// ---------------- PTX helpers (base-PTX, sm_80-era) ------------------------
__device__ __forceinline__ uint32_t smem_u32(const void* p) {
    uint32_t a;
    asm("{ .reg .u64 t; cvta.to.shared.u64 t, %1; cvt.u32.u64 %0, t; }"
        : "=r"(a) : "l"(p));
    return a;
}

__device__ __forceinline__ void cp16(uint32_t dst, const void* src) {
    asm volatile("cp.async.cg.shared.global [%0], [%1], 16;" :: "r"(dst), "l"(src));
}
#define CP_COMMIT() asm volatile("cp.async.commit_group;" ::: "memory")
#define CP_WAIT(n)  asm volatile("cp.async.wait_group %0;" :: "n"(n) : "memory")

__device__ __forceinline__ void ldsm4(uint32_t (&r)[4], uint32_t addr) {
    asm volatile("ldmatrix.sync.aligned.m8n8.x4.shared.b16 {%0,%1,%2,%3}, [%4];"
                 : "=r"(r[0]), "=r"(r[1]), "=r"(r[2]), "=r"(r[3]) : "r"(addr));
}

__device__ __forceinline__ void mma16816(float (&d)[4], const uint32_t (&a)[4],
                                         uint32_t b0, uint32_t b1) {
    asm volatile(
        "mma.sync.aligned.m16n8k16.row.col.f32.f16.f16.f32 "
        "{%0,%1,%2,%3}, {%4,%5,%6,%7}, {%8,%9}, {%0,%1,%2,%3};"
        : "+f"(d[0]), "+f"(d[1]), "+f"(d[2]), "+f"(d[3])
        : "r"(a[0]), "r"(a[1]), "r"(a[2]), "r"(a[3]), "r"(b0), "r"(b1));
}

__device__ __forceinline__ uint32_t packh2(float x, float y) {
    __half2 h = __floats2half2_rn(x, y);
    return *reinterpret_cast<uint32_t*>(&h);
}

__device__ __forceinline__ void store2(float* p, float x, float y) {
    *reinterpret_cast<float2*>(p) = make_float2(x, y);
}
__device__ __forceinline__ void store2(__half* p, float x, float y) {
    *reinterpret_cast<__half2*>(p) = __floats2half2_rn(x, y);
}

// ---------------------------------------------------------------------------
// transpose to [bs][t][d] + fp16 convert; 64d x 32p tiles, __half2 stores
// ---------------------------------------------------------------------------
__global__ __launch_bounds__(1024) void transpose_in_h(const float* __restrict__ src,
                                                       __half* __restrict__ dst) {
    __shared__ float tile[64][33];
    int bt = blockIdx.z, b = bt >> 5, t = bt & 31;
    int dblk = blockIdx.y * 64, pblk = blockIdx.x * 32;
    int tx = threadIdx.x, ty = threadIdx.y;

    const float* sp = src + ((size_t)bt * D_ + dblk + ty) * P_ + pblk + tx;
    tile[ty][tx]      = sp[0];
    tile[ty + 32][tx] = sp[(size_t)32 * P_];
    __syncthreads();
    int d2 = 2 * tx;
    int p2 = pblk + ty;
    __half2 v = __floats2half2_rn(tile[d2][ty], tile[d2 + 1][ty]);
    *reinterpret_cast<__half2*>(
        dst + ((size_t)(b * P_ + p2) * T_ + t) * D_ + dblk + d2) = v;
}

// ---------------------------------------------------------------------------
// weight convert (all 4) + bias pack fold
// ---------------------------------------------------------------------------
__global__ __launch_bounds__(256) void wconv4(const float* __restrict__ Wq,
                                              const float* __restrict__ Wk,
                                              const float* __restrict__ Wv,
                                              const float* __restrict__ Wo,
                                              __half* __restrict__ wqkv,
                                              __half* __restrict__ wo,
                                              const float* __restrict__ bq,
                                              const float* __restrict__ bk,
                                              const float* __restrict__ bv,
                                              float* __restrict__ bqkv) {
    int idx = blockIdx.x * 256 + threadIdx.x;
    int w = blockIdx.y;
    const float* src = (w == 0) ? Wq : (w == 1) ? Wk : (w == 2) ? Wv : Wo;
    __half* dst = (w == 3) ? wo : wqkv + (size_t)w * D_ * D_;
    float4 v = *reinterpret_cast<const float4*>(src + idx * 4);
    __half2 h0 = __floats2half2_rn(v.x, v.y);
    __half2 h1 = __floats2half2_rn(v.z, v.w);
    uint2 o = make_uint2(*reinterpret_cast<uint32_t*>(&h0),
                         *reinterpret_cast<uint32_t*>(&h1));
    *reinterpret_cast<uint2*>(dst + idx * 4) = o;

    if (w == 3 && idx < NQKV) {
        float bv_ = (idx < D_) ? bq[idx]
                  : (idx < 2 * D_) ? bk[idx - D_] : bv[idx - 2 * D_];
        bqkv[idx] = bv_;
    }
}

// ---------------------------------------------------------------------------
// u_pen   [bs][t]
// ---------------------------------------------------------------------------
__global__ __launch_bounds__(256) void upen_kernel(const float* __restrict__ u,
                                                   const float* __restrict__ lam,
                                                   float* __restrict__ upen) {
    int bt = blockIdx.x, b = bt >> 5, t = bt & 31;
    int p = threadIdx.x;
    const float* up = u + (size_t)bt * D_ * P_ + p;
    float acc = 0.f;
#pragma unroll 8
    for (int d = 0; d < D_; d++) acc += up[(size_t)d * P_];
    upen[(b * P_ + p) * T_ + t] = lam[(size_t)bt * P_ + p] * acc * (1.0f / (float)D_);
}

// ---------------------------------------------------------------------------
// HMMA GEMM (QKV): C[m,n] = A[m,768] @ W^T + bias, C fp16 stride NQKV.
// Smem-staged epilogue -> 256B coalesced row stores.
// ---------------------------------------------------------------------------
__global__ __launch_bounds__(256, 2) void gemm_qkv(const __half* __restrict__ A,
                                                   const __half* __restrict__ Wt,
                                                   const float* __restrict__ bias,
                                                   __half* __restrict__ C) {
    extern __shared__ __align__(128) char dyn[];
    const uint32_t dynb = smem_u32(dyn);

    const int tid  = threadIdx.x;
    const int wid  = tid >> 5;
    const int lane = tid & 31;
    const int mblk = blockIdx.y * BM;
    const int nblk = blockIdx.x * BN;

    const int warp_m = (wid >> 1) * 32;
    const int warp_n = (wid & 1) * 64;

    const __half* Ab = A  + (size_t)mblk * D_;
    const __half* Bb = Wt + (size_t)nblk * D_;

    auto load_tile = [&](int stage, int kt) {
        uint32_t sb = dynb + stage * STG_BYTES;
        const __half* Ak = Ab + kt * BK;
        const __half* Bk = Bb + kt * BK;
#pragma unroll
        for (int i = 0; i < 8; ++i) {
            int c = tid + 256 * i;
            if (c < 1024) {
                int r = c >> 3, kc = c & 7;
                cp16(sb + SW128(r * 128 + kc * 16),
                     Ak + (size_t)r * D_ + kc * 8);
            } else {
                int c2 = c - 1024;
                int r = c2 >> 3, kc = c2 & 7;
                cp16(sb + B_OFFS + SW128(r * 128 + kc * 16),
                     Bk + (size_t)r * D_ + kc * 8);
            }
        }
        CP_COMMIT();
    };

    const int a_row = warp_m + (lane & 15);
    const int a_kh  = lane >> 4;
    const int b_row = warp_n + (lane & 7) + ((lane >> 4) << 3);
    const int b_kh  = (lane >> 3) & 1;

    float acc[2][8][4];
#pragma unroll
    for (int mi = 0; mi < 2; mi++)
#pragma unroll
        for (int ni = 0; ni < 8; ni++)
#pragma unroll
            for (int e = 0; e < 4; e++) acc[mi][ni][e] = 0.f;

    load_tile(0, 0);
    load_tile(1, 1);

    for (int kt = 0; kt < NKT; ++kt) {
        const int cur = kt % 3;
        if (kt < NKT - 1) CP_WAIT(1); else CP_WAIT(0);
        __syncthreads();
        if (kt + 2 < NKT) load_tile((kt + 2) % 3, kt + 2);

        const uint32_t sb = dynb + cur * STG_BYTES;
#pragma unroll
        for (int s = 0; s < 4; ++s) {
            uint32_t bfr[4][4];
#pragma unroll
            for (int nj = 0; nj < 4; nj++)
                ldsm4(bfr[nj], sb + B_OFFS +
                      SW128((b_row + nj * 16) * 128 + (s * 2 + b_kh) * 16));
            uint32_t afr[2][4];
#pragma unroll
            for (int mi = 0; mi < 2; mi++)
                ldsm4(afr[mi], sb +
                      SW128((a_row + mi * 16) * 128 + (s * 2 + a_kh) * 16));
#pragma unroll
            for (int mi = 0; mi < 2; mi++) {
#pragma unroll
                for (int ni = 0; ni < 8; ni++) {
                    uint32_t b0 = bfr[ni >> 1][(ni & 1) * 2 + 0];
                    uint32_t b1 = bfr[ni >> 1][(ni & 1) * 2 + 1];
                    mma16816(acc[mi][ni], afr[mi], b0, b1);
                }
            }
        }
    }

    // ---- smem-staged epilogue: stage[128][136h], then 256B row stores ----
    const int rloc0 = warp_m + (lane >> 2);
    const int cloc0 = warp_n + (lane & 3) * 2;
    float2 bb[8];
#pragma unroll
    for (int ni = 0; ni < 8; ni++) {
        int n = nblk + cloc0 + ni * 8;
        bb[ni].x = __ldg(&bias[n]);
        bb[ni].y = __ldg(&bias[n + 1]);
    }
    __syncthreads();   // pipeline smem fully consumed by all warps
    __half* cst = reinterpret_cast<__half*>(dyn);
#pragma unroll
    for (int mi = 0; mi < 2; mi++) {
        int r0 = rloc0 + mi * 16;
#pragma unroll
        for (int ni = 0; ni < 8; ni++) {
            int n = cloc0 + ni * 8;
            store2(cst + (size_t)r0 * 136 + n,
                   acc[mi][ni][0] + bb[ni].x, acc[mi][ni][1] + bb[ni].y);
            store2(cst + (size_t)(r0 + 8) * 136 + n,
                   acc[mi][ni][2] + bb[ni].x, acc[mi][ni][3] + bb[ni].y);
        }
    }
    __syncthreads();
#pragma unroll
    for (int i = 0; i < 16; ++i) {
        int r = wid * 16 + i;
        uint2 v = *reinterpret_cast<uint2*>(cst + (size_t)r * 136 + lane * 4);
        *reinterpret_cast<uint2*>(C + (size_t)(mblk + r) * NQKV + nblk + lane * 4) = v;
    }
}

// ---------------------------------------------------------------------------
// HMMA GEMM (O proj) with FUSED TRANSPOSE epilogue (unchanged from R13):
// A = aout [t][bs][d] fp16; writes final out (B,T,D,P) fp32 directly.
// ---------------------------------------------------------------------------
__global__ __launch_bounds__(256, 2) void gemm_oproj(const __half* __restrict__ A,
                                                     const __half* __restrict__ Wt,
                                                     const float* __restrict__ bias,
                                                     float* __restrict__ out) {
    extern __shared__ __align__(128) char dyn[];
    const uint32_t dynb = smem_u32(dyn);

    const int tid  = threadIdx.x;
    const int wid  = tid >> 5;
    const int lane = tid & 31;
    const int mblk = blockIdx.y * BM;
    const int nblk = blockIdx.x * BN;

    const int warp_m = (wid >> 1) * 32;
    const int warp_n = (wid & 1) * 64;

    const __half* Ab = A  + (size_t)mblk * D_;
    const __half* Bb = Wt + (size_t)nblk * D_;

    auto load_tile = [&](int stage, int kt) {
        uint32_t sb = dynb + stage * STG_BYTES;
        const __half* Ak = Ab + kt * BK;
        const __half* Bk = Bb + kt * BK;
#pragma unroll
        for (int i = 0; i < 8; ++i) {
            int c = tid + 256 * i;
            if (c < 1024) {
                int r = c >> 3, kc = c & 7;
                cp16(sb + SW128(r * 128 + kc * 16),
                     Ak + (size_t)r * D_ + kc * 8);
            } else {
                int c2 = c - 1024;
                int r = c2 >> 3, kc = c2 & 7;
                cp16(sb + B_OFFS + SW128(r * 128 + kc * 16),
                     Bk + (size_t)r * D_ + kc * 8);
            }
        }
        CP_COMMIT();
    };

    const int a_row = warp_m + (lane & 15);
    const int a_kh  = lane >> 4;
    const int b_row = warp_n + (lane & 7) + ((lane >> 4) << 3);
    const int b_kh  = (lane >> 3) & 1;

    float acc[2][8][4];
#pragma unroll
    for (int mi = 0; mi < 2; mi++)
#pragma unroll
        for (int ni = 0; ni < 8; ni++)
#pragma unroll
            for (int e = 0; e < 4; e++) acc[mi][ni][e] = 0.f;

    load_tile(0, 0);
    load_tile(1, 1);

    for (int kt = 0; kt < NKT; ++kt) {
        const int cur = kt % 3;
        if (kt < NKT - 1) CP_WAIT(1); else CP_WAIT(0);
        __syncthreads();
        if (kt + 2 < NKT) load_tile((kt + 2) % 3, kt + 2);

        const uint32_t sb = dynb + cur * STG_BYTES;
#pragma unroll
        for (int s = 0; s < 4; ++s) {
            uint32_t bfr[4][4];
#pragma unroll
            for (int nj = 0; nj < 4; nj++)
                ldsm4(bfr[nj], sb + B_OFFS +
                      SW128((b_row + nj * 16) * 128 + (s * 2 + b_kh) * 16));
            uint32_t afr[2][4];
#pragma unroll
            for (int mi = 0; mi < 2; mi++)
                ldsm4(afr[mi], sb +
                      SW128((a_row + mi * 16) * 128 + (s * 2 + a_kh) * 16));
#pragma unroll
            for (int mi = 0; mi < 2; mi++) {
#pragma unroll
                for (int ni = 0; ni < 8; ni++) {
                    uint32_t b0 = bfr[ni >> 1][(ni & 1) * 2 + 0];
                    uint32_t b1 = bfr[ni >> 1][(ni & 1) * 2 + 1];
                    mma16816(acc[mi][ni], afr[mi], b0, b1);
                }
            }
        }
    }

    // ---- fused transpose epilogue (stride 129 floats; scalar stores) ----
    float* stage = reinterpret_cast<float*>(dyn);
    const int rloc0 = warp_m + (lane >> 2);
    const int nloc0 = warp_n + (lane & 3) * 2;
    float2 bb[8];
#pragma unroll
    for (int ni = 0; ni < 8; ni++) {
        int n = nblk + nloc0 + ni * 8;
        bb[ni].x = __ldg(&bias[n]);
        bb[ni].y = __ldg(&bias[n + 1]);
    }
    __syncthreads();
#pragma unroll
    for (int mi = 0; mi < 2; mi++) {
        int r0 = rloc0 + mi * 16;
#pragma unroll
        for (int ni = 0; ni < 8; ni++) {
            int n = nloc0 + ni * 8;
            stage[(size_t)r0 * 129 + n]           = acc[mi][ni][0] + bb[ni].x;
            stage[(size_t)r0 * 129 + n + 1]       = acc[mi][ni][1] + bb[ni].y;
            stage[(size_t)(r0 + 8) * 129 + n]     = acc[mi][ni][2] + bb[ni].x;
            stage[(size_t)(r0 + 8) * 129 + n + 1] = acc[mi][ni][3] + bb[ni].y;
        }
    }
    __syncthreads();

    const int t  = mblk >> 10;
    const int b  = (mblk & 1023) >> 8;
    const int p0 = mblk & 255;
    float* obase = out + ((size_t)(b * T_ + t) * D_ + nblk) * P_ + p0;
#pragma unroll
    for (int i = 0; i < 16; ++i) {
        int c = tid + 256 * i;
        int dn = c >> 5, f4 = c & 31;
        float4 v;
        v.x = stage[(size_t)(f4 * 4 + 0) * 129 + dn];
        v.y = stage[(size_t)(f4 * 4 + 1) * 129 + dn];
        v.z = stage[(size_t)(f4 * 4 + 2) * 129 + dn];
        v.w = stage[(size_t)(f4 * 4 + 3) * 129 + dn];
        *reinterpret_cast<float4*>(obase + (size_t)dn * P_ + f4 * 4) = v;
    }
}

// ---------------------------------------------------------------------------
// HMMA attention: 1 warp per (bs, head). QKV [bs][t] (contiguous loads);
// writes aout [t][bs] via smem-staged 128B coalesced row stores.
// ---------------------------------------------------------------------------
__global__ __launch_bounds__(128) void attn_mma(const __half* __restrict__ QKV,
                                                const float* __restrict__ upen,
                                                __half* __restrict__ O) {
    extern __shared__ __align__(128) char asm_[];
    const int bs   = blockIdx.x;
    const int wid  = threadIdx.x >> 5;
    const int lane = threadIdx.x & 31;
    const int head = blockIdx.y * 4 + wid;

    char* wb = asm_ + wid * AWARP_BYTES;
    const uint32_t wbase = smem_u32(asm_) + wid * AWARP_BYTES;
    float* us = reinterpret_cast<float*>(asm_ + AUPEN_OFF);

    if (threadIdx.x < 32) us[threadIdx.x] = upen[bs * T_ + threadIdx.x];

    const __half* hb = QKV + (size_t)(bs * T_) * NQKV + head * HD_;
#pragma unroll
    for (int i = 0; i < 8; ++i) {
        int id = lane + 32 * i;
        int r = id >> 3, c = id & 7;
        const __half* qsrc = hb + (size_t)r * NQKV + c * 8;
        *reinterpret_cast<uint4*>(wb + AQ_OFF + r * QK_STRIDE_B + c * 16) =
            *reinterpret_cast<const uint4*>(qsrc);
        *reinterpret_cast<uint4*>(wb + AK_OFF + r * QK_STRIDE_B + c * 16) =
            *reinterpret_cast<const uint4*>(qsrc + D_);
        uint4 vv = *reinterpret_cast<const uint4*>(qsrc + 2 * D_);
        const __half* vh = reinterpret_cast<const __half*>(&vv);
#pragma unroll
        for (int j = 0; j < 8; ++j)
            *reinterpret_cast<__half*>(wb + AVT_OFF + (c * 8 + j) * VT_STRIDE_B + r * 2) = vh[j];
    }
    __syncthreads();

    const int a_kh  = lane >> 4;
    const int b_row = (lane & 7) + ((lane >> 4) << 3);
    const int b_kh  = (lane >> 3) & 1;
    const int col0  = (lane & 3) * 2;

    float S[2][4][4];
#pragma unroll
    for (int mi = 0; mi < 2; mi++)
#pragma unroll
        for (int ni = 0; ni < 4; ni++)
#pragma unroll
            for (int e = 0; e < 4; e++) S[mi][ni][e] = 0.f;

#pragma unroll
    for (int s = 0; s < 4; ++s) {
        uint32_t bfr[2][4];
#pragma unroll
        for (int nj = 0; nj < 2; nj++)
            ldsm4(bfr[nj], wbase + AK_OFF +
                  (b_row + nj * 16) * QK_STRIDE_B + (s * 2 + b_kh) * 16);
        uint32_t afr[2][4];
#pragma unroll
        for (int mi = 0; mi < 2; mi++)
            ldsm4(afr[mi], wbase + AQ_OFF +
                  ((lane & 15) + mi * 16) * QK_STRIDE_B + (s * 2 + a_kh) * 16);
#pragma unroll
        for (int mi = 0; mi < 2; mi++)
#pragma unroll
            for (int ni = 0; ni < 4; ni++)
                mma16816(S[mi][ni], afr[mi],
                         bfr[ni >> 1][(ni & 1) * 2], bfr[ni >> 1][(ni & 1) * 2 + 1]);
    }

    float uv[4][2];
#pragma unroll
    for (int ni = 0; ni < 4; ni++) {
        uv[ni][0] = us[8 * ni + col0];
        uv[ni][1] = us[8 * ni + col0 + 1];
    }
    float mA[2] = {-1e30f, -1e30f}, mB[2] = {-1e30f, -1e30f};
#pragma unroll
    for (int mi = 0; mi < 2; mi++)
#pragma unroll
        for (int ni = 0; ni < 4; ni++) {
            S[mi][ni][0] = S[mi][ni][0] * 0.125f - uv[ni][0];
            S[mi][ni][1] = S[mi][ni][1] * 0.125f - uv[ni][1];
            S[mi][ni][2] = S[mi][ni][2] * 0.125f - uv[ni][0];
            S[mi][ni][3] = S[mi][ni][3] * 0.125f - uv[ni][1];
            mA[mi] = fmaxf(mA[mi], fmaxf(S[mi][ni][0], S[mi][ni][1]));
            mB[mi] = fmaxf(mB[mi], fmaxf(S[mi][ni][2], S[mi][ni][3]));
        }
#pragma unroll
    for (int off = 1; off <= 2; off <<= 1) {
#pragma unroll
        for (int mi = 0; mi < 2; mi++) {
            mA[mi] = fmaxf(mA[mi], __shfl_xor_sync(0xffffffffu, mA[mi], off));
            mB[mi] = fmaxf(mB[mi], __shfl_xor_sync(0xffffffffu, mB[mi], off));
        }
    }
    float sA[2] = {0.f, 0.f}, sB[2] = {0.f, 0.f};
#pragma unroll
    for (int mi = 0; mi < 2; mi++)
#pragma unroll
        for (int ni = 0; ni < 4; ni++) {
            S[mi][ni][0] = __expf(S[mi][ni][0] - mA[mi]);
            S[mi][ni][1] = __expf(S[mi][ni][1] - mA[mi]);
            S[mi][ni][2] = __expf(S[mi][ni][2] - mB[mi]);
            S[mi][ni][3] = __expf(S[mi][ni][3] - mB[mi]);
            sA[mi] += S[mi][ni][0] + S[mi][ni][1];
            sB[mi] += S[mi][ni][2] + S[mi][ni][3];
        }
#pragma unroll
    for (int off = 1; off <= 2; off <<= 1) {
#pragma unroll
        for (int mi = 0; mi < 2; mi++) {
            sA[mi] += __shfl_xor_sync(0xffffffffu, sA[mi], off);
            sB[mi] += __shfl_xor_sync(0xffffffffu, sB[mi], off);
        }
    }
    uint32_t p01[2][4], p23[2][4];
#pragma unroll
    for (int mi = 0; mi < 2; mi++) {
        float iA = 1.f / sA[mi], iB = 1.f / sB[mi];
#pragma unroll
        for (int ni = 0; ni < 4; ni++) {
            p01[mi][ni] = packh2(S[mi][ni][0] * iA, S[mi][ni][1] * iA);
            p23[mi][ni] = packh2(S[mi][ni][2] * iB, S[mi][ni][3] * iB);
        }
    }

    float o[2][8][4];
#pragma unroll
    for (int mi = 0; mi < 2; mi++)
#pragma unroll
        for (int ni = 0; ni < 8; ni++)
#pragma unroll
            for (int e = 0; e < 4; e++) o[mi][ni][e] = 0.f;

#pragma unroll
    for (int s = 0; s < 2; ++s) {
        uint32_t bfr[4][4];
#pragma unroll
        for (int nj = 0; nj < 4; nj++)
            ldsm4(bfr[nj], wbase + AVT_OFF +
                  (b_row + nj * 16) * VT_STRIDE_B + (s * 2 + b_kh) * 16);
#pragma unroll
        for (int mi = 0; mi < 2; mi++) {
            uint32_t a[4] = {p01[mi][2 * s], p23[mi][2 * s],
                             p01[mi][2 * s + 1], p23[mi][2 * s + 1]};
#pragma unroll
            for (int ni = 0; ni < 8; ni++)
                mma16816(o[mi][ni], a,
                         bfr[ni >> 1][(ni & 1) * 2], bfr[ni >> 1][(ni & 1) * 2 + 1]);
        }
    }

    // ---- smem-stage O (reuse AQ area; warp-private), then 128B row stores
    __syncwarp();
    __half* ost = reinterpret_cast<__half*>(wb + AQ_OFF);   // [32][72h]
#pragma unroll
    for (int mi = 0; mi < 2; mi++) {
        int rA = (lane >> 2) + 16 * mi;
#pragma unroll
        for (int ni = 0; ni < 8; ni++) {
            int d = 8 * ni + col0;
            store2(ost + (size_t)rA * 72 + d,       o[mi][ni][0], o[mi][ni][1]);
            store2(ost + (size_t)(rA + 8) * 72 + d, o[mi][ni][2], o[mi][ni][3]);
        }
    }
    __syncwarp();
    __half* ob = O + (size_t)bs * D_ + head * HD_;    // aout [t][bs][d]
    const size_t ostride = (size_t)BS_ * D_;
#pragma unroll
    for (int r = 0; r < 32; ++r) {
        uint32_t v = *reinterpret_cast<uint32_t*>(ost + (size_t)r * 72 + lane * 2);
        *reinterpret_cast<uint32_t*>(ob + (size_t)r * ostride + lane * 2) = v;
    }
}

// ---------------------------------------------------------------------------
extern "C" void kernel_launch(void* const* d_in, const int* in_sizes, int n_in,
                              void* d_out, int out_size) {
    const float* h   = (const float*)d_in[0];
    const float* u   = (const float*)d_in[1];
    const float* lam = (const float*)d_in[2];
    const float* Wq  = (const float*)d_in[3];
    const float* bq  = (const float*)d_in[4];
    const float* Wk  = (const float*)d_in[5];
    const float* bk  = (const float*)d_in[6];
    const float* Wv  = (const float*)d_in[7];
    const float* bv  = (const float*)d_in[8];
    const float* Wo  = (const float*)d_in[9];
    const float* bo  = (const float*)d_in[10];
    float* out = (float*)d_out;

    __half *hh, *aout, *wqkv, *wo, *QKVh;
    float *bqkv, *upen;
    cudaGetSymbolAddress((void**)&hh,   g_hh);
    cudaGetSymbolAddress((void**)&aout, g_aout);
    cudaGetSymbolAddress((void**)&wqkv, g_wqkv);
    cudaGetSymbolAddress((void**)&wo,   g_wo);
    cudaGetSymbolAddress((void**)&bqkv, g_bqkv);
    cudaGetSymbolAddress((void**)&QKVh, g_QKV);
    cudaGetSymbolAddress((void**)&upen, g_upen);

    cudaFuncSetAttribute(gemm_qkv, cudaFuncAttributeMaxDynamicSharedMemorySize,
                         3 * STG_BYTES);
    cudaFuncSetAttribute(gemm_oproj, cudaFuncAttributeMaxDynamicSharedMemorySize,
                         3 * STG_BYTES);
    cudaFuncSetAttribute(attn_mma, cudaFuncAttributeMaxDynamicSharedMemorySize,
                         ATTN_SMEM);

    dim3 tgrid(P_ / 32, D_ / 64, 128), tblk(32, 32);
    transpose_in_h<<<tgrid, tblk>>>(h, hh);
    upen_kernel<<<128, 256>>>(u, lam, upen);
    dim3 wgrid((D_ * D_) / 1024, 4);
    wconv4<<<wgrid, 256>>>(Wq, Wk, Wv, Wo, wqkv, wo, bq, bk, bv, bqkv);

    // fused QKV projection: C[M, 2304] fp16, rows [bs][t]
    dim3 qgrid(NQKV / BN, M_ / BM);        // (18, 256)
    gemm_qkv<<<qgrid, 256, 3 * STG_BYTES>>>(hh, wqkv, bqkv, QKVh);

    dim3 agrid(BS_, 3);
    attn_mma<<<agrid, 128, ATTN_SMEM>>>(QKVh, upen, aout);

    // O projection with fused transpose -> writes final out directly
    dim3 ogrid(D_ / BN, M_ / BM);          // (6, 256)
    gemm_oproj<<<ogrid, 256, 3 * STG_BYTES>>>(aout, wo, bo, out);
}